// round 1
// baseline (speedup 1.0000x reference)
#include <cuda_runtime.h>
#include <cuda_bf16.h>
#include <math.h>

// Problem constants
#define BNODES 8192      // B*N
#define HDIM   256
#define NEDGE  131072
#define NLAYER 4

// ---------------- scratch (device globals; no allocation allowed) ----------
__device__ float g_h [BNODES * HDIM];        // activations (BN, H)
__device__ float g_t1[BNODES * 1024];        // gcn lin / qkv / ffn mid / head mid
__device__ float g_t2[BNODES * HDIM];        // gcn agg / attn out
__device__ float g_t3[BNODES * HDIM];        // proj outputs feeding BN
__device__ int   g_cnt[BNODES];
__device__ int   g_off[BNODES + 1];
__device__ int   g_cur[BNODES];
__device__ int   g_eidx[NEDGE];
__device__ float g_psum[128 * HDIM];
__device__ float g_psq [128 * HDIM];
__device__ float g_mean[HDIM];
__device__ float g_istd[HDIM];

__device__ __forceinline__ float gelu_f(float x) {
    return 0.5f * x * (1.0f + erff(x * 0.70710678118654752f));
}

// ---------------- GEMM: C = act(A @ W^T + bias [+ C]) ----------------------
// A: (M,K) row-major, W: (N,K) row-major, C: (M,N). M,N multiples of 64, K mult of 4.
// 64x64 tile, BK=16, 256 threads, 4x4 per thread.
template<int ACT, bool ACCUM>
__global__ void gemm_kernel(const float* __restrict__ A, const float* __restrict__ W,
                            const float* __restrict__ bias, float* __restrict__ C,
                            int K, int N) {
    __shared__ float As[16][68];
    __shared__ float Bs[16][68];
    const int bm = blockIdx.y * 64, bn = blockIdx.x * 64;
    const int tid = threadIdx.x;
    const int lr = tid >> 2;             // 0..63
    const int lk = (tid & 3) << 2;       // 0,4,8,12
    const int tn = (tid & 15) << 2;      // col 0..60
    const int tm = (tid >> 4) << 2;      // row 0..60
    float acc[4][4] = {};
    const float* Arow = A + (size_t)(bm + lr) * K;
    const float* Wrow = W + (size_t)(bn + lr) * K;

    for (int k0 = 0; k0 < K; k0 += 16) {
        float4 a4, b4;
        if (k0 + lk < K) {
            a4 = *(const float4*)(Arow + k0 + lk);
            b4 = *(const float4*)(Wrow + k0 + lk);
        } else {
            a4 = make_float4(0.f, 0.f, 0.f, 0.f);
            b4 = a4;
        }
        As[lk + 0][lr] = a4.x; As[lk + 1][lr] = a4.y;
        As[lk + 2][lr] = a4.z; As[lk + 3][lr] = a4.w;
        Bs[lk + 0][lr] = b4.x; Bs[lk + 1][lr] = b4.y;
        Bs[lk + 2][lr] = b4.z; Bs[lk + 3][lr] = b4.w;
        __syncthreads();
        #pragma unroll
        for (int k = 0; k < 16; k++) {
            float am[4], bv[4];
            #pragma unroll
            for (int i = 0; i < 4; i++) am[i] = As[k][tm + i];
            #pragma unroll
            for (int j = 0; j < 4; j++) bv[j] = Bs[k][tn + j];
            #pragma unroll
            for (int i = 0; i < 4; i++)
                #pragma unroll
                for (int j = 0; j < 4; j++)
                    acc[i][j] += am[i] * bv[j];
        }
        __syncthreads();
    }

    #pragma unroll
    for (int i = 0; i < 4; i++) {
        size_t crow = (size_t)(bm + tm + i) * N + bn + tn;
        #pragma unroll
        for (int j = 0; j < 4; j++) {
            float c = acc[i][j];
            if (bias) c += bias[bn + tn + j];
            if (ACCUM) c += C[crow + j];
            if (ACT == 1) c = gelu_f(c);
            C[crow + j] = c;
        }
    }
}

// ---------------- CSR build (per-launch, from edge_row) --------------------
__global__ void count_deg_kernel(const int* __restrict__ row, int* __restrict__ cnt) {
    int e = blockIdx.x * 256 + threadIdx.x;
    if (e < NEDGE) atomicAdd(&cnt[row[e]], 1);
}

__global__ void scan_kernel(const int* __restrict__ cnt, int* __restrict__ off,
                            int* __restrict__ cur) {
    __shared__ int part[256];
    const int t = threadIdx.x;
    int loc[32];
    int s = 0;
    #pragma unroll
    for (int i = 0; i < 32; i++) { loc[i] = s; s += cnt[t * 32 + i]; }
    part[t] = s;
    __syncthreads();
    for (int ofs = 1; ofs < 256; ofs <<= 1) {
        int mine = part[t];
        int add = (t >= ofs) ? part[t - ofs] : 0;
        __syncthreads();
        part[t] = mine + add;
        __syncthreads();
    }
    int excl = (t > 0) ? part[t - 1] : 0;
    #pragma unroll
    for (int i = 0; i < 32; i++) {
        int v = excl + loc[i];
        off[t * 32 + i] = v;
        cur[t * 32 + i] = v;
    }
    if (t == 255) off[BNODES] = part[255];
}

__global__ void fill_csr_kernel(const int* __restrict__ row, int* __restrict__ cur,
                                int* __restrict__ eidx) {
    int e = blockIdx.x * 256 + threadIdx.x;
    if (e < NEDGE) {
        int p = atomicAdd(&cur[row[e]], 1);
        eidx[p] = e;
    }
}

// ---------------- GCN gather: agg[r] = sum_{e in row r} val[e]*t1[col[e]] ---
__global__ void gcn_gather_kernel(const float* __restrict__ t1,
                                  const int* __restrict__ off,
                                  const int* __restrict__ eidx,
                                  const int* __restrict__ ecol,
                                  const float* __restrict__ eval,
                                  float* __restrict__ agg) {
    const int node = blockIdx.x;
    const int f = threadIdx.x;
    __shared__ int   scol[64];
    __shared__ float sval[64];
    const int s = off[node], e_end = off[node + 1];
    float acc = 0.f;
    for (int base = s; base < e_end; base += 64) {
        int n = min(64, e_end - base);
        if (f < n) {
            int e = eidx[base + f];
            scol[f] = ecol[e];
            sval[f] = eval[e];
        }
        __syncthreads();
        for (int j = 0; j < n; j++)
            acc += sval[j] * t1[(size_t)scol[j] * HDIM + f];
        __syncthreads();
    }
    agg[(size_t)node * HDIM + f] = acc;
}

// ---------------- BatchNorm (training-mode, biased var) --------------------
// Phase 1: x = h + act(add), write x to h, produce per-block partial sums.
template<int ACT>
__global__ void bnpre_kernel(float* __restrict__ h, const float* __restrict__ add,
                             float* __restrict__ psum, float* __restrict__ psq) {
    const int f = threadIdx.x;
    const int blk = blockIdx.x;  // 128 blocks x 64 rows
    float s = 0.f, sq = 0.f;
    size_t base = (size_t)blk * 64 * HDIM + f;
    #pragma unroll 4
    for (int r = 0; r < 64; r++) {
        size_t idx = base + (size_t)r * HDIM;
        float a = add[idx];
        if (ACT == 1) a = gelu_f(a);
        float v = h[idx] + a;
        h[idx] = v;
        s += v;
        sq += v * v;
    }
    psum[blk * HDIM + f] = s;
    psq [blk * HDIM + f] = sq;
}

__global__ void bnfin_kernel(const float* __restrict__ psum, const float* __restrict__ psq,
                             float* __restrict__ mean, float* __restrict__ istd) {
    const int f = threadIdx.x;
    float s = 0.f, sq = 0.f;
    for (int b = 0; b < 128; b++) { s += psum[b * HDIM + f]; sq += psq[b * HDIM + f]; }
    float m = s * (1.0f / BNODES);
    float v = sq * (1.0f / BNODES) - m * m;
    mean[f] = m;
    istd[f] = rsqrtf(v + 1e-5f);
}

__global__ void bnapply_kernel(float* __restrict__ h, const float* __restrict__ mean,
                               const float* __restrict__ istd, const float* __restrict__ g,
                               const float* __restrict__ b) {
    const int f = threadIdx.x;
    const float mu = mean[f], is_ = istd[f], gg = g[f], bb = b[f];
    size_t base = (size_t)blockIdx.x * 8 * HDIM + f;
    #pragma unroll
    for (int r = 0; r < 8; r++) {
        size_t i = base + (size_t)r * HDIM;
        h[i] = (h[i] - mu) * is_ * gg + bb;
    }
}

// ---------------- Flash attention (per-graph, NH=8, DH=32, N=1024) ---------
// grid (16 q-tiles, 8 heads, 8 graphs), 256 threads.
// Thread (tq=tid>>4, tc=tid&15): owns 4 q-rows (tq*4..+3), 4 k-cols (tc*4..+3)
// for S; 4 q-rows x 2 dims (tc*2..+1) for O.
__global__ void attn_kernel(const float* __restrict__ qkv, float* __restrict__ out) {
    const int qt = blockIdx.x, nh = blockIdx.y, b = blockIdx.z;
    __shared__ float Qs[64][33];
    __shared__ float Ks[64][33];
    __shared__ float Vs[64][33];
    __shared__ float Ss[64][65];
    const int tid = threadIdx.x;
    const int tq = tid >> 4, tc = tid & 15;
    const float scale = 0.17677669529663687f;  // 1/sqrt(32)

    size_t qoff = ((size_t)(b * 1024 + qt * 64)) * 768 + nh * 32;
    {
        int r0 = tid >> 5, d = tid & 31;
        for (int r = r0; r < 64; r += 8)
            Qs[r][d] = qkv[qoff + (size_t)r * 768 + d];
    }
    float m[4], l[4], o[4][2];
    #pragma unroll
    for (int i = 0; i < 4; i++) { m[i] = -1e30f; l[i] = 0.f; o[i][0] = 0.f; o[i][1] = 0.f; }
    __syncthreads();

    for (int kt = 0; kt < 16; kt++) {
        size_t koff = ((size_t)(b * 1024 + kt * 64)) * 768 + nh * 32;
        {
            int r0 = tid >> 5, d = tid & 31;
            for (int r = r0; r < 64; r += 8) {
                Ks[r][d] = qkv[koff + (size_t)r * 768 + 256 + d];
                Vs[r][d] = qkv[koff + (size_t)r * 768 + 512 + d];
            }
        }
        __syncthreads();

        float sv[4][4] = {};
        #pragma unroll
        for (int d = 0; d < 32; d++) {
            float qv[4], kv[4];
            #pragma unroll
            for (int i = 0; i < 4; i++) qv[i] = Qs[tq * 4 + i][d];
            #pragma unroll
            for (int j = 0; j < 4; j++) kv[j] = Ks[tc * 4 + j][d];
            #pragma unroll
            for (int i = 0; i < 4; i++)
                #pragma unroll
                for (int j = 0; j < 4; j++)
                    sv[i][j] += qv[i] * kv[j];
        }

        // online softmax per q-row (row group = 16 consecutive lanes)
        #pragma unroll
        for (int i = 0; i < 4; i++) {
            #pragma unroll
            for (int j = 0; j < 4; j++) sv[i][j] *= scale;
            float rmax = fmaxf(fmaxf(sv[i][0], sv[i][1]), fmaxf(sv[i][2], sv[i][3]));
            #pragma unroll
            for (int ofs = 1; ofs < 16; ofs <<= 1)
                rmax = fmaxf(rmax, __shfl_xor_sync(0xffffffffu, rmax, ofs));
            float mnew = fmaxf(m[i], rmax);
            float corr = __expf(m[i] - mnew);
            float ps = 0.f;
            #pragma unroll
            for (int j = 0; j < 4; j++) {
                float p = __expf(sv[i][j] - mnew);
                Ss[tq * 4 + i][tc * 4 + j] = p;
                ps += p;
            }
            #pragma unroll
            for (int ofs = 1; ofs < 16; ofs <<= 1)
                ps += __shfl_xor_sync(0xffffffffu, ps, ofs);
            l[i] = l[i] * corr + ps;
            m[i] = mnew;
            o[i][0] *= corr;
            o[i][1] *= corr;
        }
        __syncwarp();  // Ss row produced & consumed within one warp's 16-lane group

        #pragma unroll 8
        for (int kc = 0; kc < 64; kc++) {
            float v0 = Vs[kc][tc * 2];
            float v1 = Vs[kc][tc * 2 + 1];
            #pragma unroll
            for (int i = 0; i < 4; i++) {
                float p = Ss[tq * 4 + i][kc];
                o[i][0] += p * v0;
                o[i][1] += p * v1;
            }
        }
        __syncthreads();
    }

    #pragma unroll
    for (int i = 0; i < 4; i++) {
        float inv = 1.0f / l[i];
        size_t off = ((size_t)(b * 1024 + qt * 64 + tq * 4 + i)) * HDIM + nh * 32 + tc * 2;
        out[off]     = o[i][0] * inv;
        out[off + 1] = o[i][1] * inv;
    }
}

// ---------------- head final: out = sigmoid(t @ w2^T + b2), OUT=1 ----------
__global__ void head_final_kernel(const float* __restrict__ t, const float* __restrict__ w,
                                  const float* __restrict__ b, float* __restrict__ out) {
    int row = blockIdx.x * 8 + (threadIdx.x >> 5);
    int lane = threadIdx.x & 31;
    float acc = 0.f;
    #pragma unroll
    for (int i = lane; i < 128; i += 32)
        acc += t[(size_t)row * 128 + i] * w[i];
    #pragma unroll
    for (int ofs = 16; ofs; ofs >>= 1)
        acc += __shfl_xor_sync(0xffffffffu, acc, ofs);
    if (lane == 0)
        out[row] = 1.0f / (1.0f + expf(-(acc + b[0])));
}

// ---------------- host orchestration ----------------------------------------
static void bn_block(float* h, const float* add, int act,
                     const float* g, const float* b,
                     float* psum, float* psq, float* mean, float* istd) {
    if (act) bnpre_kernel<1><<<128, 256>>>(h, add, psum, psq);
    else     bnpre_kernel<0><<<128, 256>>>(h, add, psum, psq);
    bnfin_kernel<<<1, 256>>>(psum, psq, mean, istd);
    bnapply_kernel<<<1024, 256>>>(h, mean, istd, g, b);
}

extern "C" void kernel_launch(void* const* d_in, const int* in_sizes, int n_in,
                              void* d_out, int out_size) {
    const float* x        = (const float*)d_in[0];
    const int*   erow     = (const int*)  d_in[1];
    const int*   ecol     = (const int*)  d_in[2];
    const float* eval     = (const float*)d_in[3];
    const float* pe       = (const float*)d_in[4];
    const float* W_in     = (const float*)d_in[5];
    const float* b_in     = (const float*)d_in[6];
    const float* W_pe     = (const float*)d_in[7];
    const float* b_pe     = (const float*)d_in[8];
    const float* gcn_W    = (const float*)d_in[9];
    const float* ain_W    = (const float*)d_in[10];
    const float* ain_b    = (const float*)d_in[11];
    const float* aout_W   = (const float*)d_in[12];
    const float* aout_b   = (const float*)d_in[13];
    const float* bn_g     = (const float*)d_in[14];
    const float* bn_b     = (const float*)d_in[15];
    const float* ffn_W1   = (const float*)d_in[16];
    const float* ffn_b1   = (const float*)d_in[17];
    const float* ffn_W2   = (const float*)d_in[18];
    const float* ffn_b2   = (const float*)d_in[19];
    const float* head_W1  = (const float*)d_in[20];
    const float* head_b1  = (const float*)d_in[21];
    const float* head_W2  = (const float*)d_in[22];
    const float* head_b2  = (const float*)d_in[23];

    float *h, *t1, *t2, *t3, *psum, *psq, *mean, *istd;
    int *cnt, *off, *cur, *eidx;
    cudaGetSymbolAddress((void**)&h,    g_h);
    cudaGetSymbolAddress((void**)&t1,   g_t1);
    cudaGetSymbolAddress((void**)&t2,   g_t2);
    cudaGetSymbolAddress((void**)&t3,   g_t3);
    cudaGetSymbolAddress((void**)&psum, g_psum);
    cudaGetSymbolAddress((void**)&psq,  g_psq);
    cudaGetSymbolAddress((void**)&mean, g_mean);
    cudaGetSymbolAddress((void**)&istd, g_istd);
    cudaGetSymbolAddress((void**)&cnt,  g_cnt);
    cudaGetSymbolAddress((void**)&off,  g_off);
    cudaGetSymbolAddress((void**)&cur,  g_cur);
    cudaGetSymbolAddress((void**)&eidx, g_eidx);

    // CSR build (edges fixed per call; deterministic segment structure)
    cudaMemsetAsync(cnt, 0, BNODES * sizeof(int));
    count_deg_kernel<<<NEDGE / 256, 256>>>(erow, cnt);
    scan_kernel<<<1, 256>>>(cnt, off, cur);
    fill_csr_kernel<<<NEDGE / 256, 256>>>(erow, cur, eidx);

    const dim3 g256 (HDIM / 64,  BNODES / 64);   // (4,128)
    const dim3 g768 (768 / 64,   BNODES / 64);   // (12,128)
    const dim3 g1024(1024 / 64,  BNODES / 64);   // (16,128)
    const dim3 g128 (128 / 64,   BNODES / 64);   // (2,128)

    // input projection: h = x@W_in^T + b_in + pe@W_pe^T + b_pe
    gemm_kernel<0, false><<<g256, 256>>>(x,  W_in, b_in, h, 128, HDIM);
    gemm_kernel<0, true ><<<g256, 256>>>(pe, W_pe, b_pe, h, 8,   HDIM);

    for (int l = 0; l < NLAYER; l++) {
        // ---- local GCN ----
        gemm_kernel<0, false><<<g256, 256>>>(h, gcn_W + (size_t)l * HDIM * HDIM,
                                             nullptr, t1, HDIM, HDIM);
        gcn_gather_kernel<<<BNODES, 256>>>(t1, off, eidx, ecol, eval, t2);
        bn_block(h, t2, 1, bn_g + l * 3 * HDIM, bn_b + l * 3 * HDIM,
                 psum, psq, mean, istd);
        // ---- global attention ----
        gemm_kernel<0, false><<<g768, 256>>>(h, ain_W + (size_t)l * 768 * HDIM,
                                             ain_b + l * 768, t1, HDIM, 768);
        attn_kernel<<<dim3(16, 8, 8), 256>>>(t1, t2);
        gemm_kernel<0, false><<<g256, 256>>>(t2, aout_W + (size_t)l * HDIM * HDIM,
                                             aout_b + l * HDIM, t3, HDIM, HDIM);
        bn_block(h, t3, 0, bn_g + l * 3 * HDIM + HDIM, bn_b + l * 3 * HDIM + HDIM,
                 psum, psq, mean, istd);
        // ---- FFN ----
        gemm_kernel<1, false><<<g1024, 256>>>(h, ffn_W1 + (size_t)l * 1024 * HDIM,
                                              ffn_b1 + l * 1024, t1, HDIM, 1024);
        gemm_kernel<0, false><<<g256, 256>>>(t1, ffn_W2 + (size_t)l * HDIM * 1024,
                                             ffn_b2 + l * HDIM, t3, 1024, HDIM);
        bn_block(h, t3, 0, bn_g + l * 3 * HDIM + 2 * HDIM, bn_b + l * 3 * HDIM + 2 * HDIM,
                 psum, psq, mean, istd);
    }

    // ---- head ----
    gemm_kernel<1, false><<<g128, 256>>>(h, head_W1, head_b1, t1, HDIM, 128);
    head_final_kernel<<<BNODES / 8, 256>>>(t1, head_W2, head_b2, (float*)d_out);
}

// round 2
// speedup vs baseline: 1.3081x; 1.3081x over previous
#include <cuda_runtime.h>
#include <cuda_bf16.h>
#include <math.h>

// Problem constants
#define BNODES 8192      // B*N
#define HDIM   256
#define NEDGE  131072
#define NLAYER 4

// ---------------- scratch (device globals; no allocation allowed) ----------
__device__ float g_h [BNODES * HDIM];
__device__ float g_t1[BNODES * 1024];
__device__ float g_t2[BNODES * HDIM];
__device__ float g_t3[BNODES * HDIM];
__device__ int   g_cnt[BNODES];
__device__ int   g_off[BNODES + 1];
__device__ int   g_cur[BNODES];
__device__ int   g_eidx[NEDGE];
__device__ float g_psum[128 * HDIM];
__device__ float g_psq [128 * HDIM];
__device__ float g_mean[HDIM];
__device__ float g_istd[HDIM];

__device__ __forceinline__ float gelu_f(float x) {
    return 0.5f * x * (1.0f + erff(x * 0.70710678118654752f));
}

__device__ __forceinline__ unsigned f2tf32(float x) {
    unsigned y;
    asm("cvt.rna.tf32.f32 %0, %1;" : "=r"(y) : "f"(x));
    return y;
}

#define MMA_TF32(c0,c1,c2,c3, a0,a1,a2,a3, b0,b1)                          \
    asm volatile(                                                          \
        "mma.sync.aligned.m16n8k8.row.col.f32.tf32.tf32.f32 "              \
        "{%0,%1,%2,%3}, {%4,%5,%6,%7}, {%8,%9}, {%0,%1,%2,%3};\n"          \
        : "+f"(c0), "+f"(c1), "+f"(c2), "+f"(c3)                            \
        : "r"(a0), "r"(a1), "r"(a2), "r"(a3), "r"(b0), "r"(b1))

// ---------------- tf32 tensor-core GEMM: C = act(A @ W^T + bias [+ C]) -----
// A: (M,K) rm, W: (N,K) rm. M mult of 128, N mult of 128, K mult of 8.
// 128x128 block tile, 8 warps (2x4), warp tile 64x32, BK=16, m16n8k8 tf32.
template<int ACT, bool ACCUM>
__global__ __launch_bounds__(256, 2)
void gemm_tc_kernel(const float* __restrict__ A, const float* __restrict__ W,
                    const float* __restrict__ bias, float* __restrict__ C,
                    int K, int N) {
    __shared__ unsigned As[128][17];
    __shared__ unsigned Bs[128][17];
    const int bm = blockIdx.y * 128, bn = blockIdx.x * 128;
    const int tid  = threadIdx.x;
    const int lane = tid & 31;
    const int wid  = tid >> 5;
    const int wm   = wid >> 2;        // 0..1
    const int wn   = wid & 3;         // 0..3
    const int g    = lane >> 2;       // 0..7
    const int tig  = lane & 3;        // 0..3

    const int lrow  = tid >> 1;       // 0..127
    const int lhalf = (tid & 1) * 8;  // 0 or 8

    float acc[4][4][4] = {};

    const float* Arow = A + (size_t)(bm + lrow) * K;
    const float* Wrow = W + (size_t)(bn + lrow) * K;

    const int KT = (K + 15) >> 4;
    for (int it = 0; it < KT; it++) {
        const int k0 = it * 16;
        // load + convert A,B tiles into smem
        {
            float4 v0 = make_float4(0.f,0.f,0.f,0.f), v1 = v0;
            if (k0 + lhalf < K)     v0 = *(const float4*)(Arow + k0 + lhalf);
            if (k0 + lhalf + 4 < K) v1 = *(const float4*)(Arow + k0 + lhalf + 4);
            As[lrow][lhalf+0] = f2tf32(v0.x); As[lrow][lhalf+1] = f2tf32(v0.y);
            As[lrow][lhalf+2] = f2tf32(v0.z); As[lrow][lhalf+3] = f2tf32(v0.w);
            As[lrow][lhalf+4] = f2tf32(v1.x); As[lrow][lhalf+5] = f2tf32(v1.y);
            As[lrow][lhalf+6] = f2tf32(v1.z); As[lrow][lhalf+7] = f2tf32(v1.w);
            v0 = make_float4(0.f,0.f,0.f,0.f); v1 = v0;
            if (k0 + lhalf < K)     v0 = *(const float4*)(Wrow + k0 + lhalf);
            if (k0 + lhalf + 4 < K) v1 = *(const float4*)(Wrow + k0 + lhalf + 4);
            Bs[lrow][lhalf+0] = f2tf32(v0.x); Bs[lrow][lhalf+1] = f2tf32(v0.y);
            Bs[lrow][lhalf+2] = f2tf32(v0.z); Bs[lrow][lhalf+3] = f2tf32(v0.w);
            Bs[lrow][lhalf+4] = f2tf32(v1.x); Bs[lrow][lhalf+5] = f2tf32(v1.y);
            Bs[lrow][lhalf+6] = f2tf32(v1.z); Bs[lrow][lhalf+7] = f2tf32(v1.w);
        }
        __syncthreads();

        #pragma unroll
        for (int ks = 0; ks < 2; ks++) {
            const int kc = ks * 8 + tig;
            unsigned a[4][4], b[4][2];
            #pragma unroll
            for (int mt = 0; mt < 4; mt++) {
                const int r = wm * 64 + mt * 16 + g;
                a[mt][0] = As[r    ][kc];
                a[mt][1] = As[r + 8][kc];
                a[mt][2] = As[r    ][kc + 4];
                a[mt][3] = As[r + 8][kc + 4];
            }
            #pragma unroll
            for (int nt = 0; nt < 4; nt++) {
                const int r = wn * 32 + nt * 8 + g;
                b[nt][0] = Bs[r][kc];
                b[nt][1] = Bs[r][kc + 4];
            }
            #pragma unroll
            for (int mt = 0; mt < 4; mt++)
                #pragma unroll
                for (int nt = 0; nt < 4; nt++)
                    MMA_TF32(acc[mt][nt][0], acc[mt][nt][1],
                             acc[mt][nt][2], acc[mt][nt][3],
                             a[mt][0], a[mt][1], a[mt][2], a[mt][3],
                             b[nt][0], b[nt][1]);
        }
        __syncthreads();
    }

    // epilogue
    #pragma unroll
    for (int mt = 0; mt < 4; mt++) {
        const int row = bm + wm * 64 + mt * 16 + g;
        #pragma unroll
        for (int nt = 0; nt < 4; nt++) {
            const int col = bn + wn * 32 + nt * 8 + 2 * tig;
            float b0 = 0.f, b1 = 0.f;
            if (bias) { b0 = bias[col]; b1 = bias[col + 1]; }
            #pragma unroll
            for (int half = 0; half < 2; half++) {
                const int r = row + half * 8;
                size_t idx = (size_t)r * N + col;
                float c0 = acc[mt][nt][half * 2 + 0] + b0;
                float c1 = acc[mt][nt][half * 2 + 1] + b1;
                if (ACCUM) { c0 += C[idx]; c1 += C[idx + 1]; }
                if (ACT == 1) { c0 = gelu_f(c0); c1 = gelu_f(c1); }
                C[idx]     = c0;
                C[idx + 1] = c1;
            }
        }
    }
}

// ---------------- CSR build (per-launch, from edge_row) --------------------
__global__ void count_deg_kernel(const int* __restrict__ row, int* __restrict__ cnt) {
    int e = blockIdx.x * 256 + threadIdx.x;
    if (e < NEDGE) atomicAdd(&cnt[row[e]], 1);
}

__global__ void scan_kernel(const int* __restrict__ cnt, int* __restrict__ off,
                            int* __restrict__ cur) {
    __shared__ int part[256];
    const int t = threadIdx.x;
    int loc[32];
    int s = 0;
    #pragma unroll
    for (int i = 0; i < 32; i++) { loc[i] = s; s += cnt[t * 32 + i]; }
    part[t] = s;
    __syncthreads();
    for (int ofs = 1; ofs < 256; ofs <<= 1) {
        int mine = part[t];
        int add = (t >= ofs) ? part[t - ofs] : 0;
        __syncthreads();
        part[t] = mine + add;
        __syncthreads();
    }
    int excl = (t > 0) ? part[t - 1] : 0;
    #pragma unroll
    for (int i = 0; i < 32; i++) {
        int v = excl + loc[i];
        off[t * 32 + i] = v;
        cur[t * 32 + i] = v;
    }
    if (t == 255) off[BNODES] = part[255];
}

__global__ void fill_csr_kernel(const int* __restrict__ row, int* __restrict__ cur,
                                int* __restrict__ eidx) {
    int e = blockIdx.x * 256 + threadIdx.x;
    if (e < NEDGE) {
        int p = atomicAdd(&cur[row[e]], 1);
        eidx[p] = e;
    }
}

// ---------------- GCN gather ------------------------------------------------
__global__ void gcn_gather_kernel(const float* __restrict__ t1,
                                  const int* __restrict__ off,
                                  const int* __restrict__ eidx,
                                  const int* __restrict__ ecol,
                                  const float* __restrict__ eval,
                                  float* __restrict__ agg) {
    const int node = blockIdx.x;
    const int f = threadIdx.x;
    __shared__ int   scol[64];
    __shared__ float sval[64];
    const int s = off[node], e_end = off[node + 1];
    float acc = 0.f;
    for (int base = s; base < e_end; base += 64) {
        int n = min(64, e_end - base);
        if (f < n) {
            int e = eidx[base + f];
            scol[f] = ecol[e];
            sval[f] = eval[e];
        }
        __syncthreads();
        for (int j = 0; j < n; j++)
            acc += sval[j] * t1[(size_t)scol[j] * HDIM + f];
        __syncthreads();
    }
    agg[(size_t)node * HDIM + f] = acc;
}

// ---------------- BatchNorm -------------------------------------------------
template<int ACT>
__global__ void bnpre_kernel(float* __restrict__ h, const float* __restrict__ add,
                             float* __restrict__ psum, float* __restrict__ psq) {
    const int f = threadIdx.x;
    const int blk = blockIdx.x;
    float s = 0.f, sq = 0.f;
    size_t base = (size_t)blk * 64 * HDIM + f;
    #pragma unroll 4
    for (int r = 0; r < 64; r++) {
        size_t idx = base + (size_t)r * HDIM;
        float a = add[idx];
        if (ACT == 1) a = gelu_f(a);
        float v = h[idx] + a;
        h[idx] = v;
        s += v;
        sq += v * v;
    }
    psum[blk * HDIM + f] = s;
    psq [blk * HDIM + f] = sq;
}

__global__ void bnfin_kernel(const float* __restrict__ psum, const float* __restrict__ psq,
                             float* __restrict__ mean, float* __restrict__ istd) {
    const int f = threadIdx.x;
    float s = 0.f, sq = 0.f;
    for (int b = 0; b < 128; b++) { s += psum[b * HDIM + f]; sq += psq[b * HDIM + f]; }
    float m = s * (1.0f / BNODES);
    float v = sq * (1.0f / BNODES) - m * m;
    mean[f] = m;
    istd[f] = rsqrtf(v + 1e-5f);
}

__global__ void bnapply_kernel(float* __restrict__ h, const float* __restrict__ mean,
                               const float* __restrict__ istd, const float* __restrict__ g,
                               const float* __restrict__ b) {
    const int f = threadIdx.x;
    const float mu = mean[f], is_ = istd[f], gg = g[f], bb = b[f];
    size_t base = (size_t)blockIdx.x * 8 * HDIM + f;
    #pragma unroll
    for (int r = 0; r < 8; r++) {
        size_t i = base + (size_t)r * HDIM;
        h[i] = (h[i] - mu) * is_ * gg + bb;
    }
}

// ---------------- Flash attention (fp32, unchanged this round) -------------
__global__ void attn_kernel(const float* __restrict__ qkv, float* __restrict__ out) {
    const int qt = blockIdx.x, nh = blockIdx.y, b = blockIdx.z;
    __shared__ float Qs[64][33];
    __shared__ float Ks[64][33];
    __shared__ float Vs[64][33];
    __shared__ float Ss[64][65];
    const int tid = threadIdx.x;
    const int tq = tid >> 4, tc = tid & 15;
    const float scale = 0.17677669529663687f;

    size_t qoff = ((size_t)(b * 1024 + qt * 64)) * 768 + nh * 32;
    {
        int r0 = tid >> 5, d = tid & 31;
        for (int r = r0; r < 64; r += 8)
            Qs[r][d] = qkv[qoff + (size_t)r * 768 + d];
    }
    float m[4], l[4], o[4][2];
    #pragma unroll
    for (int i = 0; i < 4; i++) { m[i] = -1e30f; l[i] = 0.f; o[i][0] = 0.f; o[i][1] = 0.f; }
    __syncthreads();

    for (int kt = 0; kt < 16; kt++) {
        size_t koff = ((size_t)(b * 1024 + kt * 64)) * 768 + nh * 32;
        {
            int r0 = tid >> 5, d = tid & 31;
            for (int r = r0; r < 64; r += 8) {
                Ks[r][d] = qkv[koff + (size_t)r * 768 + 256 + d];
                Vs[r][d] = qkv[koff + (size_t)r * 768 + 512 + d];
            }
        }
        __syncthreads();

        float sv[4][4] = {};
        #pragma unroll
        for (int d = 0; d < 32; d++) {
            float qv[4], kv[4];
            #pragma unroll
            for (int i = 0; i < 4; i++) qv[i] = Qs[tq * 4 + i][d];
            #pragma unroll
            for (int j = 0; j < 4; j++) kv[j] = Ks[tc * 4 + j][d];
            #pragma unroll
            for (int i = 0; i < 4; i++)
                #pragma unroll
                for (int j = 0; j < 4; j++)
                    sv[i][j] += qv[i] * kv[j];
        }

        #pragma unroll
        for (int i = 0; i < 4; i++) {
            #pragma unroll
            for (int j = 0; j < 4; j++) sv[i][j] *= scale;
            float rmax = fmaxf(fmaxf(sv[i][0], sv[i][1]), fmaxf(sv[i][2], sv[i][3]));
            #pragma unroll
            for (int ofs = 1; ofs < 16; ofs <<= 1)
                rmax = fmaxf(rmax, __shfl_xor_sync(0xffffffffu, rmax, ofs));
            float mnew = fmaxf(m[i], rmax);
            float corr = __expf(m[i] - mnew);
            float ps = 0.f;
            #pragma unroll
            for (int j = 0; j < 4; j++) {
                float p = __expf(sv[i][j] - mnew);
                Ss[tq * 4 + i][tc * 4 + j] = p;
                ps += p;
            }
            #pragma unroll
            for (int ofs = 1; ofs < 16; ofs <<= 1)
                ps += __shfl_xor_sync(0xffffffffu, ps, ofs);
            l[i] = l[i] * corr + ps;
            m[i] = mnew;
            o[i][0] *= corr;
            o[i][1] *= corr;
        }
        __syncwarp();

        #pragma unroll 8
        for (int kc = 0; kc < 64; kc++) {
            float v0 = Vs[kc][tc * 2];
            float v1 = Vs[kc][tc * 2 + 1];
            #pragma unroll
            for (int i = 0; i < 4; i++) {
                float p = Ss[tq * 4 + i][kc];
                o[i][0] += p * v0;
                o[i][1] += p * v1;
            }
        }
        __syncthreads();
    }

    #pragma unroll
    for (int i = 0; i < 4; i++) {
        float inv = 1.0f / l[i];
        size_t off = ((size_t)(b * 1024 + qt * 64 + tq * 4 + i)) * HDIM + nh * 32 + tc * 2;
        out[off]     = o[i][0] * inv;
        out[off + 1] = o[i][1] * inv;
    }
}

// ---------------- head final ------------------------------------------------
__global__ void head_final_kernel(const float* __restrict__ t, const float* __restrict__ w,
                                  const float* __restrict__ b, float* __restrict__ out) {
    int row = blockIdx.x * 8 + (threadIdx.x >> 5);
    int lane = threadIdx.x & 31;
    float acc = 0.f;
    #pragma unroll
    for (int i = lane; i < 128; i += 32)
        acc += t[(size_t)row * 128 + i] * w[i];
    #pragma unroll
    for (int ofs = 16; ofs; ofs >>= 1)
        acc += __shfl_xor_sync(0xffffffffu, acc, ofs);
    if (lane == 0)
        out[row] = 1.0f / (1.0f + expf(-(acc + b[0])));
}

// ---------------- host orchestration ----------------------------------------
static void bn_block(float* h, const float* add, int act,
                     const float* g, const float* b,
                     float* psum, float* psq, float* mean, float* istd) {
    if (act) bnpre_kernel<1><<<128, 256>>>(h, add, psum, psq);
    else     bnpre_kernel<0><<<128, 256>>>(h, add, psum, psq);
    bnfin_kernel<<<1, 256>>>(psum, psq, mean, istd);
    bnapply_kernel<<<1024, 256>>>(h, mean, istd, g, b);
}

extern "C" void kernel_launch(void* const* d_in, const int* in_sizes, int n_in,
                              void* d_out, int out_size) {
    const float* x        = (const float*)d_in[0];
    const int*   erow     = (const int*)  d_in[1];
    const int*   ecol     = (const int*)  d_in[2];
    const float* eval     = (const float*)d_in[3];
    const float* pe       = (const float*)d_in[4];
    const float* W_in     = (const float*)d_in[5];
    const float* b_in     = (const float*)d_in[6];
    const float* W_pe     = (const float*)d_in[7];
    const float* b_pe     = (const float*)d_in[8];
    const float* gcn_W    = (const float*)d_in[9];
    const float* ain_W    = (const float*)d_in[10];
    const float* ain_b    = (const float*)d_in[11];
    const float* aout_W   = (const float*)d_in[12];
    const float* aout_b   = (const float*)d_in[13];
    const float* bn_g     = (const float*)d_in[14];
    const float* bn_b     = (const float*)d_in[15];
    const float* ffn_W1   = (const float*)d_in[16];
    const float* ffn_b1   = (const float*)d_in[17];
    const float* ffn_W2   = (const float*)d_in[18];
    const float* ffn_b2   = (const float*)d_in[19];
    const float* head_W1  = (const float*)d_in[20];
    const float* head_b1  = (const float*)d_in[21];
    const float* head_W2  = (const float*)d_in[22];
    const float* head_b2  = (const float*)d_in[23];

    float *h, *t1, *t2, *t3, *psum, *psq, *mean, *istd;
    int *cnt, *off, *cur, *eidx;
    cudaGetSymbolAddress((void**)&h,    g_h);
    cudaGetSymbolAddress((void**)&t1,   g_t1);
    cudaGetSymbolAddress((void**)&t2,   g_t2);
    cudaGetSymbolAddress((void**)&t3,   g_t3);
    cudaGetSymbolAddress((void**)&psum, g_psum);
    cudaGetSymbolAddress((void**)&psq,  g_psq);
    cudaGetSymbolAddress((void**)&mean, g_mean);
    cudaGetSymbolAddress((void**)&istd, g_istd);
    cudaGetSymbolAddress((void**)&cnt,  g_cnt);
    cudaGetSymbolAddress((void**)&off,  g_off);
    cudaGetSymbolAddress((void**)&cur,  g_cur);
    cudaGetSymbolAddress((void**)&eidx, g_eidx);

    cudaMemsetAsync(cnt, 0, BNODES * sizeof(int));
    count_deg_kernel<<<NEDGE / 256, 256>>>(erow, cnt);
    scan_kernel<<<1, 256>>>(cnt, off, cur);
    fill_csr_kernel<<<NEDGE / 256, 256>>>(erow, cur, eidx);

    const dim3 g256 (HDIM / 128,  BNODES / 128);   // (2,64)
    const dim3 g768 (768 / 128,   BNODES / 128);   // (6,64)
    const dim3 g1024(1024 / 128,  BNODES / 128);   // (8,64)
    const dim3 g128 (128 / 128,   BNODES / 128);   // (1,64)

    // input projection: h = x@W_in^T + b_in + pe@W_pe^T + b_pe
    gemm_tc_kernel<0, false><<<g256, 256>>>(x,  W_in, b_in, h, 128, HDIM);
    gemm_tc_kernel<0, true ><<<g256, 256>>>(pe, W_pe, b_pe, h, 8,   HDIM);

    for (int l = 0; l < NLAYER; l++) {
        // ---- local GCN ----
        gemm_tc_kernel<0, false><<<g256, 256>>>(h, gcn_W + (size_t)l * HDIM * HDIM,
                                                nullptr, t1, HDIM, HDIM);
        gcn_gather_kernel<<<BNODES, 256>>>(t1, off, eidx, ecol, eval, t2);
        bn_block(h, t2, 1, bn_g + l * 3 * HDIM, bn_b + l * 3 * HDIM,
                 psum, psq, mean, istd);
        // ---- global attention ----
        gemm_tc_kernel<0, false><<<g768, 256>>>(h, ain_W + (size_t)l * 768 * HDIM,
                                                ain_b + l * 768, t1, HDIM, 768);
        attn_kernel<<<dim3(16, 8, 8), 256>>>(t1, t2);
        gemm_tc_kernel<0, false><<<g256, 256>>>(t2, aout_W + (size_t)l * HDIM * HDIM,
                                                aout_b + l * HDIM, t3, HDIM, HDIM);
        bn_block(h, t3, 0, bn_g + l * 3 * HDIM + HDIM, bn_b + l * 3 * HDIM + HDIM,
                 psum, psq, mean, istd);
        // ---- FFN ----
        gemm_tc_kernel<1, false><<<g1024, 256>>>(h, ffn_W1 + (size_t)l * 1024 * HDIM,
                                                 ffn_b1 + l * 1024, t1, HDIM, 1024);
        gemm_tc_kernel<0, false><<<g256, 256>>>(t1, ffn_W2 + (size_t)l * HDIM * 1024,
                                                ffn_b2 + l * HDIM, t3, 1024, HDIM);
        bn_block(h, t3, 0, bn_g + l * 3 * HDIM + 2 * HDIM, bn_b + l * 3 * HDIM + 2 * HDIM,
                 psum, psq, mean, istd);
    }

    // ---- head ----
    gemm_tc_kernel<1, false><<<g128, 256>>>(h, head_W1, head_b1, t1, HDIM, 128);
    head_final_kernel<<<BNODES / 8, 256>>>(t1, head_W2, head_b2, (float*)d_out);
}

// round 3
// speedup vs baseline: 1.7140x; 1.3103x over previous
#include <cuda_runtime.h>
#include <cuda_bf16.h>
#include <math.h>

#define BNODES 8192
#define HDIM   256
#define NEDGE  131072
#define NLAYER 4

__device__ float g_h [BNODES * HDIM];
__device__ float g_t1[BNODES * 1024];
__device__ float g_t2[BNODES * HDIM];
__device__ float g_t3[BNODES * HDIM];
__device__ int   g_cnt[BNODES];
__device__ int   g_off[BNODES + 1];
__device__ int   g_cur[BNODES];
__device__ int   g_eidx[NEDGE];
__device__ float g_psum[128 * HDIM];
__device__ float g_psq [128 * HDIM];
__device__ float g_mean[HDIM];
__device__ float g_istd[HDIM];

__device__ __forceinline__ float gelu_f(float x) {
    return 0.5f * x * (1.0f + erff(x * 0.70710678118654752f));
}

__device__ __forceinline__ unsigned f2tf32(float x) {
    unsigned y;
    asm("cvt.rna.tf32.f32 %0, %1;" : "=r"(y) : "f"(x));
    return y;
}

#define MMA_TF32(c0,c1,c2,c3, a0,a1,a2,a3, b0,b1)                          \
    asm volatile(                                                          \
        "mma.sync.aligned.m16n8k8.row.col.f32.tf32.tf32.f32 "              \
        "{%0,%1,%2,%3}, {%4,%5,%6,%7}, {%8,%9}, {%0,%1,%2,%3};\n"          \
        : "+f"(c0), "+f"(c1), "+f"(c2), "+f"(c3)                            \
        : "r"(a0), "r"(a1), "r"(a2), "r"(a3), "r"(b0), "r"(b1))

// ---------------- tf32 GEMM: C = act(A @ W^T + bias [+ C]) -----------------
// Block tile TM x 128. 8 warps (2 x 4): warp tile (TM/2) x 32. BK=16.
template<int TM, int ACT, bool ACCUM>
__global__ __launch_bounds__(256, 2)
void gemm_tc_kernel(const float* __restrict__ A, const float* __restrict__ W,
                    const float* __restrict__ bias, float* __restrict__ C,
                    int K, int N) {
    constexpr int MT = TM / 32;
    __shared__ unsigned As[TM][17];
    __shared__ unsigned Bs[128][17];
    const int bm = blockIdx.y * TM, bn = blockIdx.x * 128;
    const int tid  = threadIdx.x;
    const int lane = tid & 31;
    const int wid  = tid >> 5;
    const int wm   = wid >> 2;
    const int wn   = wid & 3;
    const int g    = lane >> 2;
    const int tig  = lane & 3;

    const int lrow  = tid >> 1;
    const int lhalf = (tid & 1) * 8;
    const int lrowA = tid >> 2;          // TM==64 path
    const int lq    = (tid & 3) * 4;

    float acc[MT][4][4] = {};

    const float* Wrow = W + (size_t)(bn + lrow) * K;

    const int KT = (K + 15) >> 4;
    for (int it = 0; it < KT; it++) {
        const int k0 = it * 16;
        if (TM == 128) {
            const float* Arow = A + (size_t)(bm + lrow) * K;
            float4 v0 = make_float4(0.f,0.f,0.f,0.f), v1 = v0;
            if (k0 + lhalf < K)     v0 = *(const float4*)(Arow + k0 + lhalf);
            if (k0 + lhalf + 4 < K) v1 = *(const float4*)(Arow + k0 + lhalf + 4);
            As[lrow][lhalf+0] = f2tf32(v0.x); As[lrow][lhalf+1] = f2tf32(v0.y);
            As[lrow][lhalf+2] = f2tf32(v0.z); As[lrow][lhalf+3] = f2tf32(v0.w);
            As[lrow][lhalf+4] = f2tf32(v1.x); As[lrow][lhalf+5] = f2tf32(v1.y);
            As[lrow][lhalf+6] = f2tf32(v1.z); As[lrow][lhalf+7] = f2tf32(v1.w);
        } else {
            const float* Arow = A + (size_t)(bm + lrowA) * K;
            float4 v0 = make_float4(0.f,0.f,0.f,0.f);
            if (k0 + lq < K) v0 = *(const float4*)(Arow + k0 + lq);
            As[lrowA][lq+0] = f2tf32(v0.x); As[lrowA][lq+1] = f2tf32(v0.y);
            As[lrowA][lq+2] = f2tf32(v0.z); As[lrowA][lq+3] = f2tf32(v0.w);
        }
        {
            float4 v0 = make_float4(0.f,0.f,0.f,0.f), v1 = v0;
            if (k0 + lhalf < K)     v0 = *(const float4*)(Wrow + k0 + lhalf);
            if (k0 + lhalf + 4 < K) v1 = *(const float4*)(Wrow + k0 + lhalf + 4);
            Bs[lrow][lhalf+0] = f2tf32(v0.x); Bs[lrow][lhalf+1] = f2tf32(v0.y);
            Bs[lrow][lhalf+2] = f2tf32(v0.z); Bs[lrow][lhalf+3] = f2tf32(v0.w);
            Bs[lrow][lhalf+4] = f2tf32(v1.x); Bs[lrow][lhalf+5] = f2tf32(v1.y);
            Bs[lrow][lhalf+6] = f2tf32(v1.z); Bs[lrow][lhalf+7] = f2tf32(v1.w);
        }
        __syncthreads();

        #pragma unroll
        for (int ks = 0; ks < 2; ks++) {
            const int kc = ks * 8 + tig;
            unsigned a[MT][4], b[4][2];
            #pragma unroll
            for (int mt = 0; mt < MT; mt++) {
                const int r = wm * (TM/2) + mt * 16 + g;
                a[mt][0] = As[r    ][kc];
                a[mt][1] = As[r + 8][kc];
                a[mt][2] = As[r    ][kc + 4];
                a[mt][3] = As[r + 8][kc + 4];
            }
            #pragma unroll
            for (int nt = 0; nt < 4; nt++) {
                const int r = wn * 32 + nt * 8 + g;
                b[nt][0] = Bs[r][kc];
                b[nt][1] = Bs[r][kc + 4];
            }
            #pragma unroll
            for (int mt = 0; mt < MT; mt++)
                #pragma unroll
                for (int nt = 0; nt < 4; nt++)
                    MMA_TF32(acc[mt][nt][0], acc[mt][nt][1],
                             acc[mt][nt][2], acc[mt][nt][3],
                             a[mt][0], a[mt][1], a[mt][2], a[mt][3],
                             b[nt][0], b[nt][1]);
        }
        __syncthreads();
    }

    #pragma unroll
    for (int mt = 0; mt < MT; mt++) {
        const int row = bm + wm * (TM/2) + mt * 16 + g;
        #pragma unroll
        for (int nt = 0; nt < 4; nt++) {
            const int col = bn + wn * 32 + nt * 8 + 2 * tig;
            float b0 = 0.f, b1 = 0.f;
            if (bias) { b0 = bias[col]; b1 = bias[col + 1]; }
            #pragma unroll
            for (int half = 0; half < 2; half++) {
                const int r = row + half * 8;
                size_t idx = (size_t)r * N + col;
                float c0 = acc[mt][nt][half * 2 + 0] + b0;
                float c1 = acc[mt][nt][half * 2 + 1] + b1;
                if (ACCUM) { c0 += C[idx]; c1 += C[idx + 1]; }
                if (ACT == 1) { c0 = gelu_f(c0); c1 = gelu_f(c1); }
                C[idx]     = c0;
                C[idx + 1] = c1;
            }
        }
    }
}

// ---------------- CSR build -------------------------------------------------
__global__ void count_deg_kernel(const int* __restrict__ row, int* __restrict__ cnt) {
    int e = blockIdx.x * 256 + threadIdx.x;
    if (e < NEDGE) atomicAdd(&cnt[row[e]], 1);
}

__global__ void scan_kernel(const int* __restrict__ cnt, int* __restrict__ off,
                            int* __restrict__ cur) {
    __shared__ int part[256];
    const int t = threadIdx.x;
    int loc[32];
    int s = 0;
    #pragma unroll
    for (int i = 0; i < 32; i++) { loc[i] = s; s += cnt[t * 32 + i]; }
    part[t] = s;
    __syncthreads();
    for (int ofs = 1; ofs < 256; ofs <<= 1) {
        int mine = part[t];
        int add = (t >= ofs) ? part[t - ofs] : 0;
        __syncthreads();
        part[t] = mine + add;
        __syncthreads();
    }
    int excl = (t > 0) ? part[t - 1] : 0;
    #pragma unroll
    for (int i = 0; i < 32; i++) {
        int v = excl + loc[i];
        off[t * 32 + i] = v;
        cur[t * 32 + i] = v;
    }
    if (t == 255) off[BNODES] = part[255];
}

__global__ void fill_csr_kernel(const int* __restrict__ row, int* __restrict__ cur,
                                int* __restrict__ eidx) {
    int e = blockIdx.x * 256 + threadIdx.x;
    if (e < NEDGE) {
        int p = atomicAdd(&cur[row[e]], 1);
        eidx[p] = e;
    }
}

// ---------------- GCN gather ------------------------------------------------
__global__ void gcn_gather_kernel(const float* __restrict__ t1,
                                  const int* __restrict__ off,
                                  const int* __restrict__ eidx,
                                  const int* __restrict__ ecol,
                                  const float* __restrict__ eval,
                                  float* __restrict__ agg) {
    const int node = blockIdx.x;
    const int f = threadIdx.x;
    __shared__ int   scol[64];
    __shared__ float sval[64];
    const int s = off[node], e_end = off[node + 1];
    float acc = 0.f;
    for (int base = s; base < e_end; base += 64) {
        int n = min(64, e_end - base);
        if (f < n) {
            int e = eidx[base + f];
            scol[f] = ecol[e];
            sval[f] = eval[e];
        }
        __syncthreads();
        for (int j = 0; j < n; j++)
            acc += sval[j] * t1[(size_t)scol[j] * HDIM + f];
        __syncthreads();
    }
    agg[(size_t)node * HDIM + f] = acc;
}

// ---------------- BatchNorm -------------------------------------------------
template<int ACT>
__global__ void bnpre_kernel(float* __restrict__ h, const float* __restrict__ add,
                             float* __restrict__ psum, float* __restrict__ psq) {
    const int f = threadIdx.x;
    const int blk = blockIdx.x;
    float s = 0.f, sq = 0.f;
    size_t base = (size_t)blk * 64 * HDIM + f;
    #pragma unroll 4
    for (int r = 0; r < 64; r++) {
        size_t idx = base + (size_t)r * HDIM;
        float a = add[idx];
        if (ACT == 1) a = gelu_f(a);
        float v = h[idx] + a;
        h[idx] = v;
        s += v;
        sq += v * v;
    }
    psum[blk * HDIM + f] = s;
    psq [blk * HDIM + f] = sq;
}

__global__ void bnfin_kernel(const float* __restrict__ psum, const float* __restrict__ psq,
                             float* __restrict__ mean, float* __restrict__ istd) {
    const int f = threadIdx.x;
    float s = 0.f, sq = 0.f;
    for (int b = 0; b < 128; b++) { s += psum[b * HDIM + f]; sq += psq[b * HDIM + f]; }
    float m = s * (1.0f / BNODES);
    float v = sq * (1.0f / BNODES) - m * m;
    mean[f] = m;
    istd[f] = rsqrtf(v + 1e-5f);
}

__global__ void bnapply_kernel(float* __restrict__ h, const float* __restrict__ mean,
                               const float* __restrict__ istd, const float* __restrict__ g,
                               const float* __restrict__ b) {
    const int f = threadIdx.x;
    const float mu = mean[f], is_ = istd[f], gg = g[f], bb = b[f];
    size_t base = (size_t)blockIdx.x * 8 * HDIM + f;
    #pragma unroll
    for (int r = 0; r < 8; r++) {
        size_t i = base + (size_t)r * HDIM;
        h[i] = (h[i] - mu) * is_ * gg + bb;
    }
}

// ---------------- tf32 tensor-core flash attention --------------------------
// grid (16 q-tiles, 8 heads, 8 graphs), 128 threads (4 warps).
// Warp w owns 16 q-rows. S=Q@K^T and O=P@V via m16n8k8 tf32.
__global__ __launch_bounds__(128)
void attn_tc_kernel(const float* __restrict__ qkv, float* __restrict__ out) {
    const int qt = blockIdx.x, nh = blockIdx.y, b = blockIdx.z;
    __shared__ unsigned Ks[64][33];   // [kvpos][dim]
    __shared__ unsigned Vs[64][40];   // [kvpos][dim]
    __shared__ unsigned Ss[64][68];   // P tiles (tf32); also Q float staging
    float* Ssf = (float*)&Ss[0][0];   // 64 x 68 float view

    const int tid  = threadIdx.x;
    const int lane = tid & 31;
    const int w    = tid >> 5;
    const int g    = lane >> 2;
    const int tig  = lane & 3;
    const float scale = 0.17677669529663687f;  // 1/sqrt(32)

    const size_t rowb = (size_t)(b * 1024) * 768 + nh * 32;

    // stage Q (64 x 32) into Ssf, then extract per-warp fragments
    {
        size_t qoff = rowb + (size_t)(qt * 64) * 768;
        #pragma unroll
        for (int i = 0; i < 4; i++) {
            int idx = tid + i * 128;
            int r = idx >> 3, c4 = (idx & 7) * 4;
            float4 v = *(const float4*)(qkv + qoff + (size_t)r * 768 + c4);
            Ssf[r * 68 + c4 + 0] = v.x; Ssf[r * 68 + c4 + 1] = v.y;
            Ssf[r * 68 + c4 + 2] = v.z; Ssf[r * 68 + c4 + 3] = v.w;
        }
    }
    __syncthreads();

    unsigned q[4][4];
    {
        const int r0 = w * 16 + g;
        #pragma unroll
        for (int kt4 = 0; kt4 < 4; kt4++) {
            q[kt4][0] = f2tf32(Ssf[(r0    ) * 68 + kt4 * 8 + tig    ]);
            q[kt4][1] = f2tf32(Ssf[(r0 + 8) * 68 + kt4 * 8 + tig    ]);
            q[kt4][2] = f2tf32(Ssf[(r0    ) * 68 + kt4 * 8 + tig + 4]);
            q[kt4][3] = f2tf32(Ssf[(r0 + 8) * 68 + kt4 * 8 + tig + 4]);
        }
    }
    __syncthreads();

    float m0 = -1e30f, m1 = -1e30f, l0 = 0.f, l1 = 0.f;
    float o[4][4] = {};

    for (int kt = 0; kt < 16; kt++) {
        // load K,V tiles (64 x 32) as tf32
        size_t koff = rowb + (size_t)(kt * 64) * 768;
        #pragma unroll
        for (int i = 0; i < 4; i++) {
            int idx = tid + i * 128;
            int r = idx >> 3, c4 = (idx & 7) * 4;
            float4 kv = *(const float4*)(qkv + koff + (size_t)r * 768 + 256 + c4);
            float4 vv = *(const float4*)(qkv + koff + (size_t)r * 768 + 512 + c4);
            Ks[r][c4+0] = f2tf32(kv.x); Ks[r][c4+1] = f2tf32(kv.y);
            Ks[r][c4+2] = f2tf32(kv.z); Ks[r][c4+3] = f2tf32(kv.w);
            Vs[r][c4+0] = f2tf32(vv.x); Vs[r][c4+1] = f2tf32(vv.y);
            Vs[r][c4+2] = f2tf32(vv.z); Vs[r][c4+3] = f2tf32(vv.w);
        }
        __syncthreads();

        // S = Q @ K^T  (64x64, per warp 16x64)
        float s[8][4] = {};
        #pragma unroll
        for (int kt4 = 0; kt4 < 4; kt4++) {
            #pragma unroll
            for (int nt = 0; nt < 8; nt++) {
                unsigned b0 = Ks[nt * 8 + g][kt4 * 8 + tig];
                unsigned b1 = Ks[nt * 8 + g][kt4 * 8 + tig + 4];
                MMA_TF32(s[nt][0], s[nt][1], s[nt][2], s[nt][3],
                         q[kt4][0], q[kt4][1], q[kt4][2], q[kt4][3], b0, b1);
            }
        }

        // online softmax (rows w*16+g and w*16+g+8)
        float rmax0 = -1e30f, rmax1 = -1e30f;
        #pragma unroll
        for (int nt = 0; nt < 8; nt++) {
            s[nt][0] *= scale; s[nt][1] *= scale;
            s[nt][2] *= scale; s[nt][3] *= scale;
            rmax0 = fmaxf(rmax0, fmaxf(s[nt][0], s[nt][1]));
            rmax1 = fmaxf(rmax1, fmaxf(s[nt][2], s[nt][3]));
        }
        rmax0 = fmaxf(rmax0, __shfl_xor_sync(0xffffffffu, rmax0, 1));
        rmax0 = fmaxf(rmax0, __shfl_xor_sync(0xffffffffu, rmax0, 2));
        rmax1 = fmaxf(rmax1, __shfl_xor_sync(0xffffffffu, rmax1, 1));
        rmax1 = fmaxf(rmax1, __shfl_xor_sync(0xffffffffu, rmax1, 2));

        float mn0 = fmaxf(m0, rmax0), mn1 = fmaxf(m1, rmax1);
        float cor0 = __expf(m0 - mn0), cor1 = __expf(m1 - mn1);
        m0 = mn0; m1 = mn1;

        const int r0 = w * 16 + g;
        float ps0 = 0.f, ps1 = 0.f;
        #pragma unroll
        for (int nt = 0; nt < 8; nt++) {
            float p0 = __expf(s[nt][0] - mn0);
            float p1 = __expf(s[nt][1] - mn0);
            float p2 = __expf(s[nt][2] - mn1);
            float p3 = __expf(s[nt][3] - mn1);
            ps0 += p0 + p1; ps1 += p2 + p3;
            int c = nt * 8 + 2 * tig;
            Ss[r0    ][c] = f2tf32(p0); Ss[r0    ][c + 1] = f2tf32(p1);
            Ss[r0 + 8][c] = f2tf32(p2); Ss[r0 + 8][c + 1] = f2tf32(p3);
        }
        ps0 += __shfl_xor_sync(0xffffffffu, ps0, 1);
        ps0 += __shfl_xor_sync(0xffffffffu, ps0, 2);
        ps1 += __shfl_xor_sync(0xffffffffu, ps1, 1);
        ps1 += __shfl_xor_sync(0xffffffffu, ps1, 2);
        l0 = l0 * cor0 + ps0;
        l1 = l1 * cor1 + ps1;
        #pragma unroll
        for (int nt = 0; nt < 4; nt++) {
            o[nt][0] *= cor0; o[nt][1] *= cor0;
            o[nt][2] *= cor1; o[nt][3] *= cor1;
        }
        __syncwarp();

        // O += P @ V  (per warp 16x32)
        #pragma unroll
        for (int ks = 0; ks < 8; ks++) {
            unsigned a0 = Ss[r0    ][ks * 8 + tig];
            unsigned a1 = Ss[r0 + 8][ks * 8 + tig];
            unsigned a2 = Ss[r0    ][ks * 8 + tig + 4];
            unsigned a3 = Ss[r0 + 8][ks * 8 + tig + 4];
            #pragma unroll
            for (int nt = 0; nt < 4; nt++) {
                unsigned b0 = Vs[ks * 8 + tig    ][nt * 8 + g];
                unsigned b1 = Vs[ks * 8 + tig + 4][nt * 8 + g];
                MMA_TF32(o[nt][0], o[nt][1], o[nt][2], o[nt][3],
                         a0, a1, a2, a3, b0, b1);
            }
        }
        __syncthreads();
    }

    const float inv0 = 1.0f / l0, inv1 = 1.0f / l1;
    const int row0 = b * 1024 + qt * 64 + w * 16 + g;
    #pragma unroll
    for (int nt = 0; nt < 4; nt++) {
        const int col = nh * 32 + nt * 8 + 2 * tig;
        size_t i0 = (size_t)row0 * HDIM + col;
        size_t i1 = (size_t)(row0 + 8) * HDIM + col;
        out[i0]     = o[nt][0] * inv0;
        out[i0 + 1] = o[nt][1] * inv0;
        out[i1]     = o[nt][2] * inv1;
        out[i1 + 1] = o[nt][3] * inv1;
    }
}

// ---------------- head final ------------------------------------------------
__global__ void head_final_kernel(const float* __restrict__ t, const float* __restrict__ w,
                                  const float* __restrict__ b, float* __restrict__ out) {
    int row = blockIdx.x * 8 + (threadIdx.x >> 5);
    int lane = threadIdx.x & 31;
    float acc = 0.f;
    #pragma unroll
    for (int i = lane; i < 128; i += 32)
        acc += t[(size_t)row * 128 + i] * w[i];
    #pragma unroll
    for (int ofs = 16; ofs; ofs >>= 1)
        acc += __shfl_xor_sync(0xffffffffu, acc, ofs);
    if (lane == 0)
        out[row] = 1.0f / (1.0f + expf(-(acc + b[0])));
}

// ---------------- host orchestration ----------------------------------------
static void bn_block(float* h, const float* add, int act,
                     const float* g, const float* b,
                     float* psum, float* psq, float* mean, float* istd) {
    if (act) bnpre_kernel<1><<<128, 256>>>(h, add, psum, psq);
    else     bnpre_kernel<0><<<128, 256>>>(h, add, psum, psq);
    bnfin_kernel<<<1, 256>>>(psum, psq, mean, istd);
    bnapply_kernel<<<1024, 256>>>(h, mean, istd, g, b);
}

extern "C" void kernel_launch(void* const* d_in, const int* in_sizes, int n_in,
                              void* d_out, int out_size) {
    const float* x        = (const float*)d_in[0];
    const int*   erow     = (const int*)  d_in[1];
    const int*   ecol     = (const int*)  d_in[2];
    const float* eval     = (const float*)d_in[3];
    const float* pe       = (const float*)d_in[4];
    const float* W_in     = (const float*)d_in[5];
    const float* b_in     = (const float*)d_in[6];
    const float* W_pe     = (const float*)d_in[7];
    const float* b_pe     = (const float*)d_in[8];
    const float* gcn_W    = (const float*)d_in[9];
    const float* ain_W    = (const float*)d_in[10];
    const float* ain_b    = (const float*)d_in[11];
    const float* aout_W   = (const float*)d_in[12];
    const float* aout_b   = (const float*)d_in[13];
    const float* bn_g     = (const float*)d_in[14];
    const float* bn_b     = (const float*)d_in[15];
    const float* ffn_W1   = (const float*)d_in[16];
    const float* ffn_b1   = (const float*)d_in[17];
    const float* ffn_W2   = (const float*)d_in[18];
    const float* ffn_b2   = (const float*)d_in[19];
    const float* head_W1  = (const float*)d_in[20];
    const float* head_b1  = (const float*)d_in[21];
    const float* head_W2  = (const float*)d_in[22];
    const float* head_b2  = (const float*)d_in[23];

    float *h, *t1, *t2, *t3, *psum, *psq, *mean, *istd;
    int *cnt, *off, *cur, *eidx;
    cudaGetSymbolAddress((void**)&h,    g_h);
    cudaGetSymbolAddress((void**)&t1,   g_t1);
    cudaGetSymbolAddress((void**)&t2,   g_t2);
    cudaGetSymbolAddress((void**)&t3,   g_t3);
    cudaGetSymbolAddress((void**)&psum, g_psum);
    cudaGetSymbolAddress((void**)&psq,  g_psq);
    cudaGetSymbolAddress((void**)&mean, g_mean);
    cudaGetSymbolAddress((void**)&istd, g_istd);
    cudaGetSymbolAddress((void**)&cnt,  g_cnt);
    cudaGetSymbolAddress((void**)&off,  g_off);
    cudaGetSymbolAddress((void**)&cur,  g_cur);
    cudaGetSymbolAddress((void**)&eidx, g_eidx);

    cudaMemsetAsync(cnt, 0, BNODES * sizeof(int));
    count_deg_kernel<<<NEDGE / 256, 256>>>(erow, cnt);
    scan_kernel<<<1, 256>>>(cnt, off, cur);
    fill_csr_kernel<<<NEDGE / 256, 256>>>(erow, cur, eidx);

    const dim3 g256 (2, BNODES / 64);    // TM=64,  N=256  -> 256 blocks
    const dim3 g768 (6, BNODES / 128);   // TM=128, N=768  -> 384 blocks
    const dim3 g1024(8, BNODES / 128);   // TM=128, N=1024 -> 512 blocks
    const dim3 g128 (1, BNODES / 64);    // TM=64,  N=128  -> 128 blocks

    gemm_tc_kernel<64, 0, false><<<g256, 256>>>(x,  W_in, b_in, h, 128, HDIM);
    gemm_tc_kernel<64, 0, true ><<<g256, 256>>>(pe, W_pe, b_pe, h, 8,   HDIM);

    for (int l = 0; l < NLAYER; l++) {
        // ---- local GCN ----
        gemm_tc_kernel<64, 0, false><<<g256, 256>>>(h, gcn_W + (size_t)l * HDIM * HDIM,
                                                    nullptr, t1, HDIM, HDIM);
        gcn_gather_kernel<<<BNODES, 256>>>(t1, off, eidx, ecol, eval, t2);
        bn_block(h, t2, 1, bn_g + l * 3 * HDIM, bn_b + l * 3 * HDIM,
                 psum, psq, mean, istd);
        // ---- global attention ----
        gemm_tc_kernel<128, 0, false><<<g768, 256>>>(h, ain_W + (size_t)l * 768 * HDIM,
                                                     ain_b + l * 768, t1, HDIM, 768);
        attn_tc_kernel<<<dim3(16, 8, 8), 128>>>(t1, t2);
        gemm_tc_kernel<64, 0, false><<<g256, 256>>>(t2, aout_W + (size_t)l * HDIM * HDIM,
                                                    aout_b + l * HDIM, t3, HDIM, HDIM);
        bn_block(h, t3, 0, bn_g + l * 3 * HDIM + HDIM, bn_b + l * 3 * HDIM + HDIM,
                 psum, psq, mean, istd);
        // ---- FFN ----
        gemm_tc_kernel<128, 1, false><<<g1024, 256>>>(h, ffn_W1 + (size_t)l * 1024 * HDIM,
                                                      ffn_b1 + l * 1024, t1, HDIM, 1024);
        gemm_tc_kernel<64, 0, false><<<g256, 256>>>(t1, ffn_W2 + (size_t)l * HDIM * 1024,
                                                    ffn_b2 + l * HDIM, t3, 1024, HDIM);
        bn_block(h, t3, 0, bn_g + l * 3 * HDIM + 2 * HDIM, bn_b + l * 3 * HDIM + 2 * HDIM,
                 psum, psq, mean, istd);
    }

    gemm_tc_kernel<64, 1, false><<<g128, 256>>>(h, head_W1, head_b1, t1, HDIM, 128);
    head_final_kernel<<<BNODES / 8, 256>>>(t1, head_W2, head_b2, (float*)d_out);
}

// round 4
// speedup vs baseline: 2.2255x; 1.2984x over previous
#include <cuda_runtime.h>
#include <cuda_bf16.h>
#include <math.h>

#define BNODES 8192
#define HDIM   256
#define NEDGE  131072
#define NLAYER 4

__device__ float g_h [BNODES * HDIM];
__device__ float g_t1[BNODES * 1024];
__device__ float g_t2[BNODES * HDIM];
__device__ float g_t3[BNODES * HDIM];
__device__ int   g_cnt[BNODES];
__device__ int   g_off[BNODES + 1];
__device__ int   g_cur[BNODES];
__device__ int   g_eidx[NEDGE];
__device__ float g_psum[128 * HDIM];
__device__ float g_psq [128 * HDIM];

__device__ __forceinline__ float gelu_f(float x) {
    return 0.5f * x * (1.0f + erff(x * 0.70710678118654752f));
}

__device__ __forceinline__ unsigned f2tf32(float x) {
    unsigned y;
    asm("cvt.rna.tf32.f32 %0, %1;" : "=r"(y) : "f"(x));
    return y;
}

__device__ __forceinline__ void cp_async16(void* smem_dst, const void* gmem_src) {
    unsigned s = (unsigned)__cvta_generic_to_shared(smem_dst);
    asm volatile("cp.async.cg.shared.global [%0], [%1], 16;\n" :: "r"(s), "l"(gmem_src));
}
#define CP_COMMIT() asm volatile("cp.async.commit_group;\n" ::: "memory")
#define CP_WAIT1()  asm volatile("cp.async.wait_group 1;\n" ::: "memory")
#define CP_WAIT0()  asm volatile("cp.async.wait_group 0;\n" ::: "memory")

#define MMA_TF32(c0,c1,c2,c3, a0,a1,a2,a3, b0,b1)                          \
    asm volatile(                                                          \
        "mma.sync.aligned.m16n8k8.row.col.f32.tf32.tf32.f32 "              \
        "{%0,%1,%2,%3}, {%4,%5,%6,%7}, {%8,%9}, {%0,%1,%2,%3};\n"          \
        : "+f"(c0), "+f"(c1), "+f"(c2), "+f"(c3)                            \
        : "r"(a0), "r"(a1), "r"(a2), "r"(a3), "r"(b0), "r"(b1))

// ---------------- GEMM tile loader (cp.async, raw float) -------------------
template<int TM>
__device__ __forceinline__ void load_tile_gemm(
    const float* __restrict__ A, const float* __restrict__ W,
    float (*As)[20], float (*Bs)[20],
    int bm, int bn, int K, int k0, int tid) {
    #pragma unroll
    for (int i = 0; i < TM / 64; i++) {
        int idx = tid + i * 256;
        int r = idx >> 2, qd = idx & 3;
        const float* src = A + (size_t)(bm + r) * K + k0 + qd * 4;
        float* dst = &As[r][qd * 4];
        if (k0 + qd * 4 + 4 <= K) {
            cp_async16(dst, src);
        } else {
            float4 v = make_float4(0.f, 0.f, 0.f, 0.f);
            if (k0 + qd * 4 + 0 < K) v.x = src[0];
            if (k0 + qd * 4 + 1 < K) v.y = src[1];
            if (k0 + qd * 4 + 2 < K) v.z = src[2];
            if (k0 + qd * 4 + 3 < K) v.w = src[3];
            *(float4*)dst = v;
        }
    }
    #pragma unroll
    for (int i = 0; i < 2; i++) {
        int idx = tid + i * 256;
        int r = idx >> 2, qd = idx & 3;
        const float* src = W + (size_t)(bn + r) * K + k0 + qd * 4;
        float* dst = &Bs[r][qd * 4];
        if (k0 + qd * 4 + 4 <= K) {
            cp_async16(dst, src);
        } else {
            float4 v = make_float4(0.f, 0.f, 0.f, 0.f);
            if (k0 + qd * 4 + 0 < K) v.x = src[0];
            if (k0 + qd * 4 + 1 < K) v.y = src[1];
            if (k0 + qd * 4 + 2 < K) v.z = src[2];
            if (k0 + qd * 4 + 3 < K) v.w = src[3];
            *(float4*)dst = v;
        }
    }
    CP_COMMIT();
}

// ---------------- tf32 GEMM: C = act(A @ W^T + bias [+ C]) -----------------
// Block tile TM x 128, 8 warps (2 x 4), warp tile (TM/2) x 32, BK=16,
// 2-stage cp.async pipeline, convert-to-tf32 at fragment read.
template<int TM, int ACT, bool ACCUM>
__global__ __launch_bounds__(256, TM == 64 ? 3 : 2)
void gemm_tc_kernel(const float* __restrict__ A, const float* __restrict__ W,
                    const float* __restrict__ bias, float* __restrict__ C,
                    int K, int N) {
    constexpr int MT = TM / 32;
    __shared__ float As[2][TM][20];
    __shared__ float Bs[2][128][20];
    const int bm = blockIdx.y * TM, bn = blockIdx.x * 128;
    const int tid  = threadIdx.x;
    const int lane = tid & 31;
    const int wid  = tid >> 5;
    const int wm   = wid >> 2;
    const int wn   = wid & 3;
    const int g    = lane >> 2;
    const int tig  = lane & 3;

    float acc[MT][4][4] = {};

    load_tile_gemm<TM>(A, W, As[0], Bs[0], bm, bn, K, 0, tid);

    const int KT = (K + 15) >> 4;
    for (int it = 0; it < KT; it++) {
        if (it + 1 < KT) {
            load_tile_gemm<TM>(A, W, As[(it + 1) & 1], Bs[(it + 1) & 1],
                               bm, bn, K, (it + 1) * 16, tid);
            CP_WAIT1();
        } else {
            CP_WAIT0();
        }
        __syncthreads();

        const float (*Ac)[20] = As[it & 1];
        const float (*Bc)[20] = Bs[it & 1];
        #pragma unroll
        for (int ks = 0; ks < 2; ks++) {
            const int kc = ks * 8 + tig;
            unsigned a[MT][4], b[4][2];
            #pragma unroll
            for (int mt = 0; mt < MT; mt++) {
                const int r = wm * (TM / 2) + mt * 16 + g;
                a[mt][0] = f2tf32(Ac[r    ][kc]);
                a[mt][1] = f2tf32(Ac[r + 8][kc]);
                a[mt][2] = f2tf32(Ac[r    ][kc + 4]);
                a[mt][3] = f2tf32(Ac[r + 8][kc + 4]);
            }
            #pragma unroll
            for (int nt = 0; nt < 4; nt++) {
                const int r = wn * 32 + nt * 8 + g;
                b[nt][0] = f2tf32(Bc[r][kc]);
                b[nt][1] = f2tf32(Bc[r][kc + 4]);
            }
            #pragma unroll
            for (int mt = 0; mt < MT; mt++)
                #pragma unroll
                for (int nt = 0; nt < 4; nt++)
                    MMA_TF32(acc[mt][nt][0], acc[mt][nt][1],
                             acc[mt][nt][2], acc[mt][nt][3],
                             a[mt][0], a[mt][1], a[mt][2], a[mt][3],
                             b[nt][0], b[nt][1]);
        }
        __syncthreads();
    }

    #pragma unroll
    for (int mt = 0; mt < MT; mt++) {
        const int row = bm + wm * (TM / 2) + mt * 16 + g;
        #pragma unroll
        for (int nt = 0; nt < 4; nt++) {
            const int col = bn + wn * 32 + nt * 8 + 2 * tig;
            float b0 = 0.f, b1 = 0.f;
            if (bias) { b0 = bias[col]; b1 = bias[col + 1]; }
            #pragma unroll
            for (int half = 0; half < 2; half++) {
                const int r = row + half * 8;
                size_t idx = (size_t)r * N + col;
                float c0 = acc[mt][nt][half * 2 + 0] + b0;
                float c1 = acc[mt][nt][half * 2 + 1] + b1;
                if (ACCUM) { c0 += C[idx]; c1 += C[idx + 1]; }
                if (ACT == 1) { c0 = gelu_f(c0); c1 = gelu_f(c1); }
                C[idx]     = c0;
                C[idx + 1] = c1;
            }
        }
    }
}

// ---------------- CSR build -------------------------------------------------
__global__ void count_deg_kernel(const int* __restrict__ row, int* __restrict__ cnt) {
    int e = blockIdx.x * 256 + threadIdx.x;
    if (e < NEDGE) atomicAdd(&cnt[row[e]], 1);
}

__global__ void scan_kernel(const int* __restrict__ cnt, int* __restrict__ off,
                            int* __restrict__ cur) {
    __shared__ int part[256];
    const int t = threadIdx.x;
    int loc[32];
    int s = 0;
    #pragma unroll
    for (int i = 0; i < 32; i++) { loc[i] = s; s += cnt[t * 32 + i]; }
    part[t] = s;
    __syncthreads();
    for (int ofs = 1; ofs < 256; ofs <<= 1) {
        int mine = part[t];
        int add = (t >= ofs) ? part[t - ofs] : 0;
        __syncthreads();
        part[t] = mine + add;
        __syncthreads();
    }
    int excl = (t > 0) ? part[t - 1] : 0;
    #pragma unroll
    for (int i = 0; i < 32; i++) {
        int v = excl + loc[i];
        off[t * 32 + i] = v;
        cur[t * 32 + i] = v;
    }
    if (t == 255) off[BNODES] = part[255];
}

__global__ void fill_csr_kernel(const int* __restrict__ row, int* __restrict__ cur,
                                int* __restrict__ eidx) {
    int e = blockIdx.x * 256 + threadIdx.x;
    if (e < NEDGE) {
        int p = atomicAdd(&cur[row[e]], 1);
        eidx[p] = e;
    }
}

// ---------------- GCN gather ------------------------------------------------
__global__ void gcn_gather_kernel(const float* __restrict__ t1,
                                  const int* __restrict__ off,
                                  const int* __restrict__ eidx,
                                  const int* __restrict__ ecol,
                                  const float* __restrict__ eval,
                                  float* __restrict__ agg) {
    const int node = blockIdx.x;
    const int f = threadIdx.x;
    __shared__ int   scol[64];
    __shared__ float sval[64];
    const int s = off[node], e_end = off[node + 1];
    float acc = 0.f;
    for (int base = s; base < e_end; base += 64) {
        int n = min(64, e_end - base);
        if (f < n) {
            int e = eidx[base + f];
            scol[f] = ecol[e];
            sval[f] = eval[e];
        }
        __syncthreads();
        for (int j = 0; j < n; j++)
            acc += sval[j] * t1[(size_t)scol[j] * HDIM + f];
        __syncthreads();
    }
    agg[(size_t)node * HDIM + f] = acc;
}

// ---------------- BatchNorm -------------------------------------------------
template<int ACT>
__global__ void bnpre_kernel(float* __restrict__ h, const float* __restrict__ add,
                             float* __restrict__ psum, float* __restrict__ psq) {
    const int f = threadIdx.x;
    const int blk = blockIdx.x;
    float s = 0.f, sq = 0.f;
    size_t base = (size_t)blk * 64 * HDIM + f;
    #pragma unroll 4
    for (int r = 0; r < 64; r++) {
        size_t idx = base + (size_t)r * HDIM;
        float a = add[idx];
        if (ACT == 1) a = gelu_f(a);
        float v = h[idx] + a;
        h[idx] = v;
        s += v;
        sq += v * v;
    }
    psum[blk * HDIM + f] = s;
    psq [blk * HDIM + f] = sq;
}

// fused: each block recomputes mean/istd from partials (deterministic order),
// then normalizes its 128-row slab. grid = 64 blocks x 256 threads.
__global__ void bnapply_kernel(float* __restrict__ h,
                               const float* __restrict__ psum,
                               const float* __restrict__ psq,
                               const float* __restrict__ g,
                               const float* __restrict__ b) {
    const int f = threadIdx.x;
    float s = 0.f, sq = 0.f;
    #pragma unroll 8
    for (int p = 0; p < 128; p++) { s += psum[p * HDIM + f]; sq += psq[p * HDIM + f]; }
    const float mu  = s * (1.0f / BNODES);
    const float is_ = rsqrtf(sq * (1.0f / BNODES) - mu * mu + 1e-5f);
    const float gg = g[f], bb = b[f];
    size_t base = (size_t)blockIdx.x * 128 * HDIM + f;
    #pragma unroll 4
    for (int r = 0; r < 128; r++) {
        size_t i = base + (size_t)r * HDIM;
        h[i] = (h[i] - mu) * is_ * gg + bb;
    }
}

// ---------------- tf32 flash attention, cp.async double-buffered -----------
// grid (16 q-tiles, 8 heads, 8 graphs), 128 threads (4 warps).
#define ATTN_SMEM ((4 * 64 * 36 + 64 * 68) * 4)

__global__ __launch_bounds__(128)
void attn_tc_kernel(const float* __restrict__ qkv, float* __restrict__ out) {
    extern __shared__ float dsm[];
    float (*Kf)[64][36]  = (float(*)[64][36])dsm;                 // [2]
    float (*Vf)[64][36]  = (float(*)[64][36])(dsm + 2 * 64 * 36); // [2]
    unsigned (*Ss)[68]   = (unsigned(*)[68])(dsm + 4 * 64 * 36);
    float* Ssf = (float*)&Ss[0][0];

    const int qt = blockIdx.x, nh = blockIdx.y, b = blockIdx.z;
    const int tid  = threadIdx.x;
    const int lane = tid & 31;
    const int w    = tid >> 5;
    const int g    = lane >> 2;
    const int tig  = lane & 3;
    const float scale = 0.17677669529663687f;

    const size_t rowb = (size_t)(b * 1024) * 768 + nh * 32;

    // stage Q into Ssf, extract per-warp tf32 fragments
    {
        size_t qoff = rowb + (size_t)(qt * 64) * 768;
        #pragma unroll
        for (int i = 0; i < 4; i++) {
            int idx = tid + i * 128;
            int r = idx >> 3, c4 = (idx & 7) * 4;
            float4 v = *(const float4*)(qkv + qoff + (size_t)r * 768 + c4);
            Ssf[r * 68 + c4 + 0] = v.x; Ssf[r * 68 + c4 + 1] = v.y;
            Ssf[r * 68 + c4 + 2] = v.z; Ssf[r * 68 + c4 + 3] = v.w;
        }
    }
    __syncthreads();

    unsigned q[4][4];
    {
        const int r0 = w * 16 + g;
        #pragma unroll
        for (int kt4 = 0; kt4 < 4; kt4++) {
            q[kt4][0] = f2tf32(Ssf[(r0    ) * 68 + kt4 * 8 + tig    ]);
            q[kt4][1] = f2tf32(Ssf[(r0 + 8) * 68 + kt4 * 8 + tig    ]);
            q[kt4][2] = f2tf32(Ssf[(r0    ) * 68 + kt4 * 8 + tig + 4]);
            q[kt4][3] = f2tf32(Ssf[(r0 + 8) * 68 + kt4 * 8 + tig + 4]);
        }
    }
    __syncthreads();

    // prefetch KV tile 0
    {
        size_t koff = rowb;
        #pragma unroll
        for (int i = 0; i < 4; i++) {
            int idx = tid + i * 128;
            int r = idx >> 3, c4 = (idx & 7) * 4;
            cp_async16(&Kf[0][r][c4], qkv + koff + (size_t)r * 768 + 256 + c4);
            cp_async16(&Vf[0][r][c4], qkv + koff + (size_t)r * 768 + 512 + c4);
        }
        CP_COMMIT();
    }

    float m0 = -1e30f, m1 = -1e30f, l0 = 0.f, l1 = 0.f;
    float o[4][4] = {};
    const int r0 = w * 16 + g;

    for (int kt = 0; kt < 16; kt++) {
        if (kt + 1 < 16) {
            size_t koff = rowb + (size_t)((kt + 1) * 64) * 768;
            int st = (kt + 1) & 1;
            #pragma unroll
            for (int i = 0; i < 4; i++) {
                int idx = tid + i * 128;
                int r = idx >> 3, c4 = (idx & 7) * 4;
                cp_async16(&Kf[st][r][c4], qkv + koff + (size_t)r * 768 + 256 + c4);
                cp_async16(&Vf[st][r][c4], qkv + koff + (size_t)r * 768 + 512 + c4);
            }
            CP_COMMIT();
            CP_WAIT1();
        } else {
            CP_WAIT0();
        }
        __syncthreads();

        const float (*Kc)[36] = Kf[kt & 1];
        const float (*Vc)[36] = Vf[kt & 1];

        // S = Q @ K^T
        float s[8][4] = {};
        #pragma unroll
        for (int kt4 = 0; kt4 < 4; kt4++) {
            #pragma unroll
            for (int nt = 0; nt < 8; nt++) {
                unsigned b0 = f2tf32(Kc[nt * 8 + g][kt4 * 8 + tig]);
                unsigned b1 = f2tf32(Kc[nt * 8 + g][kt4 * 8 + tig + 4]);
                MMA_TF32(s[nt][0], s[nt][1], s[nt][2], s[nt][3],
                         q[kt4][0], q[kt4][1], q[kt4][2], q[kt4][3], b0, b1);
            }
        }

        // online softmax
        float rmax0 = -1e30f, rmax1 = -1e30f;
        #pragma unroll
        for (int nt = 0; nt < 8; nt++) {
            s[nt][0] *= scale; s[nt][1] *= scale;
            s[nt][2] *= scale; s[nt][3] *= scale;
            rmax0 = fmaxf(rmax0, fmaxf(s[nt][0], s[nt][1]));
            rmax1 = fmaxf(rmax1, fmaxf(s[nt][2], s[nt][3]));
        }
        rmax0 = fmaxf(rmax0, __shfl_xor_sync(0xffffffffu, rmax0, 1));
        rmax0 = fmaxf(rmax0, __shfl_xor_sync(0xffffffffu, rmax0, 2));
        rmax1 = fmaxf(rmax1, __shfl_xor_sync(0xffffffffu, rmax1, 1));
        rmax1 = fmaxf(rmax1, __shfl_xor_sync(0xffffffffu, rmax1, 2));

        float mn0 = fmaxf(m0, rmax0), mn1 = fmaxf(m1, rmax1);
        float cor0 = __expf(m0 - mn0), cor1 = __expf(m1 - mn1);
        m0 = mn0; m1 = mn1;

        float ps0 = 0.f, ps1 = 0.f;
        #pragma unroll
        for (int nt = 0; nt < 8; nt++) {
            float p0 = __expf(s[nt][0] - mn0);
            float p1 = __expf(s[nt][1] - mn0);
            float p2 = __expf(s[nt][2] - mn1);
            float p3 = __expf(s[nt][3] - mn1);
            ps0 += p0 + p1; ps1 += p2 + p3;
            int c = nt * 8 + 2 * tig;
            Ss[r0    ][c] = f2tf32(p0); Ss[r0    ][c + 1] = f2tf32(p1);
            Ss[r0 + 8][c] = f2tf32(p2); Ss[r0 + 8][c + 1] = f2tf32(p3);
        }
        ps0 += __shfl_xor_sync(0xffffffffu, ps0, 1);
        ps0 += __shfl_xor_sync(0xffffffffu, ps0, 2);
        ps1 += __shfl_xor_sync(0xffffffffu, ps1, 1);
        ps1 += __shfl_xor_sync(0xffffffffu, ps1, 2);
        l0 = l0 * cor0 + ps0;
        l1 = l1 * cor1 + ps1;
        #pragma unroll
        for (int nt = 0; nt < 4; nt++) {
            o[nt][0] *= cor0; o[nt][1] *= cor0;
            o[nt][2] *= cor1; o[nt][3] *= cor1;
        }
        __syncwarp();

        // O += P @ V
        #pragma unroll
        for (int ks = 0; ks < 8; ks++) {
            unsigned a0 = Ss[r0    ][ks * 8 + tig];
            unsigned a1 = Ss[r0 + 8][ks * 8 + tig];
            unsigned a2 = Ss[r0    ][ks * 8 + tig + 4];
            unsigned a3 = Ss[r0 + 8][ks * 8 + tig + 4];
            #pragma unroll
            for (int nt = 0; nt < 4; nt++) {
                unsigned b0 = f2tf32(Vc[ks * 8 + tig    ][nt * 8 + g]);
                unsigned b1 = f2tf32(Vc[ks * 8 + tig + 4][nt * 8 + g]);
                MMA_TF32(o[nt][0], o[nt][1], o[nt][2], o[nt][3],
                         a0, a1, a2, a3, b0, b1);
            }
        }
        __syncthreads();
    }

    const float inv0 = 1.0f / l0, inv1 = 1.0f / l1;
    const int row0 = b * 1024 + qt * 64 + w * 16 + g;
    #pragma unroll
    for (int nt = 0; nt < 4; nt++) {
        const int col = nh * 32 + nt * 8 + 2 * tig;
        size_t i0 = (size_t)row0 * HDIM + col;
        size_t i1 = (size_t)(row0 + 8) * HDIM + col;
        out[i0]     = o[nt][0] * inv0;
        out[i0 + 1] = o[nt][1] * inv0;
        out[i1]     = o[nt][2] * inv1;
        out[i1 + 1] = o[nt][3] * inv1;
    }
}

// ---------------- head final ------------------------------------------------
__global__ void head_final_kernel(const float* __restrict__ t, const float* __restrict__ w,
                                  const float* __restrict__ b, float* __restrict__ out) {
    int row = blockIdx.x * 8 + (threadIdx.x >> 5);
    int lane = threadIdx.x & 31;
    float acc = 0.f;
    #pragma unroll
    for (int i = lane; i < 128; i += 32)
        acc += t[(size_t)row * 128 + i] * w[i];
    #pragma unroll
    for (int ofs = 16; ofs; ofs >>= 1)
        acc += __shfl_xor_sync(0xffffffffu, acc, ofs);
    if (lane == 0)
        out[row] = 1.0f / (1.0f + expf(-(acc + b[0])));
}

// ---------------- host orchestration ----------------------------------------
static void bn_block(float* h, const float* add, int act,
                     const float* g, const float* b,
                     float* psum, float* psq) {
    if (act) bnpre_kernel<1><<<128, 256>>>(h, add, psum, psq);
    else     bnpre_kernel<0><<<128, 256>>>(h, add, psum, psq);
    bnapply_kernel<<<64, 256>>>(h, psum, psq, g, b);
}

extern "C" void kernel_launch(void* const* d_in, const int* in_sizes, int n_in,
                              void* d_out, int out_size) {
    const float* x        = (const float*)d_in[0];
    const int*   erow     = (const int*)  d_in[1];
    const int*   ecol     = (const int*)  d_in[2];
    const float* eval     = (const float*)d_in[3];
    const float* pe       = (const float*)d_in[4];
    const float* W_in     = (const float*)d_in[5];
    const float* b_in     = (const float*)d_in[6];
    const float* W_pe     = (const float*)d_in[7];
    const float* b_pe     = (const float*)d_in[8];
    const float* gcn_W    = (const float*)d_in[9];
    const float* ain_W    = (const float*)d_in[10];
    const float* ain_b    = (const float*)d_in[11];
    const float* aout_W   = (const float*)d_in[12];
    const float* aout_b   = (const float*)d_in[13];
    const float* bn_g     = (const float*)d_in[14];
    const float* bn_b     = (const float*)d_in[15];
    const float* ffn_W1   = (const float*)d_in[16];
    const float* ffn_b1   = (const float*)d_in[17];
    const float* ffn_W2   = (const float*)d_in[18];
    const float* ffn_b2   = (const float*)d_in[19];
    const float* head_W1  = (const float*)d_in[20];
    const float* head_b1  = (const float*)d_in[21];
    const float* head_W2  = (const float*)d_in[22];
    const float* head_b2  = (const float*)d_in[23];

    float *h, *t1, *t2, *t3, *psum, *psq;
    int *cnt, *off, *cur, *eidx;
    cudaGetSymbolAddress((void**)&h,    g_h);
    cudaGetSymbolAddress((void**)&t1,   g_t1);
    cudaGetSymbolAddress((void**)&t2,   g_t2);
    cudaGetSymbolAddress((void**)&t3,   g_t3);
    cudaGetSymbolAddress((void**)&psum, g_psum);
    cudaGetSymbolAddress((void**)&psq,  g_psq);
    cudaGetSymbolAddress((void**)&cnt,  g_cnt);
    cudaGetSymbolAddress((void**)&off,  g_off);
    cudaGetSymbolAddress((void**)&cur,  g_cur);
    cudaGetSymbolAddress((void**)&eidx, g_eidx);

    static int smem_set = 0;
    if (!smem_set) {
        cudaFuncSetAttribute(attn_tc_kernel,
                             cudaFuncAttributeMaxDynamicSharedMemorySize, ATTN_SMEM);
        smem_set = 1;
    }

    cudaMemsetAsync(cnt, 0, BNODES * sizeof(int));
    count_deg_kernel<<<NEDGE / 256, 256>>>(erow, cnt);
    scan_kernel<<<1, 256>>>(cnt, off, cur);
    fill_csr_kernel<<<NEDGE / 256, 256>>>(erow, cur, eidx);

    const dim3 g256 (2, BNODES / 64);    // TM=64,  N=256
    const dim3 g768 (6, BNODES / 128);   // TM=128, N=768
    const dim3 g1024(8, BNODES / 128);   // TM=128, N=1024
    const dim3 g128 (1, BNODES / 64);    // TM=64,  N=128

    gemm_tc_kernel<64, 0, false><<<g256, 256>>>(x,  W_in, b_in, h, 128, HDIM);
    gemm_tc_kernel<64, 0, true ><<<g256, 256>>>(pe, W_pe, b_pe, h, 8,   HDIM);

    for (int l = 0; l < NLAYER; l++) {
        // ---- local GCN ----
        gemm_tc_kernel<64, 0, false><<<g256, 256>>>(h, gcn_W + (size_t)l * HDIM * HDIM,
                                                    nullptr, t1, HDIM, HDIM);
        gcn_gather_kernel<<<BNODES, 256>>>(t1, off, eidx, ecol, eval, t2);
        bn_block(h, t2, 1, bn_g + l * 3 * HDIM, bn_b + l * 3 * HDIM, psum, psq);
        // ---- global attention ----
        gemm_tc_kernel<128, 0, false><<<g768, 256>>>(h, ain_W + (size_t)l * 768 * HDIM,
                                                     ain_b + l * 768, t1, HDIM, 768);
        attn_tc_kernel<<<dim3(16, 8, 8), 128, ATTN_SMEM>>>(t1, t2);
        gemm_tc_kernel<64, 0, false><<<g256, 256>>>(t2, aout_W + (size_t)l * HDIM * HDIM,
                                                    aout_b + l * HDIM, t3, HDIM, HDIM);
        bn_block(h, t3, 0, bn_g + l * 3 * HDIM + HDIM, bn_b + l * 3 * HDIM + HDIM,
                 psum, psq);
        // ---- FFN ----
        gemm_tc_kernel<128, 1, false><<<g1024, 256>>>(h, ffn_W1 + (size_t)l * 1024 * HDIM,
                                                      ffn_b1 + l * 1024, t1, HDIM, 1024);
        gemm_tc_kernel<64, 0, false><<<g256, 256>>>(t1, ffn_W2 + (size_t)l * HDIM * 1024,
                                                    ffn_b2 + l * HDIM, t3, 1024, HDIM);
        bn_block(h, t3, 0, bn_g + l * 3 * HDIM + 2 * HDIM, bn_b + l * 3 * HDIM + 2 * HDIM,
                 psum, psq);
    }

    gemm_tc_kernel<64, 1, false><<<g128, 256>>>(h, head_W1, head_b1, t1, HDIM, 128);
    head_final_kernel<<<BNODES / 8, 256>>>(t1, head_W2, head_b2, (float*)d_out);
}

// round 5
// speedup vs baseline: 2.3737x; 1.0666x over previous
#include <cuda_runtime.h>
#include <cuda_bf16.h>
#include <math.h>

#define BNODES 8192
#define HDIM   256
#define NEDGE  131072
#define NLAYER 4

__device__ float g_h [BNODES * HDIM];
__device__ float g_t1[BNODES * 1024];
__device__ float g_t2[BNODES * HDIM];
__device__ float g_t3[BNODES * HDIM];
__device__ int   g_cnt[BNODES];
__device__ int   g_off[BNODES + 1];
__device__ int   g_cur[BNODES];
__device__ int   g_eidx[NEDGE];
__device__ float g_psum[256 * HDIM];
__device__ float g_psq [256 * HDIM];

__device__ __forceinline__ float gelu_f(float x) {
    return 0.5f * x * (1.0f + erff(x * 0.70710678118654752f));
}

__device__ __forceinline__ void cp_async16(void* smem_dst, const void* gmem_src) {
    unsigned s = (unsigned)__cvta_generic_to_shared(smem_dst);
    asm volatile("cp.async.cg.shared.global [%0], [%1], 16;\n" :: "r"(s), "l"(gmem_src));
}
#define CP_COMMIT() asm volatile("cp.async.commit_group;\n" ::: "memory")
#define CP_WAIT1()  asm volatile("cp.async.wait_group 1;\n" ::: "memory")
#define CP_WAIT0()  asm volatile("cp.async.wait_group 0;\n" ::: "memory")

// raw fp32 bits fed as tf32 operands (HW truncates the low mantissa bits)
#define MMA_TF32(c0,c1,c2,c3, a0,a1,a2,a3, b0,b1)                          \
    asm volatile(                                                          \
        "mma.sync.aligned.m16n8k8.row.col.f32.tf32.tf32.f32 "              \
        "{%0,%1,%2,%3}, {%4,%5,%6,%7}, {%8,%9}, {%0,%1,%2,%3};\n"          \
        : "+f"(c0), "+f"(c1), "+f"(c2), "+f"(c3)                            \
        : "r"(a0), "r"(a1), "r"(a2), "r"(a3), "r"(b0), "r"(b1))

// ---------------- tf32 GEMM: C = act(A @ W^T + bias [+ C]) -----------------
// Block tile TM x 128, 8 warps (2 x 4), warp tile (TM/2) x 32, BK=32,
// 2-stage cp.async pipeline, dynamic smem.
template<int TM>
__device__ __forceinline__ void load_tile_gemm(
    const float* __restrict__ A, const float* __restrict__ W,
    float (*As)[36], float (*Bs)[36],
    int bm, int bn, int K, int k0, int tid) {
    #pragma unroll
    for (int i = 0; i < TM / 32; i++) {
        int idx = tid + i * 256;
        int r = idx >> 3, qd = idx & 7;
        const float* src = A + (size_t)(bm + r) * K + k0 + qd * 4;
        float* dst = &As[r][qd * 4];
        if (k0 + qd * 4 + 4 <= K) {
            cp_async16(dst, src);
        } else {
            float4 v = make_float4(0.f, 0.f, 0.f, 0.f);
            if (k0 + qd * 4 + 0 < K) v.x = src[0];
            if (k0 + qd * 4 + 1 < K) v.y = src[1];
            if (k0 + qd * 4 + 2 < K) v.z = src[2];
            if (k0 + qd * 4 + 3 < K) v.w = src[3];
            *(float4*)dst = v;
        }
    }
    #pragma unroll
    for (int i = 0; i < 4; i++) {
        int idx = tid + i * 256;
        int r = idx >> 3, qd = idx & 7;
        const float* src = W + (size_t)(bn + r) * K + k0 + qd * 4;
        float* dst = &Bs[r][qd * 4];
        if (k0 + qd * 4 + 4 <= K) {
            cp_async16(dst, src);
        } else {
            float4 v = make_float4(0.f, 0.f, 0.f, 0.f);
            if (k0 + qd * 4 + 0 < K) v.x = src[0];
            if (k0 + qd * 4 + 1 < K) v.y = src[1];
            if (k0 + qd * 4 + 2 < K) v.z = src[2];
            if (k0 + qd * 4 + 3 < K) v.w = src[3];
            *(float4*)dst = v;
        }
    }
    CP_COMMIT();
}

template<int TM, int ACT, bool ACCUM>
__global__ __launch_bounds__(256, 2)
void gemm_tc_kernel(const float* __restrict__ A, const float* __restrict__ W,
                    const float* __restrict__ bias, float* __restrict__ C,
                    int K, int N) {
    constexpr int MT = TM / 32;
    extern __shared__ float sm[];
    float (*As)[36] = (float(*)[36])sm;                       // [2*TM][36]
    float (*Bs)[36] = (float(*)[36])(sm + 2 * TM * 36);       // [2*128][36]

    const int bm = blockIdx.y * TM, bn = blockIdx.x * 128;
    const int tid  = threadIdx.x;
    const int lane = tid & 31;
    const int wid  = tid >> 5;
    const int wm   = wid >> 2;
    const int wn   = wid & 3;
    const int g    = lane >> 2;
    const int tig  = lane & 3;

    float acc[MT][4][4] = {};

    load_tile_gemm<TM>(A, W, As, Bs, bm, bn, K, 0, tid);

    const int KT = (K + 31) >> 5;
    for (int it = 0; it < KT; it++) {
        const int st  = it & 1;
        if (it + 1 < KT) {
            load_tile_gemm<TM>(A, W, As + (1 - st) * TM, Bs + (1 - st) * 128,
                               bm, bn, K, (it + 1) * 32, tid);
            CP_WAIT1();
        } else {
            CP_WAIT0();
        }
        __syncthreads();

        const float (*Ac)[36] = As + st * TM;
        const float (*Bc)[36] = Bs + st * 128;
        #pragma unroll
        for (int ks = 0; ks < 4; ks++) {
            const int kc = ks * 8 + tig;
            unsigned a[MT][4], b[4][2];
            #pragma unroll
            for (int mt = 0; mt < MT; mt++) {
                const int r = wm * (TM / 2) + mt * 16 + g;
                a[mt][0] = __float_as_uint(Ac[r    ][kc]);
                a[mt][1] = __float_as_uint(Ac[r + 8][kc]);
                a[mt][2] = __float_as_uint(Ac[r    ][kc + 4]);
                a[mt][3] = __float_as_uint(Ac[r + 8][kc + 4]);
            }
            #pragma unroll
            for (int nt = 0; nt < 4; nt++) {
                const int r = wn * 32 + nt * 8 + g;
                b[nt][0] = __float_as_uint(Bc[r][kc]);
                b[nt][1] = __float_as_uint(Bc[r][kc + 4]);
            }
            #pragma unroll
            for (int mt = 0; mt < MT; mt++)
                #pragma unroll
                for (int nt = 0; nt < 4; nt++)
                    MMA_TF32(acc[mt][nt][0], acc[mt][nt][1],
                             acc[mt][nt][2], acc[mt][nt][3],
                             a[mt][0], a[mt][1], a[mt][2], a[mt][3],
                             b[nt][0], b[nt][1]);
        }
        __syncthreads();
    }

    #pragma unroll
    for (int mt = 0; mt < MT; mt++) {
        const int row = bm + wm * (TM / 2) + mt * 16 + g;
        #pragma unroll
        for (int nt = 0; nt < 4; nt++) {
            const int col = bn + wn * 32 + nt * 8 + 2 * tig;
            float b0 = 0.f, b1 = 0.f;
            if (bias) { b0 = bias[col]; b1 = bias[col + 1]; }
            #pragma unroll
            for (int half = 0; half < 2; half++) {
                const int r = row + half * 8;
                size_t idx = (size_t)r * N + col;
                float c0 = acc[mt][nt][half * 2 + 0] + b0;
                float c1 = acc[mt][nt][half * 2 + 1] + b1;
                if (ACCUM) { c0 += C[idx]; c1 += C[idx + 1]; }
                if (ACT == 1) { c0 = gelu_f(c0); c1 = gelu_f(c1); }
                C[idx]     = c0;
                C[idx + 1] = c1;
            }
        }
    }
}

#define GEMM_SMEM_64  ((2 * 64 * 36 + 2 * 128 * 36) * 4)
#define GEMM_SMEM_128 ((2 * 128 * 36 + 2 * 128 * 36) * 4)

// ---------------- CSR build -------------------------------------------------
__global__ void count_deg_kernel(const int* __restrict__ row, int* __restrict__ cnt) {
    int e = blockIdx.x * 256 + threadIdx.x;
    if (e < NEDGE) atomicAdd(&cnt[row[e]], 1);
}

__global__ void scan_kernel(const int* __restrict__ cnt, int* __restrict__ off,
                            int* __restrict__ cur) {
    __shared__ int part[256];
    const int t = threadIdx.x;
    int loc[32];
    int s = 0;
    #pragma unroll
    for (int i = 0; i < 32; i++) { loc[i] = s; s += cnt[t * 32 + i]; }
    part[t] = s;
    __syncthreads();
    for (int ofs = 1; ofs < 256; ofs <<= 1) {
        int mine = part[t];
        int add = (t >= ofs) ? part[t - ofs] : 0;
        __syncthreads();
        part[t] = mine + add;
        __syncthreads();
    }
    int excl = (t > 0) ? part[t - 1] : 0;
    #pragma unroll
    for (int i = 0; i < 32; i++) {
        int v = excl + loc[i];
        off[t * 32 + i] = v;
        cur[t * 32 + i] = v;
    }
    if (t == 255) off[BNODES] = part[255];
}

__global__ void fill_csr_kernel(const int* __restrict__ row, int* __restrict__ cur,
                                int* __restrict__ eidx) {
    int e = blockIdx.x * 256 + threadIdx.x;
    if (e < NEDGE) {
        int p = atomicAdd(&cur[row[e]], 1);
        eidx[p] = e;
    }
}

// ---------------- GCN gather ------------------------------------------------
__global__ void gcn_gather_kernel(const float* __restrict__ t1,
                                  const int* __restrict__ off,
                                  const int* __restrict__ eidx,
                                  const int* __restrict__ ecol,
                                  const float* __restrict__ eval,
                                  float* __restrict__ agg) {
    const int node = blockIdx.x;
    const int f = threadIdx.x;
    __shared__ int   scol[64];
    __shared__ float sval[64];
    const int s = off[node], e_end = off[node + 1];
    float acc = 0.f;
    for (int base = s; base < e_end; base += 64) {
        int n = min(64, e_end - base);
        if (f < n) {
            int e = eidx[base + f];
            scol[f] = ecol[e];
            sval[f] = eval[e];
        }
        __syncthreads();
        for (int j = 0; j < n; j++)
            acc += sval[j] * t1[(size_t)scol[j] * HDIM + f];
        __syncthreads();
    }
    agg[(size_t)node * HDIM + f] = acc;
}

// ---------------- BatchNorm -------------------------------------------------
template<int ACT>
__global__ void bnpre_kernel(float* __restrict__ h, const float* __restrict__ add,
                             float* __restrict__ psum, float* __restrict__ psq) {
    const int f = threadIdx.x;
    const int blk = blockIdx.x;   // 256 blocks x 32 rows
    float s = 0.f, sq = 0.f;
    size_t base = (size_t)blk * 32 * HDIM + f;
    #pragma unroll 4
    for (int r = 0; r < 32; r++) {
        size_t idx = base + (size_t)r * HDIM;
        float a = add[idx];
        if (ACT == 1) a = gelu_f(a);
        float v = h[idx] + a;
        h[idx] = v;
        s += v;
        sq += v * v;
    }
    psum[blk * HDIM + f] = s;
    psq [blk * HDIM + f] = sq;
}

__global__ void bnapply_kernel(float* __restrict__ h,
                               const float* __restrict__ psum,
                               const float* __restrict__ psq,
                               const float* __restrict__ g,
                               const float* __restrict__ b) {
    const int f = threadIdx.x;
    float s = 0.f, sq = 0.f;
    #pragma unroll 8
    for (int p = 0; p < 256; p++) { s += psum[p * HDIM + f]; sq += psq[p * HDIM + f]; }
    const float mu  = s * (1.0f / BNODES);
    const float is_ = rsqrtf(sq * (1.0f / BNODES) - mu * mu + 1e-5f);
    const float gg = g[f], bb = b[f];
    size_t base = (size_t)blockIdx.x * 64 * HDIM + f;   // 128 blocks x 64 rows
    #pragma unroll 4
    for (int r = 0; r < 64; r++) {
        size_t i = base + (size_t)r * HDIM;
        h[i] = (h[i] - mu) * is_ * gg + bb;
    }
}

// ---------------- tf32 flash attention, Q-tile 128, 8 warps ----------------
// grid (8 q-tiles, 8 heads, 8 graphs), 256 threads.
#define ATTN_SMEM ((4 * 64 * 36) * 4 + (128 * 68) * 4)

__global__ __launch_bounds__(256)
void attn_tc_kernel(const float* __restrict__ qkv, float* __restrict__ out) {
    extern __shared__ float dsm[];
    float (*Kf)[64][36]  = (float(*)[64][36])dsm;                 // [2]
    float (*Vf)[64][36]  = (float(*)[64][36])(dsm + 2 * 64 * 36); // [2]
    unsigned (*Ss)[68]   = (unsigned(*)[68])(dsm + 4 * 64 * 36);  // [128][68]
    float* Ssf = (float*)&Ss[0][0];

    const int qt = blockIdx.x, nh = blockIdx.y, b = blockIdx.z;
    const int tid  = threadIdx.x;
    const int lane = tid & 31;
    const int w    = tid >> 5;
    const int g    = lane >> 2;
    const int tig  = lane & 3;
    const float scale = 0.17677669529663687f;

    const size_t rowb = (size_t)(b * 1024) * 768 + nh * 32;

    // stage Q (128 x 32) into Ssf
    {
        size_t qoff = rowb + (size_t)(qt * 128) * 768;
        #pragma unroll
        for (int i = 0; i < 4; i++) {
            int idx = tid + i * 256;
            int r = idx >> 3, c4 = (idx & 7) * 4;
            float4 v = *(const float4*)(qkv + qoff + (size_t)r * 768 + c4);
            Ssf[r * 68 + c4 + 0] = v.x; Ssf[r * 68 + c4 + 1] = v.y;
            Ssf[r * 68 + c4 + 2] = v.z; Ssf[r * 68 + c4 + 3] = v.w;
        }
    }
    __syncthreads();

    unsigned q[4][4];
    const int r0 = w * 16 + g;
    #pragma unroll
    for (int kt4 = 0; kt4 < 4; kt4++) {
        q[kt4][0] = __float_as_uint(Ssf[(r0    ) * 68 + kt4 * 8 + tig    ]);
        q[kt4][1] = __float_as_uint(Ssf[(r0 + 8) * 68 + kt4 * 8 + tig    ]);
        q[kt4][2] = __float_as_uint(Ssf[(r0    ) * 68 + kt4 * 8 + tig + 4]);
        q[kt4][3] = __float_as_uint(Ssf[(r0 + 8) * 68 + kt4 * 8 + tig + 4]);
    }
    __syncthreads();

    // prefetch KV tile 0
    {
        #pragma unroll
        for (int i = 0; i < 2; i++) {
            int idx = tid + i * 256;
            int r = idx >> 3, c4 = (idx & 7) * 4;
            cp_async16(&Kf[0][r][c4], qkv + rowb + (size_t)r * 768 + 256 + c4);
            cp_async16(&Vf[0][r][c4], qkv + rowb + (size_t)r * 768 + 512 + c4);
        }
        CP_COMMIT();
    }

    float m0 = -1e30f, m1 = -1e30f, l0 = 0.f, l1 = 0.f;
    float o[4][4] = {};

    for (int kt = 0; kt < 16; kt++) {
        if (kt + 1 < 16) {
            size_t koff = rowb + (size_t)((kt + 1) * 64) * 768;
            int st = (kt + 1) & 1;
            #pragma unroll
            for (int i = 0; i < 2; i++) {
                int idx = tid + i * 256;
                int r = idx >> 3, c4 = (idx & 7) * 4;
                cp_async16(&Kf[st][r][c4], qkv + koff + (size_t)r * 768 + 256 + c4);
                cp_async16(&Vf[st][r][c4], qkv + koff + (size_t)r * 768 + 512 + c4);
            }
            CP_COMMIT();
            CP_WAIT1();
        } else {
            CP_WAIT0();
        }
        __syncthreads();

        const float (*Kc)[36] = Kf[kt & 1];
        const float (*Vc)[36] = Vf[kt & 1];

        // S = Q @ K^T  (per warp 16 x 64)
        float s[8][4] = {};
        #pragma unroll
        for (int kt4 = 0; kt4 < 4; kt4++) {
            #pragma unroll
            for (int nt = 0; nt < 8; nt++) {
                unsigned b0 = __float_as_uint(Kc[nt * 8 + g][kt4 * 8 + tig]);
                unsigned b1 = __float_as_uint(Kc[nt * 8 + g][kt4 * 8 + tig + 4]);
                MMA_TF32(s[nt][0], s[nt][1], s[nt][2], s[nt][3],
                         q[kt4][0], q[kt4][1], q[kt4][2], q[kt4][3], b0, b1);
            }
        }

        // online softmax (rows r0 and r0+8)
        float rmax0 = -1e30f, rmax1 = -1e30f;
        #pragma unroll
        for (int nt = 0; nt < 8; nt++) {
            s[nt][0] *= scale; s[nt][1] *= scale;
            s[nt][2] *= scale; s[nt][3] *= scale;
            rmax0 = fmaxf(rmax0, fmaxf(s[nt][0], s[nt][1]));
            rmax1 = fmaxf(rmax1, fmaxf(s[nt][2], s[nt][3]));
        }
        rmax0 = fmaxf(rmax0, __shfl_xor_sync(0xffffffffu, rmax0, 1));
        rmax0 = fmaxf(rmax0, __shfl_xor_sync(0xffffffffu, rmax0, 2));
        rmax1 = fmaxf(rmax1, __shfl_xor_sync(0xffffffffu, rmax1, 1));
        rmax1 = fmaxf(rmax1, __shfl_xor_sync(0xffffffffu, rmax1, 2));

        float mn0 = fmaxf(m0, rmax0), mn1 = fmaxf(m1, rmax1);
        float cor0 = __expf(m0 - mn0), cor1 = __expf(m1 - mn1);
        m0 = mn0; m1 = mn1;

        float ps0 = 0.f, ps1 = 0.f;
        #pragma unroll
        for (int nt = 0; nt < 8; nt++) {
            float p0 = __expf(s[nt][0] - mn0);
            float p1 = __expf(s[nt][1] - mn0);
            float p2 = __expf(s[nt][2] - mn1);
            float p3 = __expf(s[nt][3] - mn1);
            ps0 += p0 + p1; ps1 += p2 + p3;
            int c = nt * 8 + 2 * tig;
            Ss[r0    ][c] = __float_as_uint(p0); Ss[r0    ][c + 1] = __float_as_uint(p1);
            Ss[r0 + 8][c] = __float_as_uint(p2); Ss[r0 + 8][c + 1] = __float_as_uint(p3);
        }
        ps0 += __shfl_xor_sync(0xffffffffu, ps0, 1);
        ps0 += __shfl_xor_sync(0xffffffffu, ps0, 2);
        ps1 += __shfl_xor_sync(0xffffffffu, ps1, 1);
        ps1 += __shfl_xor_sync(0xffffffffu, ps1, 2);
        l0 = l0 * cor0 + ps0;
        l1 = l1 * cor1 + ps1;
        #pragma unroll
        for (int nt = 0; nt < 4; nt++) {
            o[nt][0] *= cor0; o[nt][1] *= cor0;
            o[nt][2] *= cor1; o[nt][3] *= cor1;
        }
        __syncwarp();

        // O += P @ V  (per warp 16 x 32)
        #pragma unroll
        for (int ks = 0; ks < 8; ks++) {
            unsigned a0 = Ss[r0    ][ks * 8 + tig];
            unsigned a1 = Ss[r0 + 8][ks * 8 + tig];
            unsigned a2 = Ss[r0    ][ks * 8 + tig + 4];
            unsigned a3 = Ss[r0 + 8][ks * 8 + tig + 4];
            #pragma unroll
            for (int nt = 0; nt < 4; nt++) {
                unsigned b0 = __float_as_uint(Vc[ks * 8 + tig    ][nt * 8 + g]);
                unsigned b1 = __float_as_uint(Vc[ks * 8 + tig + 4][nt * 8 + g]);
                MMA_TF32(o[nt][0], o[nt][1], o[nt][2], o[nt][3],
                         a0, a1, a2, a3, b0, b1);
            }
        }
        __syncthreads();
    }

    const float inv0 = 1.0f / l0, inv1 = 1.0f / l1;
    const int row0 = b * 1024 + qt * 128 + w * 16 + g;
    #pragma unroll
    for (int nt = 0; nt < 4; nt++) {
        const int col = nh * 32 + nt * 8 + 2 * tig;
        size_t i0 = (size_t)row0 * HDIM + col;
        size_t i1 = (size_t)(row0 + 8) * HDIM + col;
        out[i0]     = o[nt][0] * inv0;
        out[i0 + 1] = o[nt][1] * inv0;
        out[i1]     = o[nt][2] * inv1;
        out[i1 + 1] = o[nt][3] * inv1;
    }
}

// ---------------- head final ------------------------------------------------
__global__ void head_final_kernel(const float* __restrict__ t, const float* __restrict__ w,
                                  const float* __restrict__ b, float* __restrict__ out) {
    int row = blockIdx.x * 8 + (threadIdx.x >> 5);
    int lane = threadIdx.x & 31;
    float acc = 0.f;
    #pragma unroll
    for (int i = lane; i < 128; i += 32)
        acc += t[(size_t)row * 128 + i] * w[i];
    #pragma unroll
    for (int ofs = 16; ofs; ofs >>= 1)
        acc += __shfl_xor_sync(0xffffffffu, acc, ofs);
    if (lane == 0)
        out[row] = 1.0f / (1.0f + expf(-(acc + b[0])));
}

// ---------------- host orchestration ----------------------------------------
static void bn_block(float* h, const float* add, int act,
                     const float* g, const float* b,
                     float* psum, float* psq) {
    if (act) bnpre_kernel<1><<<256, 256>>>(h, add, psum, psq);
    else     bnpre_kernel<0><<<256, 256>>>(h, add, psum, psq);
    bnapply_kernel<<<128, 256>>>(h, psum, psq, g, b);
}

extern "C" void kernel_launch(void* const* d_in, const int* in_sizes, int n_in,
                              void* d_out, int out_size) {
    const float* x        = (const float*)d_in[0];
    const int*   erow     = (const int*)  d_in[1];
    const int*   ecol     = (const int*)  d_in[2];
    const float* eval     = (const float*)d_in[3];
    const float* pe       = (const float*)d_in[4];
    const float* W_in     = (const float*)d_in[5];
    const float* b_in     = (const float*)d_in[6];
    const float* W_pe     = (const float*)d_in[7];
    const float* b_pe     = (const float*)d_in[8];
    const float* gcn_W    = (const float*)d_in[9];
    const float* ain_W    = (const float*)d_in[10];
    const float* ain_b    = (const float*)d_in[11];
    const float* aout_W   = (const float*)d_in[12];
    const float* aout_b   = (const float*)d_in[13];
    const float* bn_g     = (const float*)d_in[14];
    const float* bn_b     = (const float*)d_in[15];
    const float* ffn_W1   = (const float*)d_in[16];
    const float* ffn_b1   = (const float*)d_in[17];
    const float* ffn_W2   = (const float*)d_in[18];
    const float* ffn_b2   = (const float*)d_in[19];
    const float* head_W1  = (const float*)d_in[20];
    const float* head_b1  = (const float*)d_in[21];
    const float* head_W2  = (const float*)d_in[22];
    const float* head_b2  = (const float*)d_in[23];

    float *h, *t1, *t2, *t3, *psum, *psq;
    int *cnt, *off, *cur, *eidx;
    cudaGetSymbolAddress((void**)&h,    g_h);
    cudaGetSymbolAddress((void**)&t1,   g_t1);
    cudaGetSymbolAddress((void**)&t2,   g_t2);
    cudaGetSymbolAddress((void**)&t3,   g_t3);
    cudaGetSymbolAddress((void**)&psum, g_psum);
    cudaGetSymbolAddress((void**)&psq,  g_psq);
    cudaGetSymbolAddress((void**)&cnt,  g_cnt);
    cudaGetSymbolAddress((void**)&off,  g_off);
    cudaGetSymbolAddress((void**)&cur,  g_cur);
    cudaGetSymbolAddress((void**)&eidx, g_eidx);

    cudaFuncSetAttribute(attn_tc_kernel,
                         cudaFuncAttributeMaxDynamicSharedMemorySize, ATTN_SMEM);
    cudaFuncSetAttribute(gemm_tc_kernel<64, 0, false>,
                         cudaFuncAttributeMaxDynamicSharedMemorySize, GEMM_SMEM_64);
    cudaFuncSetAttribute(gemm_tc_kernel<64, 0, true>,
                         cudaFuncAttributeMaxDynamicSharedMemorySize, GEMM_SMEM_64);
    cudaFuncSetAttribute(gemm_tc_kernel<64, 1, false>,
                         cudaFuncAttributeMaxDynamicSharedMemorySize, GEMM_SMEM_64);
    cudaFuncSetAttribute(gemm_tc_kernel<128, 0, false>,
                         cudaFuncAttributeMaxDynamicSharedMemorySize, GEMM_SMEM_128);
    cudaFuncSetAttribute(gemm_tc_kernel<128, 1, false>,
                         cudaFuncAttributeMaxDynamicSharedMemorySize, GEMM_SMEM_128);

    cudaMemsetAsync(cnt, 0, BNODES * sizeof(int));
    count_deg_kernel<<<NEDGE / 256, 256>>>(erow, cnt);
    scan_kernel<<<1, 256>>>(cnt, off, cur);
    fill_csr_kernel<<<NEDGE / 256, 256>>>(erow, cur, eidx);

    const dim3 g256 (2, BNODES / 64);    // TM=64,  N=256
    const dim3 g768 (6, BNODES / 128);   // TM=128, N=768
    const dim3 g1024(8, BNODES / 128);   // TM=128, N=1024
    const dim3 g128 (1, BNODES / 64);    // TM=64,  N=128

    gemm_tc_kernel<64, 0, false><<<g256, 256, GEMM_SMEM_64>>>(x,  W_in, b_in, h, 128, HDIM);
    gemm_tc_kernel<64, 0, true ><<<g256, 256, GEMM_SMEM_64>>>(pe, W_pe, b_pe, h, 8,   HDIM);

    for (int l = 0; l < NLAYER; l++) {
        // ---- local GCN ----
        gemm_tc_kernel<64, 0, false><<<g256, 256, GEMM_SMEM_64>>>(
            h, gcn_W + (size_t)l * HDIM * HDIM, nullptr, t1, HDIM, HDIM);
        gcn_gather_kernel<<<BNODES, 256>>>(t1, off, eidx, ecol, eval, t2);
        bn_block(h, t2, 1, bn_g + l * 3 * HDIM, bn_b + l * 3 * HDIM, psum, psq);
        // ---- global attention ----
        gemm_tc_kernel<128, 0, false><<<g768, 256, GEMM_SMEM_128>>>(
            h, ain_W + (size_t)l * 768 * HDIM, ain_b + l * 768, t1, HDIM, 768);
        attn_tc_kernel<<<dim3(8, 8, 8), 256, ATTN_SMEM>>>(t1, t2);
        gemm_tc_kernel<64, 0, false><<<g256, 256, GEMM_SMEM_64>>>(
            t2, aout_W + (size_t)l * HDIM * HDIM, aout_b + l * HDIM, t3, HDIM, HDIM);
        bn_block(h, t3, 0, bn_g + l * 3 * HDIM + HDIM, bn_b + l * 3 * HDIM + HDIM,
                 psum, psq);
        // ---- FFN ----
        gemm_tc_kernel<128, 1, false><<<g1024, 256, GEMM_SMEM_128>>>(
            h, ffn_W1 + (size_t)l * 1024 * HDIM, ffn_b1 + l * 1024, t1, HDIM, 1024);
        gemm_tc_kernel<64, 0, false><<<g256, 256, GEMM_SMEM_64>>>(
            t1, ffn_W2 + (size_t)l * HDIM * 1024, ffn_b2 + l * HDIM, t3, 1024, HDIM);
        bn_block(h, t3, 0, bn_g + l * 3 * HDIM + 2 * HDIM, bn_b + l * 3 * HDIM + 2 * HDIM,
                 psum, psq);
    }

    gemm_tc_kernel<64, 1, false><<<g128, 256, GEMM_SMEM_64>>>(
        h, head_W1, head_b1, t1, HDIM, 128);
    head_final_kernel<<<BNODES / 8, 256>>>(t1, head_W2, head_b2, (float*)d_out);
}

// round 6
// speedup vs baseline: 2.4652x; 1.0385x over previous
#include <cuda_runtime.h>
#include <cuda_bf16.h>
#include <math.h>

#define BNODES 8192
#define HDIM   256
#define NEDGE  131072
#define NLAYER 4

__device__ float g_h [BNODES * HDIM];
__device__ float g_t1[BNODES * 1024];
__device__ float g_t2[BNODES * HDIM];
__device__ int   g_cnt[BNODES];
__device__ int   g_off[BNODES + 1];
__device__ int   g_cur[BNODES];
__device__ int   g_eidx[NEDGE];
__device__ float g_psum[256 * HDIM];
__device__ float g_psq [256 * HDIM];

__device__ __forceinline__ float gelu_f(float x) {
    return 0.5f * x * (1.0f + erff(x * 0.70710678118654752f));
}

__device__ __forceinline__ void cp_async16(void* smem_dst, const void* gmem_src) {
    unsigned s = (unsigned)__cvta_generic_to_shared(smem_dst);
    asm volatile("cp.async.cg.shared.global [%0], [%1], 16;\n" :: "r"(s), "l"(gmem_src));
}
#define CP_COMMIT() asm volatile("cp.async.commit_group;\n" ::: "memory")
#define CP_WAIT1()  asm volatile("cp.async.wait_group 1;\n" ::: "memory")
#define CP_WAIT0()  asm volatile("cp.async.wait_group 0;\n" ::: "memory")

// raw fp32 bits as tf32 operands (HW truncates low mantissa bits)
#define MMA_TF32(c0,c1,c2,c3, a0,a1,a2,a3, b0,b1)                          \
    asm volatile(                                                          \
        "mma.sync.aligned.m16n8k8.row.col.f32.tf32.tf32.f32 "              \
        "{%0,%1,%2,%3}, {%4,%5,%6,%7}, {%8,%9}, {%0,%1,%2,%3};\n"          \
        : "+f"(c0), "+f"(c1), "+f"(c2), "+f"(c3)                            \
        : "r"(a0), "r"(a1), "r"(a2), "r"(a3), "r"(b0), "r"(b1))

// ---------------- tf32 GEMM (3-stage cp.async) -----------------------------
// Block tile TM x 128, 8 warps (2 x 4), warp tile (TM/2) x 32, BK=32.
// STATS: C = h residual accumulate + per-block column sum/sumsq partials.
template<int TM>
__device__ __forceinline__ void load_tile_gemm(
    const float* __restrict__ A, const float* __restrict__ W,
    float (*As)[36], float (*Bs)[36],
    int bm, int bn, int K, int k0, int tid) {
    #pragma unroll
    for (int i = 0; i < TM / 32; i++) {
        int idx = tid + i * 256;
        int r = idx >> 3, qd = idx & 7;
        const float* src = A + (size_t)(bm + r) * K + k0 + qd * 4;
        float* dst = &As[r][qd * 4];
        if (k0 + qd * 4 + 4 <= K) {
            cp_async16(dst, src);
        } else {
            float4 v = make_float4(0.f, 0.f, 0.f, 0.f);
            if (k0 + qd * 4 + 0 < K) v.x = src[0];
            if (k0 + qd * 4 + 1 < K) v.y = src[1];
            if (k0 + qd * 4 + 2 < K) v.z = src[2];
            if (k0 + qd * 4 + 3 < K) v.w = src[3];
            *(float4*)dst = v;
        }
    }
    #pragma unroll
    for (int i = 0; i < 4; i++) {
        int idx = tid + i * 256;
        int r = idx >> 3, qd = idx & 7;
        const float* src = W + (size_t)(bn + r) * K + k0 + qd * 4;
        float* dst = &Bs[r][qd * 4];
        if (k0 + qd * 4 + 4 <= K) {
            cp_async16(dst, src);
        } else {
            float4 v = make_float4(0.f, 0.f, 0.f, 0.f);
            if (k0 + qd * 4 + 0 < K) v.x = src[0];
            if (k0 + qd * 4 + 1 < K) v.y = src[1];
            if (k0 + qd * 4 + 2 < K) v.z = src[2];
            if (k0 + qd * 4 + 3 < K) v.w = src[3];
            *(float4*)dst = v;
        }
    }
    CP_COMMIT();
}

template<int TM, int ACT, bool ACCUM, bool STATS>
__global__ __launch_bounds__(256, 2)
void gemm_tc_kernel(const float* __restrict__ A, const float* __restrict__ W,
                    const float* __restrict__ bias, float* __restrict__ C,
                    int K, int N) {
    constexpr int MT = TM / 32;
    constexpr int RED_OFF = 3 * TM * 36 + 3 * 128 * 36;
    extern __shared__ float sm[];
    float (*As)[36] = (float(*)[36])sm;                       // [3*TM][36]
    float (*Bs)[36] = (float(*)[36])(sm + 3 * TM * 36);       // [3*128][36]

    const int bm = blockIdx.y * TM, bn = blockIdx.x * 128;
    const int tid  = threadIdx.x;
    const int lane = tid & 31;
    const int wid  = tid >> 5;
    const int wm   = wid >> 2;
    const int wn   = wid & 3;
    const int g    = lane >> 2;
    const int tig  = lane & 3;

    float acc[MT][4][4] = {};

    const int KT = (K + 31) >> 5;
    load_tile_gemm<TM>(A, W, As, Bs, bm, bn, K, 0, tid);
    if (KT > 1)
        load_tile_gemm<TM>(A, W, As + TM, Bs + 128, bm, bn, K, 32, tid);

    for (int it = 0; it < KT; it++) {
        if (it + 1 < KT) CP_WAIT1(); else CP_WAIT0();
        __syncthreads();
        if (it + 2 < KT) {
            const int nb = (it + 2) % 3;
            load_tile_gemm<TM>(A, W, As + nb * TM, Bs + nb * 128,
                               bm, bn, K, (it + 2) * 32, tid);
        }

        const float (*Ac)[36] = As + (it % 3) * TM;
        const float (*Bc)[36] = Bs + (it % 3) * 128;
        #pragma unroll
        for (int ks = 0; ks < 4; ks++) {
            const int kc = ks * 8 + tig;
            unsigned a[MT][4], b[4][2];
            #pragma unroll
            for (int mt = 0; mt < MT; mt++) {
                const int r = wm * (TM / 2) + mt * 16 + g;
                a[mt][0] = __float_as_uint(Ac[r    ][kc]);
                a[mt][1] = __float_as_uint(Ac[r + 8][kc]);
                a[mt][2] = __float_as_uint(Ac[r    ][kc + 4]);
                a[mt][3] = __float_as_uint(Ac[r + 8][kc + 4]);
            }
            #pragma unroll
            for (int nt = 0; nt < 4; nt++) {
                const int r = wn * 32 + nt * 8 + g;
                b[nt][0] = __float_as_uint(Bc[r][kc]);
                b[nt][1] = __float_as_uint(Bc[r][kc + 4]);
            }
            #pragma unroll
            for (int mt = 0; mt < MT; mt++)
                #pragma unroll
                for (int nt = 0; nt < 4; nt++)
                    MMA_TF32(acc[mt][nt][0], acc[mt][nt][1],
                             acc[mt][nt][2], acc[mt][nt][3],
                             a[mt][0], a[mt][1], a[mt][2], a[mt][3],
                             b[nt][0], b[nt][1]);
        }
        __syncthreads();
    }

    float cs[4][2], cq[4][2];
    if (STATS) {
        #pragma unroll
        for (int nt = 0; nt < 4; nt++)
            cs[nt][0] = cs[nt][1] = cq[nt][0] = cq[nt][1] = 0.f;
    }

    #pragma unroll
    for (int mt = 0; mt < MT; mt++) {
        const int row = bm + wm * (TM / 2) + mt * 16 + g;
        #pragma unroll
        for (int nt = 0; nt < 4; nt++) {
            const int col = bn + wn * 32 + nt * 8 + 2 * tig;
            float b0 = 0.f, b1 = 0.f;
            if (bias) { b0 = bias[col]; b1 = bias[col + 1]; }
            #pragma unroll
            for (int half = 0; half < 2; half++) {
                const int r = row + half * 8;
                size_t idx = (size_t)r * N + col;
                float c0 = acc[mt][nt][half * 2 + 0] + b0;
                float c1 = acc[mt][nt][half * 2 + 1] + b1;
                if (ACCUM) { c0 += C[idx]; c1 += C[idx + 1]; }
                if (ACT == 1) { c0 = gelu_f(c0); c1 = gelu_f(c1); }
                C[idx]     = c0;
                C[idx + 1] = c1;
                if (STATS) {
                    cs[nt][0] += c0; cq[nt][0] += c0 * c0;
                    cs[nt][1] += c1; cq[nt][1] += c1 * c1;
                }
            }
        }
    }

    if (STATS) {
        float* sred = sm + RED_OFF;   // [2][128] sum, then [2][128] sq
        #pragma unroll
        for (int nt = 0; nt < 4; nt++)
            #pragma unroll
            for (int j = 0; j < 2; j++) {
                #pragma unroll
                for (int m = 4; m <= 16; m <<= 1) {
                    cs[nt][j] += __shfl_xor_sync(0xffffffffu, cs[nt][j], m);
                    cq[nt][j] += __shfl_xor_sync(0xffffffffu, cq[nt][j], m);
                }
            }
        if (g == 0) {
            #pragma unroll
            for (int nt = 0; nt < 4; nt++)
                #pragma unroll
                for (int j = 0; j < 2; j++) {
                    int c = wn * 32 + nt * 8 + 2 * tig + j;
                    sred[wm * 128 + c]       = cs[nt][j];
                    sred[256 + wm * 128 + c] = cq[nt][j];
                }
        }
        __syncthreads();
        if (tid < 128) {
            int c = tid;
            g_psum[blockIdx.y * HDIM + bn + c] = sred[c] + sred[128 + c];
            g_psq [blockIdx.y * HDIM + bn + c] = sred[256 + c] + sred[384 + c];
        }
    }
}

#define GEMM_SMEM_64  ((3 * 64 * 36 + 3 * 128 * 36) * 4 + 512 * 4)
#define GEMM_SMEM_128 ((3 * 128 * 36 + 3 * 128 * 36) * 4)

// ---------------- CSR build -------------------------------------------------
__global__ void count_deg_kernel(const int* __restrict__ row, int* __restrict__ cnt) {
    int e = blockIdx.x * 256 + threadIdx.x;
    if (e < NEDGE) atomicAdd(&cnt[row[e]], 1);
}

__global__ void scan_kernel(const int* __restrict__ cnt, int* __restrict__ off,
                            int* __restrict__ cur) {
    __shared__ int part[256];
    const int t = threadIdx.x;
    int loc[32];
    int s = 0;
    #pragma unroll
    for (int i = 0; i < 32; i++) { loc[i] = s; s += cnt[t * 32 + i]; }
    part[t] = s;
    __syncthreads();
    for (int ofs = 1; ofs < 256; ofs <<= 1) {
        int mine = part[t];
        int add = (t >= ofs) ? part[t - ofs] : 0;
        __syncthreads();
        part[t] = mine + add;
        __syncthreads();
    }
    int excl = (t > 0) ? part[t - 1] : 0;
    #pragma unroll
    for (int i = 0; i < 32; i++) {
        int v = excl + loc[i];
        off[t * 32 + i] = v;
        cur[t * 32 + i] = v;
    }
    if (t == 255) off[BNODES] = part[255];
}

__global__ void fill_csr_kernel(const int* __restrict__ row, int* __restrict__ cur,
                                int* __restrict__ eidx) {
    int e = blockIdx.x * 256 + threadIdx.x;
    if (e < NEDGE) {
        int p = atomicAdd(&cur[row[e]], 1);
        eidx[p] = e;
    }
}

// ---------------- GCN gather ------------------------------------------------
__global__ void gcn_gather_kernel(const float* __restrict__ t1,
                                  const int* __restrict__ off,
                                  const int* __restrict__ eidx,
                                  const int* __restrict__ ecol,
                                  const float* __restrict__ eval,
                                  float* __restrict__ agg) {
    const int node = blockIdx.x;
    const int f = threadIdx.x;
    __shared__ int   scol[64];
    __shared__ float sval[64];
    const int s = off[node], e_end = off[node + 1];
    float acc = 0.f;
    for (int base = s; base < e_end; base += 64) {
        int n = min(64, e_end - base);
        if (f < n) {
            int e = eidx[base + f];
            scol[f] = ecol[e];
            sval[f] = eval[e];
        }
        __syncthreads();
        for (int j = 0; j < n; j++)
            acc += sval[j] * t1[(size_t)scol[j] * HDIM + f];
        __syncthreads();
    }
    agg[(size_t)node * HDIM + f] = acc;
}

// ---------------- BatchNorm -------------------------------------------------
// GCN path only: x = h + gelu(add), partial sums (256 blocks x 32 rows)
__global__ void bnpre_kernel(float* __restrict__ h, const float* __restrict__ add,
                             float* __restrict__ psum, float* __restrict__ psq) {
    const int f = threadIdx.x;
    const int blk = blockIdx.x;
    float s = 0.f, sq = 0.f;
    size_t base = (size_t)blk * 32 * HDIM + f;
    #pragma unroll 4
    for (int r = 0; r < 32; r++) {
        size_t idx = base + (size_t)r * HDIM;
        float v = h[idx] + gelu_f(add[idx]);
        h[idx] = v;
        s += v;
        sq += v * v;
    }
    psum[blk * HDIM + f] = s;
    psq [blk * HDIM + f] = sq;
}

__global__ void bnapply_kernel(float* __restrict__ h,
                               const float* __restrict__ psum,
                               const float* __restrict__ psq,
                               const float* __restrict__ g,
                               const float* __restrict__ b, int npart) {
    const int f = threadIdx.x;
    float s = 0.f, sq = 0.f;
    for (int p = 0; p < npart; p++) { s += psum[p * HDIM + f]; sq += psq[p * HDIM + f]; }
    const float mu  = s * (1.0f / BNODES);
    const float is_ = rsqrtf(sq * (1.0f / BNODES) - mu * mu + 1e-5f);
    const float gg = g[f], bb = b[f];
    size_t base = (size_t)blockIdx.x * 64 * HDIM + f;   // 128 blocks x 64 rows
    #pragma unroll 4
    for (int r = 0; r < 64; r++) {
        size_t i = base + (size_t)r * HDIM;
        h[i] = (h[i] - mu) * is_ * gg + bb;
    }
}

// ---------------- tf32 flash attention, Q-tile 128, 8 warps ----------------
#define ATTN_SMEM ((4 * 64 * 36) * 4 + (128 * 68) * 4)

__global__ __launch_bounds__(256)
void attn_tc_kernel(const float* __restrict__ qkv, float* __restrict__ out) {
    extern __shared__ float dsm[];
    float (*Kf)[64][36]  = (float(*)[64][36])dsm;
    float (*Vf)[64][36]  = (float(*)[64][36])(dsm + 2 * 64 * 36);
    unsigned (*Ss)[68]   = (unsigned(*)[68])(dsm + 4 * 64 * 36);
    float* Ssf = (float*)&Ss[0][0];

    const int qt = blockIdx.x, nh = blockIdx.y, b = blockIdx.z;
    const int tid  = threadIdx.x;
    const int lane = tid & 31;
    const int w    = tid >> 5;
    const int g    = lane >> 2;
    const int tig  = lane & 3;
    const float scale = 0.17677669529663687f;

    const size_t rowb = (size_t)(b * 1024) * 768 + nh * 32;

    {
        size_t qoff = rowb + (size_t)(qt * 128) * 768;
        #pragma unroll
        for (int i = 0; i < 4; i++) {
            int idx = tid + i * 256;
            int r = idx >> 3, c4 = (idx & 7) * 4;
            float4 v = *(const float4*)(qkv + qoff + (size_t)r * 768 + c4);
            Ssf[r * 68 + c4 + 0] = v.x; Ssf[r * 68 + c4 + 1] = v.y;
            Ssf[r * 68 + c4 + 2] = v.z; Ssf[r * 68 + c4 + 3] = v.w;
        }
    }
    __syncthreads();

    unsigned q[4][4];
    const int r0 = w * 16 + g;
    #pragma unroll
    for (int kt4 = 0; kt4 < 4; kt4++) {
        q[kt4][0] = __float_as_uint(Ssf[(r0    ) * 68 + kt4 * 8 + tig    ]);
        q[kt4][1] = __float_as_uint(Ssf[(r0 + 8) * 68 + kt4 * 8 + tig    ]);
        q[kt4][2] = __float_as_uint(Ssf[(r0    ) * 68 + kt4 * 8 + tig + 4]);
        q[kt4][3] = __float_as_uint(Ssf[(r0 + 8) * 68 + kt4 * 8 + tig + 4]);
    }
    __syncthreads();

    {
        #pragma unroll
        for (int i = 0; i < 2; i++) {
            int idx = tid + i * 256;
            int r = idx >> 3, c4 = (idx & 7) * 4;
            cp_async16(&Kf[0][r][c4], qkv + rowb + (size_t)r * 768 + 256 + c4);
            cp_async16(&Vf[0][r][c4], qkv + rowb + (size_t)r * 768 + 512 + c4);
        }
        CP_COMMIT();
    }

    float m0 = -1e30f, m1 = -1e30f, l0 = 0.f, l1 = 0.f;
    float o[4][4] = {};

    for (int kt = 0; kt < 16; kt++) {
        if (kt + 1 < 16) {
            size_t koff = rowb + (size_t)((kt + 1) * 64) * 768;
            int st = (kt + 1) & 1;
            #pragma unroll
            for (int i = 0; i < 2; i++) {
                int idx = tid + i * 256;
                int r = idx >> 3, c4 = (idx & 7) * 4;
                cp_async16(&Kf[st][r][c4], qkv + koff + (size_t)r * 768 + 256 + c4);
                cp_async16(&Vf[st][r][c4], qkv + koff + (size_t)r * 768 + 512 + c4);
            }
            CP_COMMIT();
            CP_WAIT1();
        } else {
            CP_WAIT0();
        }
        __syncthreads();

        const float (*Kc)[36] = Kf[kt & 1];
        const float (*Vc)[36] = Vf[kt & 1];

        float s[8][4] = {};
        #pragma unroll
        for (int kt4 = 0; kt4 < 4; kt4++) {
            #pragma unroll
            for (int nt = 0; nt < 8; nt++) {
                unsigned b0 = __float_as_uint(Kc[nt * 8 + g][kt4 * 8 + tig]);
                unsigned b1 = __float_as_uint(Kc[nt * 8 + g][kt4 * 8 + tig + 4]);
                MMA_TF32(s[nt][0], s[nt][1], s[nt][2], s[nt][3],
                         q[kt4][0], q[kt4][1], q[kt4][2], q[kt4][3], b0, b1);
            }
        }

        float rmax0 = -1e30f, rmax1 = -1e30f;
        #pragma unroll
        for (int nt = 0; nt < 8; nt++) {
            s[nt][0] *= scale; s[nt][1] *= scale;
            s[nt][2] *= scale; s[nt][3] *= scale;
            rmax0 = fmaxf(rmax0, fmaxf(s[nt][0], s[nt][1]));
            rmax1 = fmaxf(rmax1, fmaxf(s[nt][2], s[nt][3]));
        }
        rmax0 = fmaxf(rmax0, __shfl_xor_sync(0xffffffffu, rmax0, 1));
        rmax0 = fmaxf(rmax0, __shfl_xor_sync(0xffffffffu, rmax0, 2));
        rmax1 = fmaxf(rmax1, __shfl_xor_sync(0xffffffffu, rmax1, 1));
        rmax1 = fmaxf(rmax1, __shfl_xor_sync(0xffffffffu, rmax1, 2));

        float mn0 = fmaxf(m0, rmax0), mn1 = fmaxf(m1, rmax1);
        float cor0 = __expf(m0 - mn0), cor1 = __expf(m1 - mn1);
        m0 = mn0; m1 = mn1;

        float ps0 = 0.f, ps1 = 0.f;
        #pragma unroll
        for (int nt = 0; nt < 8; nt++) {
            float p0 = __expf(s[nt][0] - mn0);
            float p1 = __expf(s[nt][1] - mn0);
            float p2 = __expf(s[nt][2] - mn1);
            float p3 = __expf(s[nt][3] - mn1);
            ps0 += p0 + p1; ps1 += p2 + p3;
            int c = nt * 8 + 2 * tig;
            Ss[r0    ][c] = __float_as_uint(p0); Ss[r0    ][c + 1] = __float_as_uint(p1);
            Ss[r0 + 8][c] = __float_as_uint(p2); Ss[r0 + 8][c + 1] = __float_as_uint(p3);
        }
        ps0 += __shfl_xor_sync(0xffffffffu, ps0, 1);
        ps0 += __shfl_xor_sync(0xffffffffu, ps0, 2);
        ps1 += __shfl_xor_sync(0xffffffffu, ps1, 1);
        ps1 += __shfl_xor_sync(0xffffffffu, ps1, 2);
        l0 = l0 * cor0 + ps0;
        l1 = l1 * cor1 + ps1;
        #pragma unroll
        for (int nt = 0; nt < 4; nt++) {
            o[nt][0] *= cor0; o[nt][1] *= cor0;
            o[nt][2] *= cor1; o[nt][3] *= cor1;
        }
        __syncwarp();

        #pragma unroll
        for (int ks = 0; ks < 8; ks++) {
            unsigned a0 = Ss[r0    ][ks * 8 + tig];
            unsigned a1 = Ss[r0 + 8][ks * 8 + tig];
            unsigned a2 = Ss[r0    ][ks * 8 + tig + 4];
            unsigned a3 = Ss[r0 + 8][ks * 8 + tig + 4];
            #pragma unroll
            for (int nt = 0; nt < 4; nt++) {
                unsigned b0 = __float_as_uint(Vc[ks * 8 + tig    ][nt * 8 + g]);
                unsigned b1 = __float_as_uint(Vc[ks * 8 + tig + 4][nt * 8 + g]);
                MMA_TF32(o[nt][0], o[nt][1], o[nt][2], o[nt][3],
                         a0, a1, a2, a3, b0, b1);
            }
        }
        __syncthreads();
    }

    const float inv0 = 1.0f / l0, inv1 = 1.0f / l1;
    const int row0 = b * 1024 + qt * 128 + w * 16 + g;
    #pragma unroll
    for (int nt = 0; nt < 4; nt++) {
        const int col = nh * 32 + nt * 8 + 2 * tig;
        size_t i0 = (size_t)row0 * HDIM + col;
        size_t i1 = (size_t)(row0 + 8) * HDIM + col;
        out[i0]     = o[nt][0] * inv0;
        out[i0 + 1] = o[nt][1] * inv0;
        out[i1]     = o[nt][2] * inv1;
        out[i1 + 1] = o[nt][3] * inv1;
    }
}

// ---------------- head final ------------------------------------------------
__global__ void head_final_kernel(const float* __restrict__ t, const float* __restrict__ w,
                                  const float* __restrict__ b, float* __restrict__ out) {
    int row = blockIdx.x * 8 + (threadIdx.x >> 5);
    int lane = threadIdx.x & 31;
    float acc = 0.f;
    #pragma unroll
    for (int i = lane; i < 128; i += 32)
        acc += t[(size_t)row * 128 + i] * w[i];
    #pragma unroll
    for (int ofs = 16; ofs; ofs >>= 1)
        acc += __shfl_xor_sync(0xffffffffu, acc, ofs);
    if (lane == 0)
        out[row] = 1.0f / (1.0f + expf(-(acc + b[0])));
}

// ---------------- host orchestration ----------------------------------------
extern "C" void kernel_launch(void* const* d_in, const int* in_sizes, int n_in,
                              void* d_out, int out_size) {
    const float* x        = (const float*)d_in[0];
    const int*   erow     = (const int*)  d_in[1];
    const int*   ecol     = (const int*)  d_in[2];
    const float* eval     = (const float*)d_in[3];
    const float* pe       = (const float*)d_in[4];
    const float* W_in     = (const float*)d_in[5];
    const float* b_in     = (const float*)d_in[6];
    const float* W_pe     = (const float*)d_in[7];
    const float* b_pe     = (const float*)d_in[8];
    const float* gcn_W    = (const float*)d_in[9];
    const float* ain_W    = (const float*)d_in[10];
    const float* ain_b    = (const float*)d_in[11];
    const float* aout_W   = (const float*)d_in[12];
    const float* aout_b   = (const float*)d_in[13];
    const float* bn_g     = (const float*)d_in[14];
    const float* bn_b     = (const float*)d_in[15];
    const float* ffn_W1   = (const float*)d_in[16];
    const float* ffn_b1   = (const float*)d_in[17];
    const float* ffn_W2   = (const float*)d_in[18];
    const float* ffn_b2   = (const float*)d_in[19];
    const float* head_W1  = (const float*)d_in[20];
    const float* head_b1  = (const float*)d_in[21];
    const float* head_W2  = (const float*)d_in[22];
    const float* head_b2  = (const float*)d_in[23];

    float *h, *t1, *t2, *psum, *psq;
    int *cnt, *off, *cur, *eidx;
    cudaGetSymbolAddress((void**)&h,    g_h);
    cudaGetSymbolAddress((void**)&t1,   g_t1);
    cudaGetSymbolAddress((void**)&t2,   g_t2);
    cudaGetSymbolAddress((void**)&psum, g_psum);
    cudaGetSymbolAddress((void**)&psq,  g_psq);
    cudaGetSymbolAddress((void**)&cnt,  g_cnt);
    cudaGetSymbolAddress((void**)&off,  g_off);
    cudaGetSymbolAddress((void**)&cur,  g_cur);
    cudaGetSymbolAddress((void**)&eidx, g_eidx);

    cudaFuncSetAttribute(attn_tc_kernel,
                         cudaFuncAttributeMaxDynamicSharedMemorySize, ATTN_SMEM);
    cudaFuncSetAttribute(gemm_tc_kernel<64, 0, false, false>,
                         cudaFuncAttributeMaxDynamicSharedMemorySize, GEMM_SMEM_64);
    cudaFuncSetAttribute(gemm_tc_kernel<64, 0, true, false>,
                         cudaFuncAttributeMaxDynamicSharedMemorySize, GEMM_SMEM_64);
    cudaFuncSetAttribute(gemm_tc_kernel<64, 0, true, true>,
                         cudaFuncAttributeMaxDynamicSharedMemorySize, GEMM_SMEM_64);
    cudaFuncSetAttribute(gemm_tc_kernel<64, 1, false, false>,
                         cudaFuncAttributeMaxDynamicSharedMemorySize, GEMM_SMEM_64);
    cudaFuncSetAttribute(gemm_tc_kernel<128, 0, false, false>,
                         cudaFuncAttributeMaxDynamicSharedMemorySize, GEMM_SMEM_128);
    cudaFuncSetAttribute(gemm_tc_kernel<128, 1, false, false>,
                         cudaFuncAttributeMaxDynamicSharedMemorySize, GEMM_SMEM_128);

    cudaMemsetAsync(cnt, 0, BNODES * sizeof(int));
    count_deg_kernel<<<NEDGE / 256, 256>>>(erow, cnt);
    scan_kernel<<<1, 256>>>(cnt, off, cur);
    fill_csr_kernel<<<NEDGE / 256, 256>>>(erow, cur, eidx);

    const dim3 g256 (2, BNODES / 64);    // TM=64,  N=256
    const dim3 g768 (6, BNODES / 128);   // TM=128, N=768
    const dim3 g1024(8, BNODES / 128);   // TM=128, N=1024
    const dim3 g128 (1, BNODES / 64);    // TM=64,  N=128

    gemm_tc_kernel<64, 0, false, false><<<g256, 256, GEMM_SMEM_64>>>(
        x,  W_in, b_in, h, 128, HDIM);
    gemm_tc_kernel<64, 0, true, false><<<g256, 256, GEMM_SMEM_64>>>(
        pe, W_pe, b_pe, h, 8, HDIM);

    for (int l = 0; l < NLAYER; l++) {
        // ---- local GCN ----
        gemm_tc_kernel<64, 0, false, false><<<g256, 256, GEMM_SMEM_64>>>(
            h, gcn_W + (size_t)l * HDIM * HDIM, nullptr, t1, HDIM, HDIM);
        gcn_gather_kernel<<<BNODES, 256>>>(t1, off, eidx, ecol, eval, t2);
        bnpre_kernel<<<256, 256>>>(h, t2, psum, psq);
        bnapply_kernel<<<128, 256>>>(h, psum, psq,
                                     bn_g + l * 3 * HDIM, bn_b + l * 3 * HDIM, 256);
        // ---- global attention ----
        gemm_tc_kernel<128, 0, false, false><<<g768, 256, GEMM_SMEM_128>>>(
            h, ain_W + (size_t)l * 768 * HDIM, ain_b + l * 768, t1, HDIM, 768);
        attn_tc_kernel<<<dim3(8, 8, 8), 256, ATTN_SMEM>>>(t1, t2);
        gemm_tc_kernel<64, 0, true, true><<<g256, 256, GEMM_SMEM_64>>>(
            t2, aout_W + (size_t)l * HDIM * HDIM, aout_b + l * HDIM, h, HDIM, HDIM);
        bnapply_kernel<<<128, 256>>>(h, psum, psq,
                                     bn_g + l * 3 * HDIM + HDIM,
                                     bn_b + l * 3 * HDIM + HDIM, 128);
        // ---- FFN ----
        gemm_tc_kernel<128, 1, false, false><<<g1024, 256, GEMM_SMEM_128>>>(
            h, ffn_W1 + (size_t)l * 1024 * HDIM, ffn_b1 + l * 1024, t1, HDIM, 1024);
        gemm_tc_kernel<64, 0, true, true><<<g256, 256, GEMM_SMEM_64>>>(
            t1, ffn_W2 + (size_t)l * HDIM * 1024, ffn_b2 + l * HDIM, h, 1024, HDIM);
        bnapply_kernel<<<128, 256>>>(h, psum, psq,
                                     bn_g + l * 3 * HDIM + 2 * HDIM,
                                     bn_b + l * 3 * HDIM + 2 * HDIM, 128);
    }

    gemm_tc_kernel<64, 1, false, false><<<g128, 256, GEMM_SMEM_64>>>(
        h, head_W1, head_b1, t1, HDIM, 128);
    head_final_kernel<<<BNODES / 8, 256>>>(t1, head_W2, head_b2, (float*)d_out);
}

// round 7
// speedup vs baseline: 2.5303x; 1.0264x over previous
#include <cuda_runtime.h>
#include <cuda_bf16.h>
#include <math.h>

#define BNODES 8192
#define HDIM   256
#define NEDGE  131072
#define NLAYER 4

__device__ float g_h [BNODES * HDIM];
__device__ float g_t1[BNODES * 1024];
__device__ float g_t2[BNODES * HDIM];
__device__ int   g_cnt[BNODES];
__device__ int   g_off[BNODES + 1];
__device__ int   g_cur[BNODES];
__device__ int   g_eidx[NEDGE];
__device__ float g_psum[256 * HDIM];
__device__ float g_psq [256 * HDIM];

__device__ __forceinline__ float gelu_f(float x) {
    return 0.5f * x * (1.0f + erff(x * 0.70710678118654752f));
}

__device__ __forceinline__ void cp_async16(void* smem_dst, const void* gmem_src) {
    unsigned s = (unsigned)__cvta_generic_to_shared(smem_dst);
    asm volatile("cp.async.cg.shared.global [%0], [%1], 16;\n" :: "r"(s), "l"(gmem_src));
}
#define CP_COMMIT() asm volatile("cp.async.commit_group;\n" ::: "memory")
#define CP_WAIT1()  asm volatile("cp.async.wait_group 1;\n" ::: "memory")
#define CP_WAIT0()  asm volatile("cp.async.wait_group 0;\n" ::: "memory")

// raw fp32 bits as tf32 operands (HW truncates low mantissa bits)
#define MMA_TF32(c0,c1,c2,c3, a0,a1,a2,a3, b0,b1)                          \
    asm volatile(                                                          \
        "mma.sync.aligned.m16n8k8.row.col.f32.tf32.tf32.f32 "              \
        "{%0,%1,%2,%3}, {%4,%5,%6,%7}, {%8,%9}, {%0,%1,%2,%3};\n"          \
        : "+f"(c0), "+f"(c1), "+f"(c2), "+f"(c3)                            \
        : "r"(a0), "r"(a1), "r"(a2), "r"(a3), "r"(b0), "r"(b1))

// ldmatrix x4: 4 8x8-b16 tiles = 4 8x4-tf32 tiles
#define LDSM4(r0,r1,r2,r3, addr)                                            \
    asm volatile("ldmatrix.sync.aligned.m8n8.x4.shared.b16 {%0,%1,%2,%3}, [%4];" \
        : "=r"(r0), "=r"(r1), "=r"(r2), "=r"(r3) : "r"(addr))

// ---------------- tf32 GEMM (3-stage cp.async + ldmatrix) -------------------
// Block tile TM x 128, 8 warps (2 x 4), warp tile (TM/2) x 32, BK=32.
template<int TM>
__device__ __forceinline__ void load_tile_gemm(
    const float* __restrict__ A, const float* __restrict__ W,
    float (*As)[36], float (*Bs)[36],
    int bm, int bn, int K, int k0, int tid) {
    #pragma unroll
    for (int i = 0; i < TM / 32; i++) {
        int idx = tid + i * 256;
        int r = idx >> 3, qd = idx & 7;
        const float* src = A + (size_t)(bm + r) * K + k0 + qd * 4;
        float* dst = &As[r][qd * 4];
        if (k0 + qd * 4 + 4 <= K) {
            cp_async16(dst, src);
        } else {
            float4 v = make_float4(0.f, 0.f, 0.f, 0.f);
            if (k0 + qd * 4 + 0 < K) v.x = src[0];
            if (k0 + qd * 4 + 1 < K) v.y = src[1];
            if (k0 + qd * 4 + 2 < K) v.z = src[2];
            if (k0 + qd * 4 + 3 < K) v.w = src[3];
            *(float4*)dst = v;
        }
    }
    #pragma unroll
    for (int i = 0; i < 4; i++) {
        int idx = tid + i * 256;
        int r = idx >> 3, qd = idx & 7;
        const float* src = W + (size_t)(bn + r) * K + k0 + qd * 4;
        float* dst = &Bs[r][qd * 4];
        if (k0 + qd * 4 + 4 <= K) {
            cp_async16(dst, src);
        } else {
            float4 v = make_float4(0.f, 0.f, 0.f, 0.f);
            if (k0 + qd * 4 + 0 < K) v.x = src[0];
            if (k0 + qd * 4 + 1 < K) v.y = src[1];
            if (k0 + qd * 4 + 2 < K) v.z = src[2];
            if (k0 + qd * 4 + 3 < K) v.w = src[3];
            *(float4*)dst = v;
        }
    }
    CP_COMMIT();
}

template<int TM, int ACT, bool ACCUM, bool STATS>
__global__ __launch_bounds__(256, 2)
void gemm_tc_kernel(const float* __restrict__ A, const float* __restrict__ W,
                    const float* __restrict__ bias, float* __restrict__ C,
                    int K, int N) {
    constexpr int MT = TM / 32;
    constexpr int RED_OFF = 3 * TM * 36 + 3 * 128 * 36;
    extern __shared__ float sm[];
    float (*As)[36] = (float(*)[36])sm;                       // [3*TM][36]
    float (*Bs)[36] = (float(*)[36])(sm + 3 * TM * 36);       // [3*128][36]

    const int bm = blockIdx.y * TM, bn = blockIdx.x * 128;
    const int tid  = threadIdx.x;
    const int lane = tid & 31;
    const int wid  = tid >> 5;
    const int wm   = wid >> 2;
    const int wn   = wid & 3;
    const int g    = lane >> 2;
    const int tig  = lane & 3;

    // ldmatrix lane-address components (bytes; row stride = 36*4 = 144)
    const unsigned aBase0 = (unsigned)__cvta_generic_to_shared(&As[0][0]);
    const unsigned bBase0 = aBase0 + 3 * TM * 36 * 4;
    const unsigned aLane = (unsigned)(wm * (TM / 2) + (lane & 15)) * 144
                         + ((lane >> 4) << 4);                       // row + col-half(16B)
    const unsigned bLane = (unsigned)(wn * 32 + ((lane >> 4) << 3) + (lane & 7)) * 144
                         + (((lane >> 3) & 1) << 4);

    float acc[MT][4][4] = {};

    const int KT = (K + 31) >> 5;
    load_tile_gemm<TM>(A, W, As, Bs, bm, bn, K, 0, tid);
    if (KT > 1)
        load_tile_gemm<TM>(A, W, As + TM, Bs + 128, bm, bn, K, 32, tid);

    for (int it = 0; it < KT; it++) {
        if (it + 1 < KT) CP_WAIT1(); else CP_WAIT0();
        __syncthreads();
        if (it + 2 < KT) {
            const int nb = (it + 2) % 3;
            load_tile_gemm<TM>(A, W, As + nb * TM, Bs + nb * 128,
                               bm, bn, K, (it + 2) * 32, tid);
        }

        const unsigned aB = aBase0 + (unsigned)((it % 3) * TM) * 144 + aLane;
        const unsigned bB = bBase0 + (unsigned)((it % 3) * 128) * 144 + bLane;

        #pragma unroll
        for (int ks = 0; ks < 4; ks++) {
            unsigned a[MT][4], b[4][2];
            #pragma unroll
            for (int mt = 0; mt < MT; mt++)
                LDSM4(a[mt][0], a[mt][1], a[mt][2], a[mt][3],
                      aB + mt * (16 * 144) + ks * 32);
            LDSM4(b[0][0], b[0][1], b[1][0], b[1][1], bB + ks * 32);
            LDSM4(b[2][0], b[2][1], b[3][0], b[3][1], bB + 16 * 144 + ks * 32);
            #pragma unroll
            for (int mt = 0; mt < MT; mt++)
                #pragma unroll
                for (int nt = 0; nt < 4; nt++)
                    MMA_TF32(acc[mt][nt][0], acc[mt][nt][1],
                             acc[mt][nt][2], acc[mt][nt][3],
                             a[mt][0], a[mt][1], a[mt][2], a[mt][3],
                             b[nt][0], b[nt][1]);
        }
        __syncthreads();
    }

    float cs[4][2], cq[4][2];
    if (STATS) {
        #pragma unroll
        for (int nt = 0; nt < 4; nt++)
            cs[nt][0] = cs[nt][1] = cq[nt][0] = cq[nt][1] = 0.f;
    }

    #pragma unroll
    for (int mt = 0; mt < MT; mt++) {
        const int row = bm + wm * (TM / 2) + mt * 16 + g;
        #pragma unroll
        for (int nt = 0; nt < 4; nt++) {
            const int col = bn + wn * 32 + nt * 8 + 2 * tig;
            float b0 = 0.f, b1 = 0.f;
            if (bias) { b0 = bias[col]; b1 = bias[col + 1]; }
            #pragma unroll
            for (int half = 0; half < 2; half++) {
                const int r = row + half * 8;
                size_t idx = (size_t)r * N + col;
                float c0 = acc[mt][nt][half * 2 + 0] + b0;
                float c1 = acc[mt][nt][half * 2 + 1] + b1;
                if (ACCUM) { c0 += C[idx]; c1 += C[idx + 1]; }
                if (ACT == 1) { c0 = gelu_f(c0); c1 = gelu_f(c1); }
                C[idx]     = c0;
                C[idx + 1] = c1;
                if (STATS) {
                    cs[nt][0] += c0; cq[nt][0] += c0 * c0;
                    cs[nt][1] += c1; cq[nt][1] += c1 * c1;
                }
            }
        }
    }

    if (STATS) {
        float* sred = sm + RED_OFF;   // [2][128] sum, then [2][128] sq
        #pragma unroll
        for (int nt = 0; nt < 4; nt++)
            #pragma unroll
            for (int j = 0; j < 2; j++) {
                #pragma unroll
                for (int m = 4; m <= 16; m <<= 1) {
                    cs[nt][j] += __shfl_xor_sync(0xffffffffu, cs[nt][j], m);
                    cq[nt][j] += __shfl_xor_sync(0xffffffffu, cq[nt][j], m);
                }
            }
        if (g == 0) {
            #pragma unroll
            for (int nt = 0; nt < 4; nt++)
                #pragma unroll
                for (int j = 0; j < 2; j++) {
                    int c = wn * 32 + nt * 8 + 2 * tig + j;
                    sred[wm * 128 + c]       = cs[nt][j];
                    sred[256 + wm * 128 + c] = cq[nt][j];
                }
        }
        __syncthreads();
        if (tid < 128) {
            int c = tid;
            g_psum[blockIdx.y * HDIM + bn + c] = sred[c] + sred[128 + c];
            g_psq [blockIdx.y * HDIM + bn + c] = sred[256 + c] + sred[384 + c];
        }
    }
}

#define GEMM_SMEM_64  ((3 * 64 * 36 + 3 * 128 * 36) * 4 + 512 * 4)
#define GEMM_SMEM_128 ((3 * 128 * 36 + 3 * 128 * 36) * 4)

// ---------------- CSR build -------------------------------------------------
__global__ void count_deg_kernel(const int* __restrict__ row, int* __restrict__ cnt) {
    int e = blockIdx.x * 256 + threadIdx.x;
    if (e < NEDGE) atomicAdd(&cnt[row[e]], 1);
}

__global__ void scan_kernel(const int* __restrict__ cnt, int* __restrict__ off,
                            int* __restrict__ cur) {
    __shared__ int part[256];
    const int t = threadIdx.x;
    int loc[32];
    int s = 0;
    #pragma unroll
    for (int i = 0; i < 32; i++) { loc[i] = s; s += cnt[t * 32 + i]; }
    part[t] = s;
    __syncthreads();
    for (int ofs = 1; ofs < 256; ofs <<= 1) {
        int mine = part[t];
        int add = (t >= ofs) ? part[t - ofs] : 0;
        __syncthreads();
        part[t] = mine + add;
        __syncthreads();
    }
    int excl = (t > 0) ? part[t - 1] : 0;
    #pragma unroll
    for (int i = 0; i < 32; i++) {
        int v = excl + loc[i];
        off[t * 32 + i] = v;
        cur[t * 32 + i] = v;
    }
    if (t == 255) off[BNODES] = part[255];
}

__global__ void fill_csr_kernel(const int* __restrict__ row, int* __restrict__ cur,
                                int* __restrict__ eidx) {
    int e = blockIdx.x * 256 + threadIdx.x;
    if (e < NEDGE) {
        int p = atomicAdd(&cur[row[e]], 1);
        eidx[p] = e;
    }
}

// ---------------- GCN gather ------------------------------------------------
__global__ void gcn_gather_kernel(const float* __restrict__ t1,
                                  const int* __restrict__ off,
                                  const int* __restrict__ eidx,
                                  const int* __restrict__ ecol,
                                  const float* __restrict__ eval,
                                  float* __restrict__ agg) {
    const int node = blockIdx.x;
    const int f = threadIdx.x;
    __shared__ int   scol[64];
    __shared__ float sval[64];
    const int s = off[node], e_end = off[node + 1];
    float acc = 0.f;
    for (int base = s; base < e_end; base += 64) {
        int n = min(64, e_end - base);
        if (f < n) {
            int e = eidx[base + f];
            scol[f] = ecol[e];
            sval[f] = eval[e];
        }
        __syncthreads();
        for (int j = 0; j < n; j++)
            acc += sval[j] * t1[(size_t)scol[j] * HDIM + f];
        __syncthreads();
    }
    agg[(size_t)node * HDIM + f] = acc;
}

// ---------------- BatchNorm -------------------------------------------------
__global__ void bnpre_kernel(float* __restrict__ h, const float* __restrict__ add,
                             float* __restrict__ psum, float* __restrict__ psq) {
    const int f = threadIdx.x;
    const int blk = blockIdx.x;
    float s = 0.f, sq = 0.f;
    size_t base = (size_t)blk * 32 * HDIM + f;
    #pragma unroll 4
    for (int r = 0; r < 32; r++) {
        size_t idx = base + (size_t)r * HDIM;
        float v = h[idx] + gelu_f(add[idx]);
        h[idx] = v;
        s += v;
        sq += v * v;
    }
    psum[blk * HDIM + f] = s;
    psq [blk * HDIM + f] = sq;
}

__global__ void bnapply_kernel(float* __restrict__ h,
                               const float* __restrict__ psum,
                               const float* __restrict__ psq,
                               const float* __restrict__ g,
                               const float* __restrict__ b, int npart) {
    const int f = threadIdx.x;
    float s = 0.f, sq = 0.f;
    for (int p = 0; p < npart; p++) { s += psum[p * HDIM + f]; sq += psq[p * HDIM + f]; }
    const float mu  = s * (1.0f / BNODES);
    const float is_ = rsqrtf(sq * (1.0f / BNODES) - mu * mu + 1e-5f);
    const float gg = g[f], bb = b[f];
    size_t base = (size_t)blockIdx.x * 64 * HDIM + f;
    #pragma unroll 4
    for (int r = 0; r < 64; r++) {
        size_t i = base + (size_t)r * HDIM;
        h[i] = (h[i] - mu) * is_ * gg + bb;
    }
}

// ---------------- tf32 flash attention, Q-tile 128, 8 warps ----------------
#define ATTN_SMEM ((4 * 64 * 36) * 4 + (128 * 68) * 4)

__global__ __launch_bounds__(256)
void attn_tc_kernel(const float* __restrict__ qkv, float* __restrict__ out) {
    extern __shared__ float dsm[];
    float (*Kf)[64][36]  = (float(*)[64][36])dsm;
    float (*Vf)[64][36]  = (float(*)[64][36])(dsm + 2 * 64 * 36);
    unsigned (*Ss)[68]   = (unsigned(*)[68])(dsm + 4 * 64 * 36);
    float* Ssf = (float*)&Ss[0][0];

    const int qt = blockIdx.x, nh = blockIdx.y, b = blockIdx.z;
    const int tid  = threadIdx.x;
    const int lane = tid & 31;
    const int w    = tid >> 5;
    const int g    = lane >> 2;
    const int tig  = lane & 3;
    const float scale = 0.17677669529663687f;

    const size_t rowb = (size_t)(b * 1024) * 768 + nh * 32;

    {
        size_t qoff = rowb + (size_t)(qt * 128) * 768;
        #pragma unroll
        for (int i = 0; i < 4; i++) {
            int idx = tid + i * 256;
            int r = idx >> 3, c4 = (idx & 7) * 4;
            float4 v = *(const float4*)(qkv + qoff + (size_t)r * 768 + c4);
            Ssf[r * 68 + c4 + 0] = v.x; Ssf[r * 68 + c4 + 1] = v.y;
            Ssf[r * 68 + c4 + 2] = v.z; Ssf[r * 68 + c4 + 3] = v.w;
        }
    }
    __syncthreads();

    unsigned q[4][4];
    const int r0 = w * 16 + g;
    #pragma unroll
    for (int kt4 = 0; kt4 < 4; kt4++) {
        q[kt4][0] = __float_as_uint(Ssf[(r0    ) * 68 + kt4 * 8 + tig    ]);
        q[kt4][1] = __float_as_uint(Ssf[(r0 + 8) * 68 + kt4 * 8 + tig    ]);
        q[kt4][2] = __float_as_uint(Ssf[(r0    ) * 68 + kt4 * 8 + tig + 4]);
        q[kt4][3] = __float_as_uint(Ssf[(r0 + 8) * 68 + kt4 * 8 + tig + 4]);
    }
    __syncthreads();

    {
        #pragma unroll
        for (int i = 0; i < 2; i++) {
            int idx = tid + i * 256;
            int r = idx >> 3, c4 = (idx & 7) * 4;
            cp_async16(&Kf[0][r][c4], qkv + rowb + (size_t)r * 768 + 256 + c4);
            cp_async16(&Vf[0][r][c4], qkv + rowb + (size_t)r * 768 + 512 + c4);
        }
        CP_COMMIT();
    }

    float m0 = -1e30f, m1 = -1e30f, l0 = 0.f, l1 = 0.f;
    float o[4][4] = {};

    for (int kt = 0; kt < 16; kt++) {
        if (kt + 1 < 16) {
            size_t koff = rowb + (size_t)((kt + 1) * 64) * 768;
            int st = (kt + 1) & 1;
            #pragma unroll
            for (int i = 0; i < 2; i++) {
                int idx = tid + i * 256;
                int r = idx >> 3, c4 = (idx & 7) * 4;
                cp_async16(&Kf[st][r][c4], qkv + koff + (size_t)r * 768 + 256 + c4);
                cp_async16(&Vf[st][r][c4], qkv + koff + (size_t)r * 768 + 512 + c4);
            }
            CP_COMMIT();
            CP_WAIT1();
        } else {
            CP_WAIT0();
        }
        __syncthreads();

        const float (*Kc)[36] = Kf[kt & 1];
        const float (*Vc)[36] = Vf[kt & 1];

        float s[8][4] = {};
        #pragma unroll
        for (int kt4 = 0; kt4 < 4; kt4++) {
            #pragma unroll
            for (int nt = 0; nt < 8; nt++) {
                unsigned b0 = __float_as_uint(Kc[nt * 8 + g][kt4 * 8 + tig]);
                unsigned b1 = __float_as_uint(Kc[nt * 8 + g][kt4 * 8 + tig + 4]);
                MMA_TF32(s[nt][0], s[nt][1], s[nt][2], s[nt][3],
                         q[kt4][0], q[kt4][1], q[kt4][2], q[kt4][3], b0, b1);
            }
        }

        float rmax0 = -1e30f, rmax1 = -1e30f;
        #pragma unroll
        for (int nt = 0; nt < 8; nt++) {
            s[nt][0] *= scale; s[nt][1] *= scale;
            s[nt][2] *= scale; s[nt][3] *= scale;
            rmax0 = fmaxf(rmax0, fmaxf(s[nt][0], s[nt][1]));
            rmax1 = fmaxf(rmax1, fmaxf(s[nt][2], s[nt][3]));
        }
        rmax0 = fmaxf(rmax0, __shfl_xor_sync(0xffffffffu, rmax0, 1));
        rmax0 = fmaxf(rmax0, __shfl_xor_sync(0xffffffffu, rmax0, 2));
        rmax1 = fmaxf(rmax1, __shfl_xor_sync(0xffffffffu, rmax1, 1));
        rmax1 = fmaxf(rmax1, __shfl_xor_sync(0xffffffffu, rmax1, 2));

        float mn0 = fmaxf(m0, rmax0), mn1 = fmaxf(m1, rmax1);
        float cor0 = __expf(m0 - mn0), cor1 = __expf(m1 - mn1);
        m0 = mn0; m1 = mn1;

        float ps0 = 0.f, ps1 = 0.f;
        #pragma unroll
        for (int nt = 0; nt < 8; nt++) {
            float p0 = __expf(s[nt][0] - mn0);
            float p1 = __expf(s[nt][1] - mn0);
            float p2 = __expf(s[nt][2] - mn1);
            float p3 = __expf(s[nt][3] - mn1);
            ps0 += p0 + p1; ps1 += p2 + p3;
            int c = nt * 8 + 2 * tig;
            Ss[r0    ][c] = __float_as_uint(p0); Ss[r0    ][c + 1] = __float_as_uint(p1);
            Ss[r0 + 8][c] = __float_as_uint(p2); Ss[r0 + 8][c + 1] = __float_as_uint(p3);
        }
        ps0 += __shfl_xor_sync(0xffffffffu, ps0, 1);
        ps0 += __shfl_xor_sync(0xffffffffu, ps0, 2);
        ps1 += __shfl_xor_sync(0xffffffffu, ps1, 1);
        ps1 += __shfl_xor_sync(0xffffffffu, ps1, 2);
        l0 = l0 * cor0 + ps0;
        l1 = l1 * cor1 + ps1;
        #pragma unroll
        for (int nt = 0; nt < 4; nt++) {
            o[nt][0] *= cor0; o[nt][1] *= cor0;
            o[nt][2] *= cor1; o[nt][3] *= cor1;
        }
        __syncwarp();

        #pragma unroll
        for (int ks = 0; ks < 8; ks++) {
            unsigned a0 = Ss[r0    ][ks * 8 + tig];
            unsigned a1 = Ss[r0 + 8][ks * 8 + tig];
            unsigned a2 = Ss[r0    ][ks * 8 + tig + 4];
            unsigned a3 = Ss[r0 + 8][ks * 8 + tig + 4];
            #pragma unroll
            for (int nt = 0; nt < 4; nt++) {
                unsigned b0 = __float_as_uint(Vc[ks * 8 + tig    ][nt * 8 + g]);
                unsigned b1 = __float_as_uint(Vc[ks * 8 + tig + 4][nt * 8 + g]);
                MMA_TF32(o[nt][0], o[nt][1], o[nt][2], o[nt][3],
                         a0, a1, a2, a3, b0, b1);
            }
        }
        __syncthreads();
    }

    const float inv0 = 1.0f / l0, inv1 = 1.0f / l1;
    const int row0 = b * 1024 + qt * 128 + w * 16 + g;
    #pragma unroll
    for (int nt = 0; nt < 4; nt++) {
        const int col = nh * 32 + nt * 8 + 2 * tig;
        size_t i0 = (size_t)row0 * HDIM + col;
        size_t i1 = (size_t)(row0 + 8) * HDIM + col;
        out[i0]     = o[nt][0] * inv0;
        out[i0 + 1] = o[nt][1] * inv0;
        out[i1]     = o[nt][2] * inv1;
        out[i1 + 1] = o[nt][3] * inv1;
    }
}

// ---------------- head final ------------------------------------------------
__global__ void head_final_kernel(const float* __restrict__ t, const float* __restrict__ w,
                                  const float* __restrict__ b, float* __restrict__ out) {
    int row = blockIdx.x * 8 + (threadIdx.x >> 5);
    int lane = threadIdx.x & 31;
    float acc = 0.f;
    #pragma unroll
    for (int i = lane; i < 128; i += 32)
        acc += t[(size_t)row * 128 + i] * w[i];
    #pragma unroll
    for (int ofs = 16; ofs; ofs >>= 1)
        acc += __shfl_xor_sync(0xffffffffu, acc, ofs);
    if (lane == 0)
        out[row] = 1.0f / (1.0f + expf(-(acc + b[0])));
}

// ---------------- host orchestration ----------------------------------------
extern "C" void kernel_launch(void* const* d_in, const int* in_sizes, int n_in,
                              void* d_out, int out_size) {
    const float* x        = (const float*)d_in[0];
    const int*   erow     = (const int*)  d_in[1];
    const int*   ecol     = (const int*)  d_in[2];
    const float* eval     = (const float*)d_in[3];
    const float* pe       = (const float*)d_in[4];
    const float* W_in     = (const float*)d_in[5];
    const float* b_in     = (const float*)d_in[6];
    const float* W_pe     = (const float*)d_in[7];
    const float* b_pe     = (const float*)d_in[8];
    const float* gcn_W    = (const float*)d_in[9];
    const float* ain_W    = (const float*)d_in[10];
    const float* ain_b    = (const float*)d_in[11];
    const float* aout_W   = (const float*)d_in[12];
    const float* aout_b   = (const float*)d_in[13];
    const float* bn_g     = (const float*)d_in[14];
    const float* bn_b     = (const float*)d_in[15];
    const float* ffn_W1   = (const float*)d_in[16];
    const float* ffn_b1   = (const float*)d_in[17];
    const float* ffn_W2   = (const float*)d_in[18];
    const float* ffn_b2   = (const float*)d_in[19];
    const float* head_W1  = (const float*)d_in[20];
    const float* head_b1  = (const float*)d_in[21];
    const float* head_W2  = (const float*)d_in[22];
    const float* head_b2  = (const float*)d_in[23];

    float *h, *t1, *t2, *psum, *psq;
    int *cnt, *off, *cur, *eidx;
    cudaGetSymbolAddress((void**)&h,    g_h);
    cudaGetSymbolAddress((void**)&t1,   g_t1);
    cudaGetSymbolAddress((void**)&t2,   g_t2);
    cudaGetSymbolAddress((void**)&psum, g_psum);
    cudaGetSymbolAddress((void**)&psq,  g_psq);
    cudaGetSymbolAddress((void**)&cnt,  g_cnt);
    cudaGetSymbolAddress((void**)&off,  g_off);
    cudaGetSymbolAddress((void**)&cur,  g_cur);
    cudaGetSymbolAddress((void**)&eidx, g_eidx);

    cudaFuncSetAttribute(attn_tc_kernel,
                         cudaFuncAttributeMaxDynamicSharedMemorySize, ATTN_SMEM);
    cudaFuncSetAttribute(gemm_tc_kernel<64, 0, false, false>,
                         cudaFuncAttributeMaxDynamicSharedMemorySize, GEMM_SMEM_64);
    cudaFuncSetAttribute(gemm_tc_kernel<64, 0, true, false>,
                         cudaFuncAttributeMaxDynamicSharedMemorySize, GEMM_SMEM_64);
    cudaFuncSetAttribute(gemm_tc_kernel<64, 0, true, true>,
                         cudaFuncAttributeMaxDynamicSharedMemorySize, GEMM_SMEM_64);
    cudaFuncSetAttribute(gemm_tc_kernel<64, 1, false, false>,
                         cudaFuncAttributeMaxDynamicSharedMemorySize, GEMM_SMEM_64);
    cudaFuncSetAttribute(gemm_tc_kernel<128, 0, false, false>,
                         cudaFuncAttributeMaxDynamicSharedMemorySize, GEMM_SMEM_128);
    cudaFuncSetAttribute(gemm_tc_kernel<128, 1, false, false>,
                         cudaFuncAttributeMaxDynamicSharedMemorySize, GEMM_SMEM_128);

    cudaMemsetAsync(cnt, 0, BNODES * sizeof(int));
    count_deg_kernel<<<NEDGE / 256, 256>>>(erow, cnt);
    scan_kernel<<<1, 256>>>(cnt, off, cur);
    fill_csr_kernel<<<NEDGE / 256, 256>>>(erow, cur, eidx);

    const dim3 g256 (2, BNODES / 64);    // TM=64,  N=256
    const dim3 g768 (6, BNODES / 128);   // TM=128, N=768
    const dim3 g1024(8, BNODES / 128);   // TM=128, N=1024
    const dim3 g128 (1, BNODES / 64);    // TM=64,  N=128

    gemm_tc_kernel<64, 0, false, false><<<g256, 256, GEMM_SMEM_64>>>(
        x,  W_in, b_in, h, 128, HDIM);
    gemm_tc_kernel<64, 0, true, false><<<g256, 256, GEMM_SMEM_64>>>(
        pe, W_pe, b_pe, h, 8, HDIM);

    for (int l = 0; l < NLAYER; l++) {
        // ---- local GCN ----
        gemm_tc_kernel<64, 0, false, false><<<g256, 256, GEMM_SMEM_64>>>(
            h, gcn_W + (size_t)l * HDIM * HDIM, nullptr, t1, HDIM, HDIM);
        gcn_gather_kernel<<<BNODES, 256>>>(t1, off, eidx, ecol, eval, t2);
        bnpre_kernel<<<256, 256>>>(h, t2, psum, psq);
        bnapply_kernel<<<128, 256>>>(h, psum, psq,
                                     bn_g + l * 3 * HDIM, bn_b + l * 3 * HDIM, 256);
        // ---- global attention ----
        gemm_tc_kernel<128, 0, false, false><<<g768, 256, GEMM_SMEM_128>>>(
            h, ain_W + (size_t)l * 768 * HDIM, ain_b + l * 768, t1, HDIM, 768);
        attn_tc_kernel<<<dim3(8, 8, 8), 256, ATTN_SMEM>>>(t1, t2);
        gemm_tc_kernel<64, 0, true, true><<<g256, 256, GEMM_SMEM_64>>>(
            t2, aout_W + (size_t)l * HDIM * HDIM, aout_b + l * HDIM, h, HDIM, HDIM);
        bnapply_kernel<<<128, 256>>>(h, psum, psq,
                                     bn_g + l * 3 * HDIM + HDIM,
                                     bn_b + l * 3 * HDIM + HDIM, 128);
        // ---- FFN ----
        gemm_tc_kernel<128, 1, false, false><<<g1024, 256, GEMM_SMEM_128>>>(
            h, ffn_W1 + (size_t)l * 1024 * HDIM, ffn_b1 + l * 1024, t1, HDIM, 1024);
        gemm_tc_kernel<64, 0, true, true><<<g256, 256, GEMM_SMEM_64>>>(
            t1, ffn_W2 + (size_t)l * HDIM * 1024, ffn_b2 + l * HDIM, h, 1024, HDIM);
        bnapply_kernel<<<128, 256>>>(h, psum, psq,
                                     bn_g + l * 3 * HDIM + 2 * HDIM,
                                     bn_b + l * 3 * HDIM + 2 * HDIM, 128);
    }

    gemm_tc_kernel<64, 1, false, false><<<g128, 256, GEMM_SMEM_64>>>(
        h, head_W1, head_b1, t1, HDIM, 128);
    head_final_kernel<<<BNODES / 8, 256>>>(t1, head_W2, head_b2, (float*)d_out);
}

// round 8
// speedup vs baseline: 3.2273x; 1.2754x over previous
#include <cuda_runtime.h>
#include <cuda_fp16.h>
#include <math.h>

#define BNODES 8192
#define HDIM   256
#define NEDGE  131072
#define NLAYER 4

// fp32 scratch
__device__ float g_h [BNODES * HDIM];
__device__ float g_t1[BNODES * HDIM];        // head intermediate (fp32)
__device__ float g_t2[BNODES * HDIM];        // gather out (fp32)
__device__ int   g_cnt[BNODES];
__device__ int   g_off[BNODES + 1];
__device__ int   g_cur[BNODES];
__device__ int   g_eidx[NEDGE];
__device__ float g_psum[256 * HDIM];
__device__ float g_psq [256 * HDIM];
// fp16 scratch
__device__ __half g_w16[3475456];            // converted weights
__device__ __half g_x16[BNODES * 128];
__device__ __half g_pe16[BNODES * 8];
__device__ __half g_h16[BNODES * HDIM];
__device__ __half g_t1h[BNODES * 1024];      // qkv / ffn1 / gcn-lin outputs
__device__ __half g_t2h[BNODES * HDIM];      // attention out

// weight offsets in g_w16
#define OFF_WIN  0
#define OFF_WPE  32768
#define OFF_GCN  34816
#define OFF_AIN  296960
#define OFF_AOUT 1083392
#define OFF_FFN1 1345536
#define OFF_FFN2 2394112
#define OFF_HW1  3442688

__device__ __forceinline__ float gelu_f(float x) {
    return 0.5f * x * (1.0f + erff(x * 0.70710678118654752f));
}

__device__ __forceinline__ void cp_async16(void* smem_dst, const void* gmem_src) {
    unsigned s = (unsigned)__cvta_generic_to_shared(smem_dst);
    asm volatile("cp.async.cg.shared.global [%0], [%1], 16;\n" :: "r"(s), "l"(gmem_src));
}
#define CP_COMMIT() asm volatile("cp.async.commit_group;\n" ::: "memory")
#define CP_WAIT1()  asm volatile("cp.async.wait_group 1;\n" ::: "memory")
#define CP_WAIT0()  asm volatile("cp.async.wait_group 0;\n" ::: "memory")

#define MMA_F16(c0,c1,c2,c3, a0,a1,a2,a3, b0,b1)                           \
    asm volatile(                                                          \
        "mma.sync.aligned.m16n8k16.row.col.f32.f16.f16.f32 "               \
        "{%0,%1,%2,%3}, {%4,%5,%6,%7}, {%8,%9}, {%0,%1,%2,%3};\n"          \
        : "+f"(c0), "+f"(c1), "+f"(c2), "+f"(c3)                            \
        : "r"(a0), "r"(a1), "r"(a2), "r"(a3), "r"(b0), "r"(b1))

#define LDSM4(r0,r1,r2,r3, addr)                                            \
    asm volatile("ldmatrix.sync.aligned.m8n8.x4.shared.b16 {%0,%1,%2,%3}, [%4];" \
        : "=r"(r0), "=r"(r1), "=r"(r2), "=r"(r3) : "r"(addr))

#define LDSM4T(r0,r1,r2,r3, addr)                                           \
    asm volatile("ldmatrix.sync.aligned.m8n8.x4.trans.shared.b16 {%0,%1,%2,%3}, [%4];" \
        : "=r"(r0), "=r"(r1), "=r"(r2), "=r"(r3) : "r"(addr))

// ---------------- fp32 -> fp16 convert (n divisible by 4) ------------------
__global__ void f2h_kernel(const float* __restrict__ src, __half* __restrict__ dst,
                           int n4) {
    int i = blockIdx.x * 256 + threadIdx.x;
    if (i < n4) {
        float4 v = ((const float4*)src)[i];
        ((__half2*)dst)[2*i]   = __floats2half2_rn(v.x, v.y);
        ((__half2*)dst)[2*i+1] = __floats2half2_rn(v.z, v.w);
    }
}

// ---------------- fp16 GEMM (3-stage cp.async + ldmatrix + m16n8k16) -------
// Block tile TM x 128, 8 warps (2x4), warp tile (TM/2) x 32, BK=32.
// Smem row stride 56 halves (112B): cp.async 16B aligned, ldmatrix conflict-free.
// OM: 0 = fp32 C; 1 = fp32 C + fp16 copy; 2 = fp16 C only.
template<int TM>
__device__ __forceinline__ void load_tile_h(
    const __half* __restrict__ A, const __half* __restrict__ W,
    __half (*As)[56], __half (*Bs)[56],
    int bm, int bn, int K, int k0, int tid) {
    #pragma unroll
    for (int i = 0; i < TM / 64; i++) {
        int idx = tid + i * 256;
        int r = idx >> 2, qd = idx & 3;
        const __half* src = A + (size_t)(bm + r) * K + k0 + qd * 8;
        __half* dst = &As[r][qd * 8];
        if (k0 + qd * 8 + 8 <= K) {
            cp_async16(dst, src);
        } else {
            #pragma unroll
            for (int j = 0; j < 8; j++)
                dst[j] = (k0 + qd * 8 + j < K) ? src[j] : __float2half(0.f);
        }
    }
    #pragma unroll
    for (int i = 0; i < 2; i++) {
        int idx = tid + i * 256;
        int r = idx >> 2, qd = idx & 3;
        const __half* src = W + (size_t)(bn + r) * K + k0 + qd * 8;
        __half* dst = &Bs[r][qd * 8];
        if (k0 + qd * 8 + 8 <= K) {
            cp_async16(dst, src);
        } else {
            #pragma unroll
            for (int j = 0; j < 8; j++)
                dst[j] = (k0 + qd * 8 + j < K) ? src[j] : __float2half(0.f);
        }
    }
    CP_COMMIT();
}

template<int TM, int ACT, bool ACCUM, bool STATS, int OM>
__global__ __launch_bounds__(256, 2)
void gemm_h_kernel(const __half* __restrict__ A, const __half* __restrict__ W,
                   const float* __restrict__ bias, float* __restrict__ C,
                   __half* __restrict__ C16, int K, int N) {
    constexpr int MT = TM / 32;
    constexpr int RED_OFF = 3 * TM * 56 + 3 * 128 * 56;   // halves
    extern __shared__ __half hsm[];
    __half (*As)[56] = (__half(*)[56])hsm;
    __half (*Bs)[56] = (__half(*)[56])(hsm + 3 * TM * 56);

    const int bm = blockIdx.y * TM, bn = blockIdx.x * 128;
    const int tid  = threadIdx.x;
    const int lane = tid & 31;
    const int wid  = tid >> 5;
    const int wm   = wid >> 2;
    const int wn   = wid & 3;
    const int g    = lane >> 2;
    const int tig  = lane & 3;

    const unsigned aBase0 = (unsigned)__cvta_generic_to_shared(&As[0][0]);
    const unsigned bBase0 = aBase0 + 3 * TM * 56 * 2;
    const unsigned aLane = (unsigned)(wm * (TM / 2) + (lane & 15)) * 112
                         + ((lane >> 4) << 4);
    const unsigned bLane = (unsigned)(wn * 32 + ((lane >> 4) << 3) + (lane & 7)) * 112
                         + (((lane >> 3) & 1) << 4);

    float acc[MT][4][4] = {};

    const int KT = (K + 31) >> 5;
    load_tile_h<TM>(A, W, As, Bs, bm, bn, K, 0, tid);
    if (KT > 1)
        load_tile_h<TM>(A, W, As + TM, Bs + 128, bm, bn, K, 32, tid);

    for (int it = 0; it < KT; it++) {
        if (it + 1 < KT) CP_WAIT1(); else CP_WAIT0();
        __syncthreads();
        if (it + 2 < KT) {
            const int nb = (it + 2) % 3;
            load_tile_h<TM>(A, W, As + nb * TM, Bs + nb * 128,
                            bm, bn, K, (it + 2) * 32, tid);
        }

        const unsigned aB = aBase0 + (unsigned)((it % 3) * TM) * 112 + aLane;
        const unsigned bB = bBase0 + (unsigned)((it % 3) * 128) * 112 + bLane;

        #pragma unroll
        for (int ks = 0; ks < 2; ks++) {       // two k16 per 32-slab
            unsigned a[MT][4], b[4][2];
            #pragma unroll
            for (int mt = 0; mt < MT; mt++)
                LDSM4(a[mt][0], a[mt][1], a[mt][2], a[mt][3],
                      aB + mt * (16 * 112) + ks * 32);
            LDSM4(b[0][0], b[0][1], b[1][0], b[1][1], bB + ks * 32);
            LDSM4(b[2][0], b[2][1], b[3][0], b[3][1], bB + 16 * 112 + ks * 32);
            #pragma unroll
            for (int mt = 0; mt < MT; mt++)
                #pragma unroll
                for (int nt = 0; nt < 4; nt++)
                    MMA_F16(acc[mt][nt][0], acc[mt][nt][1],
                            acc[mt][nt][2], acc[mt][nt][3],
                            a[mt][0], a[mt][1], a[mt][2], a[mt][3],
                            b[nt][0], b[nt][1]);
        }
        __syncthreads();
    }

    float cs[4][2], cq[4][2];
    if (STATS) {
        #pragma unroll
        for (int nt = 0; nt < 4; nt++)
            cs[nt][0] = cs[nt][1] = cq[nt][0] = cq[nt][1] = 0.f;
    }

    #pragma unroll
    for (int mt = 0; mt < MT; mt++) {
        const int row = bm + wm * (TM / 2) + mt * 16 + g;
        #pragma unroll
        for (int nt = 0; nt < 4; nt++) {
            const int col = bn + wn * 32 + nt * 8 + 2 * tig;
            float b0 = 0.f, b1 = 0.f;
            if (bias) { b0 = bias[col]; b1 = bias[col + 1]; }
            #pragma unroll
            for (int half_ = 0; half_ < 2; half_++) {
                const int r = row + half_ * 8;
                size_t idx = (size_t)r * N + col;
                float c0 = acc[mt][nt][half_ * 2 + 0] + b0;
                float c1 = acc[mt][nt][half_ * 2 + 1] + b1;
                if (ACCUM) { c0 += C[idx]; c1 += C[idx + 1]; }
                if (ACT == 1) { c0 = gelu_f(c0); c1 = gelu_f(c1); }
                if (OM != 2) { C[idx] = c0; C[idx + 1] = c1; }
                if (OM >= 1) *(\
                    __half2*)(C16 + idx) = __floats2half2_rn(c0, c1);
                if (STATS) {
                    cs[nt][0] += c0; cq[nt][0] += c0 * c0;
                    cs[nt][1] += c1; cq[nt][1] += c1 * c1;
                }
            }
        }
    }

    if (STATS) {
        float* sred = (float*)(hsm + RED_OFF);
        #pragma unroll
        for (int nt = 0; nt < 4; nt++)
            #pragma unroll
            for (int j = 0; j < 2; j++) {
                #pragma unroll
                for (int m = 4; m <= 16; m <<= 1) {
                    cs[nt][j] += __shfl_xor_sync(0xffffffffu, cs[nt][j], m);
                    cq[nt][j] += __shfl_xor_sync(0xffffffffu, cq[nt][j], m);
                }
            }
        if (g == 0) {
            #pragma unroll
            for (int nt = 0; nt < 4; nt++)
                #pragma unroll
                for (int j = 0; j < 2; j++) {
                    int c = wn * 32 + nt * 8 + 2 * tig + j;
                    sred[wm * 128 + c]       = cs[nt][j];
                    sred[256 + wm * 128 + c] = cq[nt][j];
                }
        }
        __syncthreads();
        if (tid < 128) {
            int c = tid;
            g_psum[blockIdx.y * HDIM + bn + c] = sred[c] + sred[128 + c];
            g_psq [blockIdx.y * HDIM + bn + c] = sred[256 + c] + sred[384 + c];
        }
    }
}

#define GEMM_SMEM_64  ((3 * 64 * 56 + 3 * 128 * 56) * 2 + 512 * 4)
#define GEMM_SMEM_128 ((3 * 128 * 56 + 3 * 128 * 56) * 2)

// ---------------- CSR build -------------------------------------------------
__global__ void count_deg_kernel(const int* __restrict__ row, int* __restrict__ cnt) {
    int e = blockIdx.x * 256 + threadIdx.x;
    if (e < NEDGE) atomicAdd(&cnt[row[e]], 1);
}

__global__ void scan_kernel(const int* __restrict__ cnt, int* __restrict__ off,
                            int* __restrict__ cur) {
    __shared__ int part[256];
    const int t = threadIdx.x;
    int loc[32];
    int s = 0;
    #pragma unroll
    for (int i = 0; i < 32; i++) { loc[i] = s; s += cnt[t * 32 + i]; }
    part[t] = s;
    __syncthreads();
    for (int ofs = 1; ofs < 256; ofs <<= 1) {
        int mine = part[t];
        int add = (t >= ofs) ? part[t - ofs] : 0;
        __syncthreads();
        part[t] = mine + add;
        __syncthreads();
    }
    int excl = (t > 0) ? part[t - 1] : 0;
    #pragma unroll
    for (int i = 0; i < 32; i++) {
        int v = excl + loc[i];
        off[t * 32 + i] = v;
        cur[t * 32 + i] = v;
    }
    if (t == 255) off[BNODES] = part[255];
}

__global__ void fill_csr_kernel(const int* __restrict__ row, int* __restrict__ cur,
                                int* __restrict__ eidx) {
    int e = blockIdx.x * 256 + threadIdx.x;
    if (e < NEDGE) {
        int p = atomicAdd(&cur[row[e]], 1);
        eidx[p] = e;
    }
}

// ---------------- GCN gather (fp16 features) --------------------------------
__global__ void gcn_gather_kernel(const __half* __restrict__ t1h,
                                  const int* __restrict__ off,
                                  const int* __restrict__ eidx,
                                  const int* __restrict__ ecol,
                                  const float* __restrict__ eval,
                                  float* __restrict__ agg) {
    const int node = blockIdx.x;
    const int f = threadIdx.x;
    __shared__ int   scol[64];
    __shared__ float sval[64];
    const int s = off[node], e_end = off[node + 1];
    float acc = 0.f;
    for (int base = s; base < e_end; base += 64) {
        int n = min(64, e_end - base);
        if (f < n) {
            int e = eidx[base + f];
            scol[f] = ecol[e];
            sval[f] = eval[e];
        }
        __syncthreads();
        for (int j = 0; j < n; j++)
            acc += sval[j] * __half2float(t1h[(size_t)scol[j] * HDIM + f]);
        __syncthreads();
    }
    agg[(size_t)node * HDIM + f] = acc;
}

// ---------------- BatchNorm -------------------------------------------------
__global__ void bnpre_kernel(float* __restrict__ h, const float* __restrict__ add,
                             float* __restrict__ psum, float* __restrict__ psq) {
    const int f = threadIdx.x;
    const int blk = blockIdx.x;
    float s = 0.f, sq = 0.f;
    size_t base = (size_t)blk * 32 * HDIM + f;
    #pragma unroll 4
    for (int r = 0; r < 32; r++) {
        size_t idx = base + (size_t)r * HDIM;
        float v = h[idx] + gelu_f(add[idx]);
        h[idx] = v;
        s += v;
        sq += v * v;
    }
    psum[blk * HDIM + f] = s;
    psq [blk * HDIM + f] = sq;
}

__global__ void bnapply_kernel(float* __restrict__ h, __half* __restrict__ h16,
                               const float* __restrict__ psum,
                               const float* __restrict__ psq,
                               const float* __restrict__ g,
                               const float* __restrict__ b, int npart) {
    const int f = threadIdx.x;
    float s = 0.f, sq = 0.f;
    for (int p = 0; p < npart; p++) { s += psum[p * HDIM + f]; sq += psq[p * HDIM + f]; }
    const float mu  = s * (1.0f / BNODES);
    const float is_ = rsqrtf(sq * (1.0f / BNODES) - mu * mu + 1e-5f);
    const float gg = g[f], bb = b[f];
    size_t base = (size_t)blockIdx.x * 64 * HDIM + f;
    #pragma unroll 4
    for (int r = 0; r < 64; r++) {
        size_t i = base + (size_t)r * HDIM;
        float v = (h[i] - mu) * is_ * gg + bb;
        h[i] = v;
        h16[i] = __float2half(v);
    }
}

// ---------------- fp16 flash attention (m16n8k16) ---------------------------
// grid (8 q-tiles, 8 heads, 8 graphs), 256 threads (8 warps).
#define ATTN_SMEM ((2 * 64 * 56 + 2 * 64 * 56 + 128 * 72) * 2)

__global__ __launch_bounds__(256)
void attn_h_kernel(const __half* __restrict__ qkv, __half* __restrict__ out) {
    extern __shared__ __half hsm[];
    __half (*Kh)[64][56] = (__half(*)[64][56])hsm;
    __half (*Vh)[64][56] = (__half(*)[64][56])(hsm + 2 * 64 * 56);
    __half (*Sh)[72]     = (__half(*)[72])(hsm + 4 * 64 * 56);
    __half* Qs = (__half*)Sh;   // Q staging, stride 56 (region reused for P)

    const int qt = blockIdx.x, nh = blockIdx.y, b = blockIdx.z;
    const int tid  = threadIdx.x;
    const int lane = tid & 31;
    const int w    = tid >> 5;
    const int g    = lane >> 2;
    const int tig  = lane & 3;
    const float scale = 0.17677669529663687f;

    const size_t rowb = (size_t)(b * 1024) * 768 + nh * 32;

    // stage Q (group 1)
    {
        size_t qoff = rowb + (size_t)(qt * 128) * 768;
        #pragma unroll
        for (int i = 0; i < 2; i++) {
            int idx = tid + i * 256;
            int r = idx >> 2, qd = idx & 3;
            cp_async16(Qs + r * 56 + qd * 8, qkv + qoff + (size_t)r * 768 + qd * 8);
        }
        CP_COMMIT();
    }
    // prefetch KV tile 0 (group 2)
    {
        int r = tid >> 2, qd = tid & 3;
        cp_async16(&Kh[0][r][qd * 8], qkv + rowb + (size_t)r * 768 + 256 + qd * 8);
        cp_async16(&Vh[0][r][qd * 8], qkv + rowb + (size_t)r * 768 + 512 + qd * 8);
        CP_COMMIT();
    }
    CP_WAIT1();
    __syncthreads();

    unsigned q[2][4];
    {
        unsigned qA = (unsigned)__cvta_generic_to_shared(Qs)
                    + (unsigned)(w * 16 + (lane & 15)) * 112 + ((lane >> 4) << 4);
        LDSM4(q[0][0], q[0][1], q[0][2], q[0][3], qA);
        LDSM4(q[1][0], q[1][1], q[1][2], q[1][3], qA + 32);
    }
    __syncthreads();

    const unsigned kLane = (unsigned)(((lane >> 4) << 3) + (lane & 7)) * 112
                         + (((lane >> 3) & 1) << 4);
    const unsigned pLane = (unsigned)(w * 16 + (lane & 15)) * 144 + ((lane >> 4) << 4);
    const unsigned vLane = (unsigned)((((lane >> 3) & 1) << 3) + (lane & 7)) * 112
                         + ((lane >> 4) << 4);
    const unsigned pBase = (unsigned)__cvta_generic_to_shared(&Sh[0][0]) + pLane;
    const int r0 = w * 16 + g;

    float m0 = -1e30f, m1 = -1e30f, l0 = 0.f, l1 = 0.f;
    float o[4][4] = {};

    for (int kt = 0; kt < 16; kt++) {
        if (kt + 1 < 16) {
            size_t koff = rowb + (size_t)((kt + 1) * 64) * 768;
            int st = (kt + 1) & 1;
            int r = tid >> 2, qd = tid & 3;
            cp_async16(&Kh[st][r][qd * 8], qkv + koff + (size_t)r * 768 + 256 + qd * 8);
            cp_async16(&Vh[st][r][qd * 8], qkv + koff + (size_t)r * 768 + 512 + qd * 8);
            CP_COMMIT();
            CP_WAIT1();
        } else {
            CP_WAIT0();
        }
        __syncthreads();

        const unsigned kBase = (unsigned)__cvta_generic_to_shared(&Kh[kt & 1][0][0]) + kLane;
        const unsigned vBase = (unsigned)__cvta_generic_to_shared(&Vh[kt & 1][0][0]) + vLane;

        // S = Q @ K^T  (per warp 16 x 64)
        float s[8][4] = {};
        #pragma unroll
        for (int ks = 0; ks < 2; ks++) {
            #pragma unroll
            for (int grp = 0; grp < 4; grp++) {
                unsigned b0, b1, b2, b3;
                LDSM4(b0, b1, b2, b3, kBase + grp * (16 * 112) + ks * 32);
                MMA_F16(s[grp*2  ][0], s[grp*2  ][1], s[grp*2  ][2], s[grp*2  ][3],
                        q[ks][0], q[ks][1], q[ks][2], q[ks][3], b0, b1);
                MMA_F16(s[grp*2+1][0], s[grp*2+1][1], s[grp*2+1][2], s[grp*2+1][3],
                        q[ks][0], q[ks][1], q[ks][2], q[ks][3], b2, b3);
            }
        }

        // online softmax (rows r0, r0+8)
        float rmax0 = -1e30f, rmax1 = -1e30f;
        #pragma unroll
        for (int nt = 0; nt < 8; nt++) {
            s[nt][0] *= scale; s[nt][1] *= scale;
            s[nt][2] *= scale; s[nt][3] *= scale;
            rmax0 = fmaxf(rmax0, fmaxf(s[nt][0], s[nt][1]));
            rmax1 = fmaxf(rmax1, fmaxf(s[nt][2], s[nt][3]));
        }
        rmax0 = fmaxf(rmax0, __shfl_xor_sync(0xffffffffu, rmax0, 1));
        rmax0 = fmaxf(rmax0, __shfl_xor_sync(0xffffffffu, rmax0, 2));
        rmax1 = fmaxf(rmax1, __shfl_xor_sync(0xffffffffu, rmax1, 1));
        rmax1 = fmaxf(rmax1, __shfl_xor_sync(0xffffffffu, rmax1, 2));

        float mn0 = fmaxf(m0, rmax0), mn1 = fmaxf(m1, rmax1);
        float cor0 = __expf(m0 - mn0), cor1 = __expf(m1 - mn1);
        m0 = mn0; m1 = mn1;

        float ps0 = 0.f, ps1 = 0.f;
        #pragma unroll
        for (int nt = 0; nt < 8; nt++) {
            float p0 = __expf(s[nt][0] - mn0);
            float p1 = __expf(s[nt][1] - mn0);
            float p2 = __expf(s[nt][2] - mn1);
            float p3 = __expf(s[nt][3] - mn1);
            ps0 += p0 + p1; ps1 += p2 + p3;
            int c = nt * 8 + 2 * tig;
            *(__half2*)&Sh[r0    ][c] = __floats2half2_rn(p0, p1);
            *(__half2*)&Sh[r0 + 8][c] = __floats2half2_rn(p2, p3);
        }
        ps0 += __shfl_xor_sync(0xffffffffu, ps0, 1);
        ps0 += __shfl_xor_sync(0xffffffffu, ps0, 2);
        ps1 += __shfl_xor_sync(0xffffffffu, ps1, 1);
        ps1 += __shfl_xor_sync(0xffffffffu, ps1, 2);
        l0 = l0 * cor0 + ps0;
        l1 = l1 * cor1 + ps1;
        #pragma unroll
        for (int nt = 0; nt < 4; nt++) {
            o[nt][0] *= cor0; o[nt][1] *= cor0;
            o[nt][2] *= cor1; o[nt][3] *= cor1;
        }
        __syncwarp();

        // O += P @ V  (per warp 16 x 32)
        #pragma unroll
        for (int ks = 0; ks < 4; ks++) {
            unsigned a0, a1, a2, a3;
            LDSM4(a0, a1, a2, a3, pBase + ks * 32);
            #pragma unroll
            for (int dg = 0; dg < 2; dg++) {
                unsigned v0, v1, v2, v3;
                LDSM4T(v0, v1, v2, v3, vBase + ks * (16 * 112) + dg * 32);
                MMA_F16(o[dg*2  ][0], o[dg*2  ][1], o[dg*2  ][2], o[dg*2  ][3],
                        a0, a1, a2, a3, v0, v1);
                MMA_F16(o[dg*2+1][0], o[dg*2+1][1], o[dg*2+1][2], o[dg*2+1][3],
                        a0, a1, a2, a3, v2, v3);
            }
        }
        __syncthreads();
    }

    const float inv0 = 1.0f / l0, inv1 = 1.0f / l1;
    const int row0 = b * 1024 + qt * 128 + w * 16 + g;
    #pragma unroll
    for (int nt = 0; nt < 4; nt++) {
        const int col = nh * 32 + nt * 8 + 2 * tig;
        size_t i0 = (size_t)row0 * HDIM + col;
        size_t i1 = (size_t)(row0 + 8) * HDIM + col;
        *(__half2*)(out + i0) = __floats2half2_rn(o[nt][0] * inv0, o[nt][1] * inv0);
        *(__half2*)(out + i1) = __floats2half2_rn(o[nt][2] * inv1, o[nt][3] * inv1);
    }
}

// ---------------- head final ------------------------------------------------
__global__ void head_final_kernel(const float* __restrict__ t, const float* __restrict__ w,
                                  const float* __restrict__ b, float* __restrict__ out) {
    int row = blockIdx.x * 8 + (threadIdx.x >> 5);
    int lane = threadIdx.x & 31;
    float acc = 0.f;
    #pragma unroll
    for (int i = lane; i < 128; i += 32)
        acc += t[(size_t)row * 128 + i] * w[i];
    #pragma unroll
    for (int ofs = 16; ofs; ofs >>= 1)
        acc += __shfl_xor_sync(0xffffffffu, acc, ofs);
    if (lane == 0)
        out[row] = 1.0f / (1.0f + expf(-(acc + b[0])));
}

// ---------------- host orchestration ----------------------------------------
static inline void conv(const float* src, __half* dst, int n) {
    f2h_kernel<<<(n / 4 + 255) / 256, 256>>>(src, dst, n / 4);
}

extern "C" void kernel_launch(void* const* d_in, const int* in_sizes, int n_in,
                              void* d_out, int out_size) {
    const float* x        = (const float*)d_in[0];
    const int*   erow     = (const int*)  d_in[1];
    const int*   ecol     = (const int*)  d_in[2];
    const float* eval     = (const float*)d_in[3];
    const float* pe       = (const float*)d_in[4];
    const float* W_in     = (const float*)d_in[5];
    const float* b_in     = (const float*)d_in[6];
    const float* W_pe     = (const float*)d_in[7];
    const float* b_pe     = (const float*)d_in[8];
    const float* gcn_W    = (const float*)d_in[9];
    const float* ain_W    = (const float*)d_in[10];
    const float* ain_b    = (const float*)d_in[11];
    const float* aout_W   = (const float*)d_in[12];
    const float* aout_b   = (const float*)d_in[13];
    const float* bn_g     = (const float*)d_in[14];
    const float* bn_b     = (const float*)d_in[15];
    const float* ffn_W1   = (const float*)d_in[16];
    const float* ffn_b1   = (const float*)d_in[17];
    const float* ffn_W2   = (const float*)d_in[18];
    const float* ffn_b2   = (const float*)d_in[19];
    const float* head_W1  = (const float*)d_in[20];
    const float* head_b1  = (const float*)d_in[21];
    const float* head_W2  = (const float*)d_in[22];
    const float* head_b2  = (const float*)d_in[23];

    float *h, *t1, *t2, *psum, *psq;
    __half *w16, *x16, *pe16, *h16, *t1h, *t2h;
    int *cnt, *off, *cur, *eidx;
    cudaGetSymbolAddress((void**)&h,    g_h);
    cudaGetSymbolAddress((void**)&t1,   g_t1);
    cudaGetSymbolAddress((void**)&t2,   g_t2);
    cudaGetSymbolAddress((void**)&psum, g_psum);
    cudaGetSymbolAddress((void**)&psq,  g_psq);
    cudaGetSymbolAddress((void**)&cnt,  g_cnt);
    cudaGetSymbolAddress((void**)&off,  g_off);
    cudaGetSymbolAddress((void**)&cur,  g_cur);
    cudaGetSymbolAddress((void**)&eidx, g_eidx);
    cudaGetSymbolAddress((void**)&w16,  g_w16);
    cudaGetSymbolAddress((void**)&x16,  g_x16);
    cudaGetSymbolAddress((void**)&pe16, g_pe16);
    cudaGetSymbolAddress((void**)&h16,  g_h16);
    cudaGetSymbolAddress((void**)&t1h,  g_t1h);
    cudaGetSymbolAddress((void**)&t2h,  g_t2h);

    cudaFuncSetAttribute(attn_h_kernel,
                         cudaFuncAttributeMaxDynamicSharedMemorySize, ATTN_SMEM);
    cudaFuncSetAttribute(gemm_h_kernel<64, 0, false, false, 0>,
                         cudaFuncAttributeMaxDynamicSharedMemorySize, GEMM_SMEM_64);
    cudaFuncSetAttribute(gemm_h_kernel<64, 0, true, false, 1>,
                         cudaFuncAttributeMaxDynamicSharedMemorySize, GEMM_SMEM_64);
    cudaFuncSetAttribute(gemm_h_kernel<64, 0, false, false, 2>,
                         cudaFuncAttributeMaxDynamicSharedMemorySize, GEMM_SMEM_64);
    cudaFuncSetAttribute(gemm_h_kernel<64, 0, true, true, 0>,
                         cudaFuncAttributeMaxDynamicSharedMemorySize, GEMM_SMEM_64);
    cudaFuncSetAttribute(gemm_h_kernel<64, 1, false, false, 0>,
                         cudaFuncAttributeMaxDynamicSharedMemorySize, GEMM_SMEM_64);
    cudaFuncSetAttribute(gemm_h_kernel<128, 0, false, false, 2>,
                         cudaFuncAttributeMaxDynamicSharedMemorySize, GEMM_SMEM_128);
    cudaFuncSetAttribute(gemm_h_kernel<128, 1, false, false, 2>,
                         cudaFuncAttributeMaxDynamicSharedMemorySize, GEMM_SMEM_128);

    // convert inputs + weights to fp16
    conv(x,       x16,               BNODES * 128);
    conv(pe,      pe16,              BNODES * 8);
    conv(W_in,    w16 + OFF_WIN,     HDIM * 128);
    conv(W_pe,    w16 + OFF_WPE,     HDIM * 8);
    conv(gcn_W,   w16 + OFF_GCN,     NLAYER * HDIM * HDIM);
    conv(ain_W,   w16 + OFF_AIN,     NLAYER * 768 * HDIM);
    conv(aout_W,  w16 + OFF_AOUT,    NLAYER * HDIM * HDIM);
    conv(ffn_W1,  w16 + OFF_FFN1,    NLAYER * 1024 * HDIM);
    conv(ffn_W2,  w16 + OFF_FFN2,    NLAYER * HDIM * 1024);
    conv(head_W1, w16 + OFF_HW1,     128 * HDIM);

    // CSR build
    cudaMemsetAsync(cnt, 0, BNODES * sizeof(int));
    count_deg_kernel<<<NEDGE / 256, 256>>>(erow, cnt);
    scan_kernel<<<1, 256>>>(cnt, off, cur);
    fill_csr_kernel<<<NEDGE / 256, 256>>>(erow, cur, eidx);

    const dim3 g256 (2, BNODES / 64);    // TM=64,  N=256
    const dim3 g768 (6, BNODES / 128);   // TM=128, N=768
    const dim3 g1024(8, BNODES / 128);   // TM=128, N=1024
    const dim3 g128 (1, BNODES / 64);    // TM=64,  N=128

    // input projection -> h (fp32) + h16
    gemm_h_kernel<64, 0, false, false, 0><<<g256, 256, GEMM_SMEM_64>>>(
        x16, w16 + OFF_WIN, b_in, h, nullptr, 128, HDIM);
    gemm_h_kernel<64, 0, true, false, 1><<<g256, 256, GEMM_SMEM_64>>>(
        pe16, w16 + OFF_WPE, b_pe, h, h16, 8, HDIM);

    for (int l = 0; l < NLAYER; l++) {
        // ---- local GCN ----
        gemm_h_kernel<64, 0, false, false, 2><<<g256, 256, GEMM_SMEM_64>>>(
            h16, w16 + OFF_GCN + (size_t)l * HDIM * HDIM, nullptr,
            nullptr, t1h, HDIM, HDIM);
        gcn_gather_kernel<<<BNODES, 256>>>(t1h, off, eidx, ecol, eval, t2);
        bnpre_kernel<<<256, 256>>>(h, t2, psum, psq);
        bnapply_kernel<<<128, 256>>>(h, h16, psum, psq,
                                     bn_g + l * 3 * HDIM, bn_b + l * 3 * HDIM, 256);
        // ---- global attention ----
        gemm_h_kernel<128, 0, false, false, 2><<<g768, 256, GEMM_SMEM_128>>>(
            h16, w16 + OFF_AIN + (size_t)l * 768 * HDIM, ain_b + l * 768,
            nullptr, t1h, HDIM, 768);
        attn_h_kernel<<<dim3(8, 8, 8), 256, ATTN_SMEM>>>(t1h, t2h);
        gemm_h_kernel<64, 0, true, true, 0><<<g256, 256, GEMM_SMEM_64>>>(
            t2h, w16 + OFF_AOUT + (size_t)l * HDIM * HDIM, aout_b + l * HDIM,
            h, nullptr, HDIM, HDIM);
        bnapply_kernel<<<128, 256>>>(h, h16, psum, psq,
                                     bn_g + l * 3 * HDIM + HDIM,
                                     bn_b + l * 3 * HDIM + HDIM, 128);
        // ---- FFN ----
        gemm_h_kernel<128, 1, false, false, 2><<<g1024, 256, GEMM_SMEM_128>>>(
            h16, w16 + OFF_FFN1 + (size_t)l * 1024 * HDIM, ffn_b1 + l * 1024,
            nullptr, t1h, HDIM, 1024);
        gemm_h_kernel<64, 0, true, true, 0><<<g256, 256, GEMM_SMEM_64>>>(
            t1h, w16 + OFF_FFN2 + (size_t)l * HDIM * 1024, ffn_b2 + l * HDIM,
            h, nullptr, 1024, HDIM);
        bnapply_kernel<<<128, 256>>>(h, h16, psum, psq,
                                     bn_g + l * 3 * HDIM + 2 * HDIM,
                                     bn_b + l * 3 * HDIM + 2 * HDIM, 128);
    }

    // ---- head ----
    gemm_h_kernel<64, 1, false, false, 0><<<g128, 256, GEMM_SMEM_64>>>(
        h16, w16 + OFF_HW1, head_b1, t1, nullptr, HDIM, 128);
    head_final_kernel<<<BNODES / 8, 256>>>(t1, head_W2, head_b2, (float*)d_out);
}